// round 9
// baseline (speedup 1.0000x reference)
#include <cuda_runtime.h>
#include <cuda_bf16.h>
#include <cuda_fp16.h>
#include <cstdint>

// Problem constants
#define BB   2
#define TT   2048
#define DIMC 1024
#define NH   16
#define HD   64
#define MTOT (BB * TT)          // 4096
#define N_QKV (3 * DIMC)        // 3072

// q pre-scale: 1/sqrt(64) * log2(e)
#define QSCALE 0.18033688011112042f

// -------- scratch (device globals; no allocation allowed) --------
__device__ __half g_qh[BB * NH * TT * HD], g_ql[BB * NH * TT * HD];
__device__ __half g_kh[BB * NH * TT * HD];
__device__ __half g_vh[BB * NH * TT * HD];
__device__ __half g_xh[MTOT * DIMC];          // x (fp16)
__device__ __half g_ah[MTOT * DIMC];          // attn out [B,T,C] (fp16)
__device__ __half g_wqh[N_QKV * DIMC], g_wql[N_QKV * DIMC];    // W_qkv^T hi/lo
__device__ __half g_woh[DIMC * DIMC], g_wol[DIMC * DIMC];      // W_out^T hi/lo

// ============================================================================
// Helpers (plain-target PTX: cp.async / ldmatrix / mma.sync)
// ============================================================================
__device__ __forceinline__ uint32_t smem_u32(const void* p) {
    uint32_t a;
    asm("{ .reg .u64 t; cvta.to.shared.u64 t, %1; cvt.u32.u64 %0, t; }" : "=r"(a) : "l"(p));
    return a;
}
__device__ __forceinline__ void cp16(uint32_t dst, const void* src) {
    asm volatile("cp.async.cg.shared.global [%0], [%1], 16;" :: "r"(dst), "l"(src));
}
__device__ __forceinline__ void cp_commit() { asm volatile("cp.async.commit_group;" ::: "memory"); }
__device__ __forceinline__ void cp_wait0()  { asm volatile("cp.async.wait_group 0;" ::: "memory"); }
__device__ __forceinline__ void cp_wait1()  { asm volatile("cp.async.wait_group 1;" ::: "memory"); }

__device__ __forceinline__ void ldsm4(uint32_t& r0, uint32_t& r1, uint32_t& r2, uint32_t& r3,
                                      uint32_t addr) {
    asm volatile("ldmatrix.sync.aligned.m8n8.x4.shared.b16 {%0,%1,%2,%3}, [%4];"
                 : "=r"(r0), "=r"(r1), "=r"(r2), "=r"(r3) : "r"(addr));
}
__device__ __forceinline__ void ldsm4t(uint32_t& r0, uint32_t& r1, uint32_t& r2, uint32_t& r3,
                                       uint32_t addr) {
    asm volatile("ldmatrix.sync.aligned.m8n8.x4.trans.shared.b16 {%0,%1,%2,%3}, [%4];"
                 : "=r"(r0), "=r"(r1), "=r"(r2), "=r"(r3) : "r"(addr));
}
__device__ __forceinline__ void mma_fp(float* c, const uint32_t* a, uint32_t b0, uint32_t b1) {
    asm volatile(
        "mma.sync.aligned.m16n8k16.row.col.f32.f16.f16.f32 "
        "{%0,%1,%2,%3}, {%4,%5,%6,%7}, {%8,%9}, {%0,%1,%2,%3};"
        : "+f"(c[0]), "+f"(c[1]), "+f"(c[2]), "+f"(c[3])
        : "r"(a[0]), "r"(a[1]), "r"(a[2]), "r"(a[3]), "r"(b0), "r"(b1));
}

// exp2 on FFMA pipe: magic-number round + degree-5 Taylor, t <= 0
__device__ __forceinline__ float exp2p(float t) {
    t = fmaxf(t, -80.0f);
    float k = t + 12582912.0f;
    int ik = __float_as_int(k) << 23;
    float f = t - (k - 12582912.0f);
    float r = 1.3333558146e-3f;
    r = fmaf(r, f, 9.6181291076e-3f);
    r = fmaf(r, f, 5.5504108664e-2f);
    r = fmaf(r, f, 2.4022650696e-1f);
    r = fmaf(r, f, 6.9314718056e-1f);
    r = fmaf(r, f, 1.0f);
    return __int_as_float(__float_as_int(r) + ik);
}

__device__ __forceinline__ uint32_t packh2(__half a, __half b) {
    __half2 h = __halves2half2(a, b);
    return *(uint32_t*)&h;
}
__device__ __forceinline__ void split2h(float a, float b, uint32_t& hi, uint32_t& lo) {
    __half ha = __float2half_rn(a), hb = __float2half_rn(b);
    hi = packh2(ha, hb);
    lo = packh2(__float2half_rn(a - __half2float(ha)),
                __float2half_rn(b - __half2float(hb)));
}

// ============================================================================
// fp32 -> fp16 conversion (x), vectorized float4
// ============================================================================
__global__ void conv_kernel(const float* __restrict__ src) {
    int i = (blockIdx.x * blockDim.x + threadIdx.x) * 4;
    float4 v = *(const float4*)(src + i);
    *(uint32_t*)(g_xh + i)     = packh2(__float2half_rn(v.x), __float2half_rn(v.y));
    *(uint32_t*)(g_xh + i + 2) = packh2(__float2half_rn(v.z), __float2half_rn(v.w));
}

// ============================================================================
// W[K=1024, N] -> W^T split into [N, 1024] fp16 hi/lo
// ============================================================================
template <int W>
__global__ void transpose_split(const float* __restrict__ Win) {
    const int N = (W == 0) ? N_QKV : DIMC;
    __half* Th = (W == 0) ? g_wqh : g_woh;
    __half* Tl = (W == 0) ? g_wql : g_wol;
    __shared__ float t[32][33];
    int tx = threadIdx.x, ty = threadIdx.y;
    int n0 = blockIdx.x * 32, k0 = blockIdx.y * 32;
#pragma unroll
    for (int j = 0; j < 32; j += 8)
        t[ty + j][tx] = Win[(size_t)(k0 + ty + j) * N + n0 + tx];
    __syncthreads();
#pragma unroll
    for (int j = 0; j < 32; j += 8) {
        float v = t[tx][ty + j];
        size_t o = (size_t)(n0 + ty + j) * DIMC + k0 + tx;
        __half h = __float2half_rn(v);
        Th[o] = h;
        Tl[o] = __float2half_rn(v - __half2float(h));
    }
}

// ============================================================================
// HMMA fp16 GEMM: C = A·(Bh+Bl). 128x128 CTA, BK=32, 2-stage cp.async,
// 8 warps (2x4), 64x32 warp tiles. ldsm4-pair B loads; A streamed one
// fragment at a time to minimize live regs. 3 CTAs/SM via launch_bounds.
// MODE 1 -> fp16 Q hi/lo (+pos,scaled), K, V. MODE 0 -> fp32 Cout + bias.
// ============================================================================
#define PADK   40                  // 32 + 8 fp16 padding (80B rows)
#define MAT_B  (128 * PADK * 2)    // 10240 B
#define STG_B  (3 * MAT_B)         // 30720 B (A, Bh, Bl)
#define GEMM_SMEM (2 * STG_B)      // 61440 B

template <int MODE>
__global__ __launch_bounds__(256, 3) void hmma_gemm(
    const float* __restrict__ bias, const float* __restrict__ pos,
    float* __restrict__ Cout)
{
    const __half* Aa = (MODE == 1) ? g_xh : g_ah;
    const __half* Bh = (MODE == 1) ? g_wqh : g_woh;
    const __half* Bl = (MODE == 1) ? g_wql : g_wol;

    extern __shared__ char smraw[];
    const uint32_t sbase = smem_u32(smraw);

    const int tid = threadIdx.x;
    const int wid = tid >> 5, lane = tid & 31;
    const int wm0 = (wid >> 2) * 64;
    const int wn0 = (wid & 3) * 32;

    const int row0 = blockIdx.y * 128;
    const int col0 = blockIdx.x * 128;

    const __half* srcs[3] = {
        Aa + (size_t)row0 * DIMC,
        Bh + (size_t)col0 * DIMC,
        Bl + (size_t)col0 * DIMC };

    const int lr0 = tid >> 2;           // 0..63, 2 passes -> 128 rows
    const int lch = tid & 3;            // 16B chunk in 64B row

    auto load_chunk = [&](int kc, int s) {
        uint32_t st = sbase + (uint32_t)s * STG_B;
#pragma unroll
        for (int mmat = 0; mmat < 3; ++mmat) {
            const __half* src = srcs[mmat] + (size_t)kc * 32;
            uint32_t mb = st + (uint32_t)mmat * MAT_B;
#pragma unroll
            for (int i = 0; i < 2; ++i) {
                int r = lr0 + i * 64;
                cp16(mb + (uint32_t)(r * PADK + lch * 8) * 2,
                     src + (size_t)r * DIMC + lch * 8);
            }
        }
    };

    float acc[4][4][4];
#pragma unroll
    for (int i = 0; i < 4; ++i)
#pragma unroll
        for (int j = 0; j < 4; ++j)
#pragma unroll
            for (int k = 0; k < 4; ++k) acc[i][j][k] = 0.0f;

    const int aRow = lane & 15;               // x4 ldsm row addressing
    const int aColHalf = (lane >> 4) * 8;     // k-half

    load_chunk(0, 0);
    cp_commit();

    const int NC = DIMC / 32;
    for (int kc = 0; kc < NC; ++kc) {
        int cur = kc & 1;
        if (kc + 1 < NC) {
            load_chunk(kc + 1, cur ^ 1);
            cp_commit();
            cp_wait1();
        } else {
            cp_wait0();
        }
        __syncthreads();

        uint32_t st = sbase + (uint32_t)cur * STG_B;
        uint32_t aA = st, bH = st + MAT_B, bL = st + 2 * MAT_B;

#pragma unroll
        for (int ks = 0; ks < 2; ++ks) {
            int kcol = ks * 16;
            // B fragments: 2 ldsm4 per matrix cover the 32-n warp range.
            // frag[2np]   uses (r0, r2) -> n rows np*16+0..7
            // frag[2np+1] uses (r1, r3) -> n rows np*16+8..15
            uint32_t bfh[2][4], bfl[2][4];
#pragma unroll
            for (int np = 0; np < 2; ++np) {
                uint32_t off = (uint32_t)((wn0 + np * 16 + aRow) * PADK + kcol + aColHalf) * 2;
                ldsm4(bfh[np][0], bfh[np][1], bfh[np][2], bfh[np][3], bH + off);
                ldsm4(bfl[np][0], bfl[np][1], bfl[np][2], bfl[np][3], bL + off);
            }
            // stream A fragments
#pragma unroll
            for (int mf = 0; mf < 4; ++mf) {
                uint32_t ah[4];
                uint32_t off = (uint32_t)((wm0 + mf * 16 + aRow) * PADK + kcol + aColHalf) * 2;
                ldsm4(ah[0], ah[1], ah[2], ah[3], aA + off);
#pragma unroll
                for (int np = 0; np < 2; ++np) {
                    mma_fp(acc[mf][2 * np],     ah, bfh[np][0], bfh[np][2]);
                    mma_fp(acc[mf][2 * np],     ah, bfl[np][0], bfl[np][2]);
                    mma_fp(acc[mf][2 * np + 1], ah, bfh[np][1], bfh[np][3]);
                    mma_fp(acc[mf][2 * np + 1], ah, bfl[np][1], bfl[np][3]);
                }
            }
        }
        __syncthreads();
    }

    const int erow = lane >> 2;
    const int ecol = (lane & 3) * 2;
#pragma unroll
    for (int mf = 0; mf < 4; ++mf) {
#pragma unroll
        for (int half = 0; half < 2; ++half) {
            int m = row0 + wm0 + mf * 16 + erow + half * 8;
            int b_ = m >> 11, t = m & (TT - 1);
#pragma unroll
            for (int nf = 0; nf < 4; ++nf) {
                int n = col0 + wn0 + nf * 8 + ecol;
                float vx = acc[mf][nf][half * 2 + 0] + bias[n + 0];
                float vy = acc[mf][nf][half * 2 + 1] + bias[n + 1];
                if (MODE == 0) {
                    float2 v = {vx, vy};
                    *(float2*)(Cout + (size_t)m * DIMC + n) = v;
                } else {
                    int sec = n >> 10;
                    int cc = n & (DIMC - 1);
                    int h = cc >> 6, d = cc & 63;
                    size_t idx = (((size_t)(b_ * NH + h)) * TT + t) * HD + d;
                    if (sec == 0) {
                        float qx = (vx + pos[cc + 0]) * QSCALE;
                        float qy = (vy + pos[cc + 1]) * QSCALE;
                        uint32_t hi, lo;
                        split2h(qx, qy, hi, lo);
                        *(uint32_t*)(g_qh + idx) = hi;
                        *(uint32_t*)(g_ql + idx) = lo;
                    } else if (sec == 1) {
                        *(uint32_t*)(g_kh + idx) =
                            packh2(__float2half_rn(vx), __float2half_rn(vy));
                    } else {
                        *(uint32_t*)(g_vh + idx) =
                            packh2(__float2half_rn(vx), __float2half_rn(vy));
                    }
                }
            }
        }
    }
}

// ============================================================================
// HMMA flash attention (unchanged): 128 q-rows/CTA, Bc=64.
// Q,P exact fp16 hi+lo (2 products); K,V single fp16. fp16 output.
// ============================================================================
#define AT_PADH 72                      // fp16 elems per smem row (144 B)
#define Q_BYTES (128 * AT_PADH * 2)     // 18432
#define KV_MAT  (64 * AT_PADH * 2)      // 9216
#define KV_STAGE (2 * KV_MAT)           // 18432 (Kh, Vh)
#define ATT_SMEM (2 * Q_BYTES + 2 * KV_STAGE)   // 73728

__global__ __launch_bounds__(256) void attn2()
{
    extern __shared__ char smraw[];
    const uint32_t sb = smem_u32(smraw);
    const uint32_t sQh = sb, sQl = sb + Q_BYTES;
    const uint32_t sKV = sb + 2 * Q_BYTES;

    const int tid = threadIdx.x;
    const int lane = tid & 31;
    const int qi = gridDim.x - 1 - blockIdx.x;
    const int bh = blockIdx.y;
    const int q0 = qi * 128;
    const int qr0 = (tid >> 5) * 16;

    const __half* qhp = g_qh + (size_t)bh * TT * HD;
    const __half* qlp = g_ql + (size_t)bh * TT * HD;
    const __half* kvsrc[2] = {
        g_kh + (size_t)bh * TT * HD, g_vh + (size_t)bh * TT * HD };

    auto prefetchKV = [&](int j, uint32_t dst) {
        int kb = j * 64;
#pragma unroll
        for (int i = 0; i < 4; ++i) {
            int c = tid + i * 256;
            int mat = c >> 9, rem = c & 511;
            int r = rem >> 3, ch = rem & 7;
            cp16(dst + (uint32_t)mat * KV_MAT + (uint32_t)(r * 144 + ch * 16),
                 kvsrc[mat] + (size_t)(kb + r) * HD + ch * 8);
        }
    };

#pragma unroll
    for (int i = 0; i < 4; ++i) {
        int c = tid + i * 256;
        int r = c >> 3, ch = c & 7;
        cp16(sQh + (uint32_t)(r * 144 + ch * 16), qhp + (size_t)(q0 + r) * HD + ch * 8);
        cp16(sQl + (uint32_t)(r * 144 + ch * 16), qlp + (size_t)(q0 + r) * HD + ch * 8);
    }
    prefetchKV(0, sKV);
    cp_commit();
    cp_wait0();
    __syncthreads();

    uint32_t fqh[4][4], fql[4][4];
    {
        int rr = qr0 + (lane & 15);
#pragma unroll
        for (int kf = 0; kf < 4; ++kf) {
            int cc = kf * 16 + ((lane & 16) ? 8 : 0);
            uint32_t off = (uint32_t)(rr * 144 + cc * 2);
            ldsm4(fqh[kf][0], fqh[kf][1], fqh[kf][2], fqh[kf][3], sQh + off);
            ldsm4(fql[kf][0], fql[kf][1], fql[kf][2], fql[kf][3], sQl + off);
        }
    }

    float o[8][4];
#pragma unroll
    for (int i = 0; i < 8; ++i)
#pragma unroll
        for (int k = 0; k < 4; ++k) o[i][k] = 0.0f;
    float m0 = -1e30f, m1 = -1e30f, l0 = 0.0f, l1 = 0.0f;

    const int ntiles = 2 * qi + 2;
    for (int j = 0; j < ntiles; ++j) {
        uint32_t stage = sKV + (uint32_t)(j & 1) * KV_STAGE;
        if (j + 1 < ntiles) {
            prefetchKV(j + 1, sKV + (uint32_t)((j + 1) & 1) * KV_STAGE);
            cp_commit();
        }

        float c[8][4];
#pragma unroll
        for (int i = 0; i < 8; ++i)
#pragma unroll
            for (int k = 0; k < 4; ++k) c[i][k] = 0.0f;

        uint32_t Kh = stage;
        {
            int rb = ((lane & 16) ? 8 : 0) + (lane & 7);
            int cb = ((lane & 8) ? 8 : 0);
#pragma unroll
            for (int kf = 0; kf < 4; ++kf) {
#pragma unroll
                for (int jp = 0; jp < 4; ++jp) {
                    uint32_t off = (uint32_t)((jp * 16 + rb) * 144 + (kf * 16 + cb) * 2);
                    uint32_t h0, h1, h2, h3;
                    ldsm4(h0, h1, h2, h3, Kh + off);
                    mma_fp(c[2 * jp],     fqh[kf], h0, h1);
                    mma_fp(c[2 * jp],     fql[kf], h0, h1);
                    mma_fp(c[2 * jp + 1], fqh[kf], h2, h3);
                    mma_fp(c[2 * jp + 1], fql[kf], h2, h3);
                }
            }
        }

        if (j >= 2 * qi) {
            int row0 = q0 + qr0 + (lane >> 2);
            int kb = j * 64 + (lane & 3) * 2;
#pragma unroll
            for (int nf = 0; nf < 8; ++nf) {
                int key = kb + nf * 8;
                if (key     > row0)     c[nf][0] = -1e30f;
                if (key + 1 > row0)     c[nf][1] = -1e30f;
                if (key     > row0 + 8) c[nf][2] = -1e30f;
                if (key + 1 > row0 + 8) c[nf][3] = -1e30f;
            }
        }

        float v0 = -1e30f, v1 = -1e30f;
#pragma unroll
        for (int nf = 0; nf < 8; ++nf) {
            v0 = fmaxf(v0, fmaxf(c[nf][0], c[nf][1]));
            v1 = fmaxf(v1, fmaxf(c[nf][2], c[nf][3]));
        }
        v0 = fmaxf(v0, __shfl_xor_sync(0xFFFFFFFFu, v0, 1));
        v0 = fmaxf(v0, __shfl_xor_sync(0xFFFFFFFFu, v0, 2));
        v1 = fmaxf(v1, __shfl_xor_sync(0xFFFFFFFFu, v1, 1));
        v1 = fmaxf(v1, __shfl_xor_sync(0xFFFFFFFFu, v1, 2));
        float mn0 = fmaxf(m0, v0), mn1 = fmaxf(m1, v1);
        float a0 = exp2p(m0 - mn0), a1 = exp2p(m1 - mn1);
        m0 = mn0; m1 = mn1;
        l0 *= a0; l1 *= a1;
#pragma unroll
        for (int nf = 0; nf < 8; ++nf) {
            o[nf][0] *= a0; o[nf][1] *= a0;
            o[nf][2] *= a1; o[nf][3] *= a1;
        }

        uint32_t Vh = stage + KV_MAT;
        int vrb = ((lane & 8) ? 8 : 0) + (lane & 7);
        int vcb = ((lane & 16) ? 8 : 0);
#pragma unroll
        for (int t = 0; t < 4; ++t) {
            float p00 = exp2p(c[2 * t][0] - m0), p01 = exp2p(c[2 * t][1] - m0);
            float p02 = exp2p(c[2 * t][2] - m1), p03 = exp2p(c[2 * t][3] - m1);
            float p10 = exp2p(c[2 * t + 1][0] - m0), p11 = exp2p(c[2 * t + 1][1] - m0);
            float p12 = exp2p(c[2 * t + 1][2] - m1), p13 = exp2p(c[2 * t + 1][3] - m1);
            l0 += p00 + p01 + p10 + p11;
            l1 += p02 + p03 + p12 + p13;

            uint32_t ph[4], pl[4];
            split2h(p00, p01, ph[0], pl[0]);
            split2h(p02, p03, ph[1], pl[1]);
            split2h(p10, p11, ph[2], pl[2]);
            split2h(p12, p13, ph[3], pl[3]);

#pragma unroll
            for (int dp = 0; dp < 4; ++dp) {
                uint32_t off = (uint32_t)((t * 16 + vrb) * 144 + (dp * 16 + vcb) * 2);
                uint32_t h0, h1, h2, h3;
                ldsm4t(h0, h1, h2, h3, Vh + off);
                mma_fp(o[2 * dp],     ph, h0, h1);
                mma_fp(o[2 * dp],     pl, h0, h1);
                mma_fp(o[2 * dp + 1], ph, h2, h3);
                mma_fp(o[2 * dp + 1], pl, h2, h3);
            }
        }

        if (j + 1 < ntiles) cp_wait0();
        __syncthreads();
    }

    l0 += __shfl_xor_sync(0xFFFFFFFFu, l0, 1);
    l0 += __shfl_xor_sync(0xFFFFFFFFu, l0, 2);
    l1 += __shfl_xor_sync(0xFFFFFFFFu, l1, 1);
    l1 += __shfl_xor_sync(0xFFFFFFFFu, l1, 2);
    float inv0 = 1.0f / l0, inv1 = 1.0f / l1;

    int b_ = bh >> 4, h = bh & 15;
    int t0 = q0 + qr0 + (lane >> 2);
    size_t r0 = ((size_t)b_ * TT + t0) * DIMC;
    size_t r1 = r0 + (size_t)8 * DIMC;
    int coff = h * 64 + (lane & 3) * 2;
#pragma unroll
    for (int nf = 0; nf < 8; ++nf) {
        int col = coff + nf * 8;
        *(uint32_t*)(g_ah + r0 + col) =
            packh2(__float2half_rn(o[nf][0] * inv0), __float2half_rn(o[nf][1] * inv0));
        *(uint32_t*)(g_ah + r1 + col) =
            packh2(__float2half_rn(o[nf][2] * inv1), __float2half_rn(o[nf][3] * inv1));
    }
}

// ============================================================================
// Launch
// ============================================================================
extern "C" void kernel_launch(void* const* d_in, const int* in_sizes, int n_in,
                              void* d_out, int out_size)
{
    (void)in_sizes; (void)n_in; (void)out_size;
    const float* x     = (const float*)d_in[0];
    const float* w_qkv = (const float*)d_in[1];
    const float* b_qkv = (const float*)d_in[2];
    const float* w_out = (const float*)d_in[3];
    const float* b_out = (const float*)d_in[4];
    const float* pos   = (const float*)d_in[5];
    float* out = (float*)d_out;

    cudaFuncSetAttribute(hmma_gemm<1>, cudaFuncAttributeMaxDynamicSharedMemorySize, GEMM_SMEM);
    cudaFuncSetAttribute(hmma_gemm<0>, cudaFuncAttributeMaxDynamicSharedMemorySize, GEMM_SMEM);
    cudaFuncSetAttribute(attn2, cudaFuncAttributeMaxDynamicSharedMemorySize, ATT_SMEM);

    // 0) convert input to fp16 + transpose/split weights (fp16 hi/lo)
    conv_kernel<<<MTOT * DIMC / 1024, 256>>>(x);
    transpose_split<0><<<dim3(N_QKV / 32, DIMC / 32), dim3(32, 8)>>>(w_qkv);
    transpose_split<1><<<dim3(DIMC / 32, DIMC / 32), dim3(32, 8)>>>(w_out);

    // 1) QKV projection + bias (+pos, q-scale) -> fp16 Q hi/lo, K, V
    hmma_gemm<1><<<dim3(N_QKV / 128, MTOT / 128), 256, GEMM_SMEM>>>(b_qkv, pos, nullptr);

    // 2) HMMA flash attention -> fp16 attn out
    attn2<<<dim3(TT / 128, BB * NH), 256, ATT_SMEM>>>();

    // 3) output projection + bias
    hmma_gemm<0><<<dim3(DIMC / 128, MTOT / 128), 256, GEMM_SMEM>>>(b_out, nullptr, out);
}

// round 10
// speedup vs baseline: 1.3509x; 1.3509x over previous
#include <cuda_runtime.h>
#include <cuda_bf16.h>
#include <cuda_fp16.h>
#include <cstdint>

// Problem constants
#define BB   2
#define TT   2048
#define DIMC 1024
#define NH   16
#define HD   64
#define MTOT (BB * TT)          // 4096
#define N_QKV (3 * DIMC)        // 3072

// q pre-scale: 1/sqrt(64) * log2(e)
#define QSCALE 0.18033688011112042f

// -------- scratch (device globals; no allocation allowed) --------
__device__ __half g_qh[BB * NH * TT * HD], g_ql[BB * NH * TT * HD];
__device__ __half g_kh[BB * NH * TT * HD];
__device__ __half g_vh[BB * NH * TT * HD];
__device__ __half g_xh[MTOT * DIMC];          // x (fp16)
__device__ __half g_ah[MTOT * DIMC];          // attn out [B,T,C] (fp16)
__device__ __half g_wqh[N_QKV * DIMC], g_wql[N_QKV * DIMC];    // W_qkv^T hi/lo
__device__ __half g_woh[DIMC * DIMC], g_wol[DIMC * DIMC];      // W_out^T hi/lo

// ============================================================================
// Helpers (plain-target PTX: cp.async / ldmatrix / mma.sync)
// ============================================================================
__device__ __forceinline__ uint32_t smem_u32(const void* p) {
    uint32_t a;
    asm("{ .reg .u64 t; cvta.to.shared.u64 t, %1; cvt.u32.u64 %0, t; }" : "=r"(a) : "l"(p));
    return a;
}
__device__ __forceinline__ void cp16(uint32_t dst, const void* src) {
    asm volatile("cp.async.cg.shared.global [%0], [%1], 16;" :: "r"(dst), "l"(src));
}
__device__ __forceinline__ void cp_commit() { asm volatile("cp.async.commit_group;" ::: "memory"); }
__device__ __forceinline__ void cp_wait0()  { asm volatile("cp.async.wait_group 0;" ::: "memory"); }
__device__ __forceinline__ void cp_wait1()  { asm volatile("cp.async.wait_group 1;" ::: "memory"); }

__device__ __forceinline__ void ldsm4(uint32_t& r0, uint32_t& r1, uint32_t& r2, uint32_t& r3,
                                      uint32_t addr) {
    asm volatile("ldmatrix.sync.aligned.m8n8.x4.shared.b16 {%0,%1,%2,%3}, [%4];"
                 : "=r"(r0), "=r"(r1), "=r"(r2), "=r"(r3) : "r"(addr));
}
__device__ __forceinline__ void ldsm4t(uint32_t& r0, uint32_t& r1, uint32_t& r2, uint32_t& r3,
                                       uint32_t addr) {
    asm volatile("ldmatrix.sync.aligned.m8n8.x4.trans.shared.b16 {%0,%1,%2,%3}, [%4];"
                 : "=r"(r0), "=r"(r1), "=r"(r2), "=r"(r3) : "r"(addr));
}
__device__ __forceinline__ void ldsm2(uint32_t& r0, uint32_t& r1, uint32_t addr) {
    asm volatile("ldmatrix.sync.aligned.m8n8.x2.shared.b16 {%0,%1}, [%2];"
                 : "=r"(r0), "=r"(r1) : "r"(addr));
}
__device__ __forceinline__ void mma_fp(float* c, const uint32_t* a, uint32_t b0, uint32_t b1) {
    asm volatile(
        "mma.sync.aligned.m16n8k16.row.col.f32.f16.f16.f32 "
        "{%0,%1,%2,%3}, {%4,%5,%6,%7}, {%8,%9}, {%0,%1,%2,%3};"
        : "+f"(c[0]), "+f"(c[1]), "+f"(c[2]), "+f"(c[3])
        : "r"(a[0]), "r"(a[1]), "r"(a[2]), "r"(a[3]), "r"(b0), "r"(b1));
}

// exp2 on FFMA pipe: magic-number round + degree-5 Taylor, t <= 0
__device__ __forceinline__ float exp2p(float t) {
    t = fmaxf(t, -80.0f);
    float k = t + 12582912.0f;
    int ik = __float_as_int(k) << 23;
    float f = t - (k - 12582912.0f);
    float r = 1.3333558146e-3f;
    r = fmaf(r, f, 9.6181291076e-3f);
    r = fmaf(r, f, 5.5504108664e-2f);
    r = fmaf(r, f, 2.4022650696e-1f);
    r = fmaf(r, f, 6.9314718056e-1f);
    r = fmaf(r, f, 1.0f);
    return __int_as_float(__float_as_int(r) + ik);
}

__device__ __forceinline__ uint32_t packh2(__half a, __half b) {
    __half2 h = __halves2half2(a, b);
    return *(uint32_t*)&h;
}
__device__ __forceinline__ void split2h(float a, float b, uint32_t& hi, uint32_t& lo) {
    __half ha = __float2half_rn(a), hb = __float2half_rn(b);
    hi = packh2(ha, hb);
    lo = packh2(__float2half_rn(a - __half2float(ha)),
                __float2half_rn(b - __half2float(hb)));
}

// ============================================================================
// fp32 -> fp16 conversion (x), vectorized float4
// ============================================================================
__global__ void conv_kernel(const float* __restrict__ src) {
    int i = (blockIdx.x * blockDim.x + threadIdx.x) * 4;
    float4 v = *(const float4*)(src + i);
    *(uint32_t*)(g_xh + i)     = packh2(__float2half_rn(v.x), __float2half_rn(v.y));
    *(uint32_t*)(g_xh + i + 2) = packh2(__float2half_rn(v.z), __float2half_rn(v.w));
}

// ============================================================================
// W[K=1024, N] -> W^T split into [N, 1024] fp16 hi/lo
// ============================================================================
template <int W>
__global__ void transpose_split(const float* __restrict__ Win) {
    const int N = (W == 0) ? N_QKV : DIMC;
    __half* Th = (W == 0) ? g_wqh : g_woh;
    __half* Tl = (W == 0) ? g_wql : g_wol;
    __shared__ float t[32][33];
    int tx = threadIdx.x, ty = threadIdx.y;
    int n0 = blockIdx.x * 32, k0 = blockIdx.y * 32;
#pragma unroll
    for (int j = 0; j < 32; j += 8)
        t[ty + j][tx] = Win[(size_t)(k0 + ty + j) * N + n0 + tx];
    __syncthreads();
#pragma unroll
    for (int j = 0; j < 32; j += 8) {
        float v = t[tx][ty + j];
        size_t o = (size_t)(n0 + ty + j) * DIMC + k0 + tx;
        __half h = __float2half_rn(v);
        Th[o] = h;
        Tl[o] = __float2half_rn(v - __half2float(h));
    }
}

// ============================================================================
// HMMA fp16 GEMM: C = A·(Bh+Bl). Round-8 anchor loop body (ldsm4 A, ldsm2 B,
// 2 products, free regs) with a 3-stage cp.async ring and ONE __syncthreads
// per iteration (load for kc+2 issued after the barrier, overlapping compute).
// 128x128 CTA, BK=32, 8 warps (2x4), 64x32 warp tiles.
// MODE 1 -> fp16 Q hi/lo (+pos,scaled), K, V. MODE 0 -> fp32 Cout + bias.
// ============================================================================
#define PADK   40                  // 32 + 8 fp16 padding (80B rows)
#define MAT_B  (128 * PADK * 2)    // 10240 B
#define STG_B  (3 * MAT_B)         // 30720 B (A, Bh, Bl)
#define NSTG   3
#define GEMM_SMEM (NSTG * STG_B)   // 92160 B

template <int MODE>
__global__ __launch_bounds__(256) void hmma_gemm(
    const float* __restrict__ bias, const float* __restrict__ pos,
    float* __restrict__ Cout)
{
    const __half* Aa = (MODE == 1) ? g_xh : g_ah;
    const __half* Bh = (MODE == 1) ? g_wqh : g_woh;
    const __half* Bl = (MODE == 1) ? g_wql : g_wol;

    extern __shared__ char smraw[];
    const uint32_t sbase = smem_u32(smraw);

    const int tid = threadIdx.x;
    const int wid = tid >> 5, lane = tid & 31;
    const int wm0 = (wid >> 2) * 64;
    const int wn0 = (wid & 3) * 32;

    const int row0 = blockIdx.y * 128;
    const int col0 = blockIdx.x * 128;

    const __half* srcs[3] = {
        Aa + (size_t)row0 * DIMC,
        Bh + (size_t)col0 * DIMC,
        Bl + (size_t)col0 * DIMC };

    const int lr0 = tid >> 2;           // 0..63, 2 passes -> 128 rows
    const int lch = tid & 3;            // 16B chunk in 64B row

    auto load_chunk = [&](int kc, int s) {
        uint32_t st = sbase + (uint32_t)s * STG_B;
#pragma unroll
        for (int mmat = 0; mmat < 3; ++mmat) {
            const __half* src = srcs[mmat] + (size_t)kc * 32;
            uint32_t mb = st + (uint32_t)mmat * MAT_B;
#pragma unroll
            for (int i = 0; i < 2; ++i) {
                int r = lr0 + i * 64;
                cp16(mb + (uint32_t)(r * PADK + lch * 8) * 2,
                     src + (size_t)r * DIMC + lch * 8);
            }
        }
    };

    float acc[4][4][4];
#pragma unroll
    for (int i = 0; i < 4; ++i)
#pragma unroll
        for (int j = 0; j < 4; ++j)
#pragma unroll
            for (int k = 0; k < 4; ++k) acc[i][j][k] = 0.0f;

    const int aRow = lane & 15;
    const int aColHalf = (lane >> 4) * 8;
    const int bRow = lane & 7;
    const int bColHalf = ((lane >> 3) & 1) * 8;

    load_chunk(0, 0); cp_commit();
    load_chunk(1, 1); cp_commit();

    const int NC = DIMC / 32;   // 32
    int sc = 0;                 // stage of chunk kc
    for (int kc = 0; kc < NC; ++kc) {
        // wait for chunk kc (leave kc+1 in flight), then ONE barrier
        if (kc + 1 < NC) cp_wait1(); else cp_wait0();
        __syncthreads();
        // issue load for kc+2 into the stage freed by compute of kc-1
        if (kc + 2 < NC) {
            int s2 = sc + 2; if (s2 >= NSTG) s2 -= NSTG;
            load_chunk(kc + 2, s2);
            cp_commit();
        }

        uint32_t st = sbase + (uint32_t)sc * STG_B;
        uint32_t aA = st, bH = st + MAT_B, bL = st + 2 * MAT_B;

#pragma unroll
        for (int ks = 0; ks < 2; ++ks) {
            uint32_t ah[4][4], bh[4][2], bl[4][2];
            int kcol = ks * 16;
#pragma unroll
            for (int mf = 0; mf < 4; ++mf) {
                uint32_t off = (uint32_t)((wm0 + mf * 16 + aRow) * PADK + kcol + aColHalf) * 2;
                ldsm4(ah[mf][0], ah[mf][1], ah[mf][2], ah[mf][3], aA + off);
            }
#pragma unroll
            for (int nf = 0; nf < 4; ++nf) {
                uint32_t off = (uint32_t)((wn0 + nf * 8 + bRow) * PADK + kcol + bColHalf) * 2;
                ldsm2(bh[nf][0], bh[nf][1], bH + off);
                ldsm2(bl[nf][0], bl[nf][1], bL + off);
            }
#pragma unroll
            for (int mf = 0; mf < 4; ++mf)
#pragma unroll
                for (int nf = 0; nf < 4; ++nf) {
                    mma_fp(acc[mf][nf], ah[mf], bh[nf][0], bh[nf][1]);
                    mma_fp(acc[mf][nf], ah[mf], bl[nf][0], bl[nf][1]);
                }
        }

        ++sc; if (sc == NSTG) sc = 0;
    }

    const int erow = lane >> 2;
    const int ecol = (lane & 3) * 2;
#pragma unroll
    for (int mf = 0; mf < 4; ++mf) {
#pragma unroll
        for (int half = 0; half < 2; ++half) {
            int m = row0 + wm0 + mf * 16 + erow + half * 8;
            int b_ = m >> 11, t = m & (TT - 1);
#pragma unroll
            for (int nf = 0; nf < 4; ++nf) {
                int n = col0 + wn0 + nf * 8 + ecol;
                float vx = acc[mf][nf][half * 2 + 0] + bias[n + 0];
                float vy = acc[mf][nf][half * 2 + 1] + bias[n + 1];
                if (MODE == 0) {
                    float2 v = {vx, vy};
                    *(float2*)(Cout + (size_t)m * DIMC + n) = v;
                } else {
                    int sec = n >> 10;
                    int cc = n & (DIMC - 1);
                    int h = cc >> 6, d = cc & 63;
                    size_t idx = (((size_t)(b_ * NH + h)) * TT + t) * HD + d;
                    if (sec == 0) {
                        float qx = (vx + pos[cc + 0]) * QSCALE;
                        float qy = (vy + pos[cc + 1]) * QSCALE;
                        uint32_t hi, lo;
                        split2h(qx, qy, hi, lo);
                        *(uint32_t*)(g_qh + idx) = hi;
                        *(uint32_t*)(g_ql + idx) = lo;
                    } else if (sec == 1) {
                        *(uint32_t*)(g_kh + idx) =
                            packh2(__float2half_rn(vx), __float2half_rn(vy));
                    } else {
                        *(uint32_t*)(g_vh + idx) =
                            packh2(__float2half_rn(vx), __float2half_rn(vy));
                    }
                }
            }
        }
    }
}

// ============================================================================
// HMMA flash attention (round-8, unchanged): 128 q-rows/CTA, Bc=64.
// Q,P exact fp16 hi+lo (2 products); K,V single fp16. fp16 output.
// ============================================================================
#define AT_PADH 72                      // fp16 elems per smem row (144 B)
#define Q_BYTES (128 * AT_PADH * 2)     // 18432
#define KV_MAT  (64 * AT_PADH * 2)      // 9216
#define KV_STAGE (2 * KV_MAT)           // 18432 (Kh, Vh)
#define ATT_SMEM (2 * Q_BYTES + 2 * KV_STAGE)   // 73728

__global__ __launch_bounds__(256) void attn2()
{
    extern __shared__ char smraw[];
    const uint32_t sb = smem_u32(smraw);
    const uint32_t sQh = sb, sQl = sb + Q_BYTES;
    const uint32_t sKV = sb + 2 * Q_BYTES;

    const int tid = threadIdx.x;
    const int lane = tid & 31;
    const int qi = gridDim.x - 1 - blockIdx.x;
    const int bh = blockIdx.y;
    const int q0 = qi * 128;
    const int qr0 = (tid >> 5) * 16;

    const __half* qhp = g_qh + (size_t)bh * TT * HD;
    const __half* qlp = g_ql + (size_t)bh * TT * HD;
    const __half* kvsrc[2] = {
        g_kh + (size_t)bh * TT * HD, g_vh + (size_t)bh * TT * HD };

    auto prefetchKV = [&](int j, uint32_t dst) {
        int kb = j * 64;
#pragma unroll
        for (int i = 0; i < 4; ++i) {
            int c = tid + i * 256;
            int mat = c >> 9, rem = c & 511;
            int r = rem >> 3, ch = rem & 7;
            cp16(dst + (uint32_t)mat * KV_MAT + (uint32_t)(r * 144 + ch * 16),
                 kvsrc[mat] + (size_t)(kb + r) * HD + ch * 8);
        }
    };

#pragma unroll
    for (int i = 0; i < 4; ++i) {
        int c = tid + i * 256;
        int r = c >> 3, ch = c & 7;
        cp16(sQh + (uint32_t)(r * 144 + ch * 16), qhp + (size_t)(q0 + r) * HD + ch * 8);
        cp16(sQl + (uint32_t)(r * 144 + ch * 16), qlp + (size_t)(q0 + r) * HD + ch * 8);
    }
    prefetchKV(0, sKV);
    cp_commit();
    cp_wait0();
    __syncthreads();

    uint32_t fqh[4][4], fql[4][4];
    {
        int rr = qr0 + (lane & 15);
#pragma unroll
        for (int kf = 0; kf < 4; ++kf) {
            int cc = kf * 16 + ((lane & 16) ? 8 : 0);
            uint32_t off = (uint32_t)(rr * 144 + cc * 2);
            ldsm4(fqh[kf][0], fqh[kf][1], fqh[kf][2], fqh[kf][3], sQh + off);
            ldsm4(fql[kf][0], fql[kf][1], fql[kf][2], fql[kf][3], sQl + off);
        }
    }

    float o[8][4];
#pragma unroll
    for (int i = 0; i < 8; ++i)
#pragma unroll
        for (int k = 0; k < 4; ++k) o[i][k] = 0.0f;
    float m0 = -1e30f, m1 = -1e30f, l0 = 0.0f, l1 = 0.0f;

    const int ntiles = 2 * qi + 2;
    for (int j = 0; j < ntiles; ++j) {
        uint32_t stage = sKV + (uint32_t)(j & 1) * KV_STAGE;
        if (j + 1 < ntiles) {
            prefetchKV(j + 1, sKV + (uint32_t)((j + 1) & 1) * KV_STAGE);
            cp_commit();
        }

        float c[8][4];
#pragma unroll
        for (int i = 0; i < 8; ++i)
#pragma unroll
            for (int k = 0; k < 4; ++k) c[i][k] = 0.0f;

        uint32_t Kh = stage;
        {
            int rb = ((lane & 16) ? 8 : 0) + (lane & 7);
            int cb = ((lane & 8) ? 8 : 0);
#pragma unroll
            for (int kf = 0; kf < 4; ++kf) {
#pragma unroll
                for (int jp = 0; jp < 4; ++jp) {
                    uint32_t off = (uint32_t)((jp * 16 + rb) * 144 + (kf * 16 + cb) * 2);
                    uint32_t h0, h1, h2, h3;
                    ldsm4(h0, h1, h2, h3, Kh + off);
                    mma_fp(c[2 * jp],     fqh[kf], h0, h1);
                    mma_fp(c[2 * jp],     fql[kf], h0, h1);
                    mma_fp(c[2 * jp + 1], fqh[kf], h2, h3);
                    mma_fp(c[2 * jp + 1], fql[kf], h2, h3);
                }
            }
        }

        if (j >= 2 * qi) {
            int row0 = q0 + qr0 + (lane >> 2);
            int kb = j * 64 + (lane & 3) * 2;
#pragma unroll
            for (int nf = 0; nf < 8; ++nf) {
                int key = kb + nf * 8;
                if (key     > row0)     c[nf][0] = -1e30f;
                if (key + 1 > row0)     c[nf][1] = -1e30f;
                if (key     > row0 + 8) c[nf][2] = -1e30f;
                if (key + 1 > row0 + 8) c[nf][3] = -1e30f;
            }
        }

        float v0 = -1e30f, v1 = -1e30f;
#pragma unroll
        for (int nf = 0; nf < 8; ++nf) {
            v0 = fmaxf(v0, fmaxf(c[nf][0], c[nf][1]));
            v1 = fmaxf(v1, fmaxf(c[nf][2], c[nf][3]));
        }
        v0 = fmaxf(v0, __shfl_xor_sync(0xFFFFFFFFu, v0, 1));
        v0 = fmaxf(v0, __shfl_xor_sync(0xFFFFFFFFu, v0, 2));
        v1 = fmaxf(v1, __shfl_xor_sync(0xFFFFFFFFu, v1, 1));
        v1 = fmaxf(v1, __shfl_xor_sync(0xFFFFFFFFu, v1, 2));
        float mn0 = fmaxf(m0, v0), mn1 = fmaxf(m1, v1);
        float a0 = exp2p(m0 - mn0), a1 = exp2p(m1 - mn1);
        m0 = mn0; m1 = mn1;
        l0 *= a0; l1 *= a1;
#pragma unroll
        for (int nf = 0; nf < 8; ++nf) {
            o[nf][0] *= a0; o[nf][1] *= a0;
            o[nf][2] *= a1; o[nf][3] *= a1;
        }

        uint32_t Vh = stage + KV_MAT;
        int vrb = ((lane & 8) ? 8 : 0) + (lane & 7);
        int vcb = ((lane & 16) ? 8 : 0);
#pragma unroll
        for (int t = 0; t < 4; ++t) {
            float p00 = exp2p(c[2 * t][0] - m0), p01 = exp2p(c[2 * t][1] - m0);
            float p02 = exp2p(c[2 * t][2] - m1), p03 = exp2p(c[2 * t][3] - m1);
            float p10 = exp2p(c[2 * t + 1][0] - m0), p11 = exp2p(c[2 * t + 1][1] - m0);
            float p12 = exp2p(c[2 * t + 1][2] - m1), p13 = exp2p(c[2 * t + 1][3] - m1);
            l0 += p00 + p01 + p10 + p11;
            l1 += p02 + p03 + p12 + p13;

            uint32_t ph[4], pl[4];
            split2h(p00, p01, ph[0], pl[0]);
            split2h(p02, p03, ph[1], pl[1]);
            split2h(p10, p11, ph[2], pl[2]);
            split2h(p12, p13, ph[3], pl[3]);

#pragma unroll
            for (int dp = 0; dp < 4; ++dp) {
                uint32_t off = (uint32_t)((t * 16 + vrb) * 144 + (dp * 16 + vcb) * 2);
                uint32_t h0, h1, h2, h3;
                ldsm4t(h0, h1, h2, h3, Vh + off);
                mma_fp(o[2 * dp],     ph, h0, h1);
                mma_fp(o[2 * dp],     pl, h0, h1);
                mma_fp(o[2 * dp + 1], ph, h2, h3);
                mma_fp(o[2 * dp + 1], pl, h2, h3);
            }
        }

        if (j + 1 < ntiles) cp_wait0();
        __syncthreads();
    }

    l0 += __shfl_xor_sync(0xFFFFFFFFu, l0, 1);
    l0 += __shfl_xor_sync(0xFFFFFFFFu, l0, 2);
    l1 += __shfl_xor_sync(0xFFFFFFFFu, l1, 1);
    l1 += __shfl_xor_sync(0xFFFFFFFFu, l1, 2);
    float inv0 = 1.0f / l0, inv1 = 1.0f / l1;

    int b_ = bh >> 4, h = bh & 15;
    int t0 = q0 + qr0 + (lane >> 2);
    size_t r0 = ((size_t)b_ * TT + t0) * DIMC;
    size_t r1 = r0 + (size_t)8 * DIMC;
    int coff = h * 64 + (lane & 3) * 2;
#pragma unroll
    for (int nf = 0; nf < 8; ++nf) {
        int col = coff + nf * 8;
        *(uint32_t*)(g_ah + r0 + col) =
            packh2(__float2half_rn(o[nf][0] * inv0), __float2half_rn(o[nf][1] * inv0));
        *(uint32_t*)(g_ah + r1 + col) =
            packh2(__float2half_rn(o[nf][2] * inv1), __float2half_rn(o[nf][3] * inv1));
    }
}

// ============================================================================
// Launch
// ============================================================================
extern "C" void kernel_launch(void* const* d_in, const int* in_sizes, int n_in,
                              void* d_out, int out_size)
{
    (void)in_sizes; (void)n_in; (void)out_size;
    const float* x     = (const float*)d_in[0];
    const float* w_qkv = (const float*)d_in[1];
    const float* b_qkv = (const float*)d_in[2];
    const float* w_out = (const float*)d_in[3];
    const float* b_out = (const float*)d_in[4];
    const float* pos   = (const float*)d_in[5];
    float* out = (float*)d_out;

    cudaFuncSetAttribute(hmma_gemm<1>, cudaFuncAttributeMaxDynamicSharedMemorySize, GEMM_SMEM);
    cudaFuncSetAttribute(hmma_gemm<0>, cudaFuncAttributeMaxDynamicSharedMemorySize, GEMM_SMEM);
    cudaFuncSetAttribute(attn2, cudaFuncAttributeMaxDynamicSharedMemorySize, ATT_SMEM);

    // 0) convert input to fp16 + transpose/split weights (fp16 hi/lo)
    conv_kernel<<<MTOT * DIMC / 1024, 256>>>(x);
    transpose_split<0><<<dim3(N_QKV / 32, DIMC / 32), dim3(32, 8)>>>(w_qkv);
    transpose_split<1><<<dim3(DIMC / 32, DIMC / 32), dim3(32, 8)>>>(w_out);

    // 1) QKV projection + bias (+pos, q-scale) -> fp16 Q hi/lo, K, V
    hmma_gemm<1><<<dim3(N_QKV / 128, MTOT / 128), 256, GEMM_SMEM>>>(b_qkv, pos, nullptr);

    // 2) HMMA flash attention -> fp16 attn out
    attn2<<<dim3(TT / 128, BB * NH), 256, ATT_SMEM>>>();

    // 3) output projection + bias
    hmma_gemm<0><<<dim3(DIMC / 128, MTOT / 128), 256, GEMM_SMEM>>>(b_out, nullptr, out);
}

// round 11
// speedup vs baseline: 1.5693x; 1.1617x over previous
#include <cuda_runtime.h>
#include <cuda_bf16.h>
#include <cuda_fp16.h>
#include <cstdint>

// Problem constants
#define BB   2
#define TT   2048
#define DIMC 1024
#define NH   16
#define HD   64
#define MTOT (BB * TT)          // 4096
#define N_QKV (3 * DIMC)        // 3072

// q pre-scale: 1/sqrt(64) * log2(e)
#define QSCALE 0.18033688011112042f

// -------- scratch (device globals; no allocation allowed) --------
__device__ __half g_qh[BB * NH * TT * HD];
__device__ __half g_kh[BB * NH * TT * HD];
__device__ __half g_vh[BB * NH * TT * HD];
__device__ __half g_xh[MTOT * DIMC];          // x (fp16)
__device__ __half g_ah[MTOT * DIMC];          // attn out [B,T,C] (fp16)
__device__ __half g_wqh[N_QKV * DIMC], g_wql[N_QKV * DIMC];    // W_qkv^T hi/lo
__device__ __half g_woh[DIMC * DIMC], g_wol[DIMC * DIMC];      // W_out^T hi/lo

// ============================================================================
// Helpers (plain-target PTX: cp.async / ldmatrix / mma.sync)
// ============================================================================
__device__ __forceinline__ uint32_t smem_u32(const void* p) {
    uint32_t a;
    asm("{ .reg .u64 t; cvta.to.shared.u64 t, %1; cvt.u32.u64 %0, t; }" : "=r"(a) : "l"(p));
    return a;
}
__device__ __forceinline__ void cp16(uint32_t dst, const void* src) {
    asm volatile("cp.async.cg.shared.global [%0], [%1], 16;" :: "r"(dst), "l"(src));
}
__device__ __forceinline__ void cp_commit() { asm volatile("cp.async.commit_group;" ::: "memory"); }
__device__ __forceinline__ void cp_wait0()  { asm volatile("cp.async.wait_group 0;" ::: "memory"); }
__device__ __forceinline__ void cp_wait1()  { asm volatile("cp.async.wait_group 1;" ::: "memory"); }

__device__ __forceinline__ void ldsm4(uint32_t& r0, uint32_t& r1, uint32_t& r2, uint32_t& r3,
                                      uint32_t addr) {
    asm volatile("ldmatrix.sync.aligned.m8n8.x4.shared.b16 {%0,%1,%2,%3}, [%4];"
                 : "=r"(r0), "=r"(r1), "=r"(r2), "=r"(r3) : "r"(addr));
}
__device__ __forceinline__ void ldsm4t(uint32_t& r0, uint32_t& r1, uint32_t& r2, uint32_t& r3,
                                       uint32_t addr) {
    asm volatile("ldmatrix.sync.aligned.m8n8.x4.trans.shared.b16 {%0,%1,%2,%3}, [%4];"
                 : "=r"(r0), "=r"(r1), "=r"(r2), "=r"(r3) : "r"(addr));
}
__device__ __forceinline__ void ldsm2(uint32_t& r0, uint32_t& r1, uint32_t addr) {
    asm volatile("ldmatrix.sync.aligned.m8n8.x2.shared.b16 {%0,%1}, [%2];"
                 : "=r"(r0), "=r"(r1) : "r"(addr));
}
__device__ __forceinline__ void mma_fp(float* c, const uint32_t* a, uint32_t b0, uint32_t b1) {
    asm volatile(
        "mma.sync.aligned.m16n8k16.row.col.f32.f16.f16.f32 "
        "{%0,%1,%2,%3}, {%4,%5,%6,%7}, {%8,%9}, {%0,%1,%2,%3};"
        : "+f"(c[0]), "+f"(c[1]), "+f"(c[2]), "+f"(c[3])
        : "r"(a[0]), "r"(a[1]), "r"(a[2]), "r"(a[3]), "r"(b0), "r"(b1));
}

// exp2 on FFMA pipe: magic-number round + degree-5 Taylor, t <= 0
__device__ __forceinline__ float exp2p(float t) {
    t = fmaxf(t, -80.0f);
    float k = t + 12582912.0f;
    int ik = __float_as_int(k) << 23;
    float f = t - (k - 12582912.0f);
    float r = 1.3333558146e-3f;
    r = fmaf(r, f, 9.6181291076e-3f);
    r = fmaf(r, f, 5.5504108664e-2f);
    r = fmaf(r, f, 2.4022650696e-1f);
    r = fmaf(r, f, 6.9314718056e-1f);
    r = fmaf(r, f, 1.0f);
    return __int_as_float(__float_as_int(r) + ik);
}

__device__ __forceinline__ uint32_t packh2(__half a, __half b) {
    __half2 h = __halves2half2(a, b);
    return *(uint32_t*)&h;
}
__device__ __forceinline__ void split2h(float a, float b, uint32_t& hi, uint32_t& lo) {
    __half ha = __float2half_rn(a), hb = __float2half_rn(b);
    hi = packh2(ha, hb);
    lo = packh2(__float2half_rn(a - __half2float(ha)),
                __float2half_rn(b - __half2float(hb)));
}

// ============================================================================
// fp32 -> fp16 conversion (x), vectorized float4
// ============================================================================
__global__ void conv_kernel(const float* __restrict__ src) {
    int i = (blockIdx.x * blockDim.x + threadIdx.x) * 4;
    float4 v = *(const float4*)(src + i);
    *(uint32_t*)(g_xh + i)     = packh2(__float2half_rn(v.x), __float2half_rn(v.y));
    *(uint32_t*)(g_xh + i + 2) = packh2(__float2half_rn(v.z), __float2half_rn(v.w));
}

// ============================================================================
// W[K=1024, N] -> W^T split into [N, 1024] fp16 hi/lo
// ============================================================================
template <int W>
__global__ void transpose_split(const float* __restrict__ Win) {
    const int N = (W == 0) ? N_QKV : DIMC;
    __half* Th = (W == 0) ? g_wqh : g_woh;
    __half* Tl = (W == 0) ? g_wql : g_wol;
    __shared__ float t[32][33];
    int tx = threadIdx.x, ty = threadIdx.y;
    int n0 = blockIdx.x * 32, k0 = blockIdx.y * 32;
#pragma unroll
    for (int j = 0; j < 32; j += 8)
        t[ty + j][tx] = Win[(size_t)(k0 + ty + j) * N + n0 + tx];
    __syncthreads();
#pragma unroll
    for (int j = 0; j < 32; j += 8) {
        float v = t[tx][ty + j];
        size_t o = (size_t)(n0 + ty + j) * DIMC + k0 + tx;
        __half h = __float2half_rn(v);
        Th[o] = h;
        Tl[o] = __float2half_rn(v - __half2float(h));
    }
}

// ============================================================================
// HMMA fp16 GEMM (round-10 winner, unchanged): C = A·(Bh+Bl).
// 3-stage cp.async ring, one barrier/iter. 128x128 CTA, BK=32, 8 warps.
// MODE 1 -> fp16 Q (+pos, scaled), K, V. MODE 0 -> fp32 Cout + bias.
// ============================================================================
#define PADK   40                  // 32 + 8 fp16 padding (80B rows)
#define MAT_B  (128 * PADK * 2)    // 10240 B
#define STG_B  (3 * MAT_B)         // 30720 B (A, Bh, Bl)
#define NSTG   3
#define GEMM_SMEM (NSTG * STG_B)   // 92160 B

template <int MODE>
__global__ __launch_bounds__(256) void hmma_gemm(
    const float* __restrict__ bias, const float* __restrict__ pos,
    float* __restrict__ Cout)
{
    const __half* Aa = (MODE == 1) ? g_xh : g_ah;
    const __half* Bh = (MODE == 1) ? g_wqh : g_woh;
    const __half* Bl = (MODE == 1) ? g_wql : g_wol;

    extern __shared__ char smraw[];
    const uint32_t sbase = smem_u32(smraw);

    const int tid = threadIdx.x;
    const int wid = tid >> 5, lane = tid & 31;
    const int wm0 = (wid >> 2) * 64;
    const int wn0 = (wid & 3) * 32;

    const int row0 = blockIdx.y * 128;
    const int col0 = blockIdx.x * 128;

    const __half* srcs[3] = {
        Aa + (size_t)row0 * DIMC,
        Bh + (size_t)col0 * DIMC,
        Bl + (size_t)col0 * DIMC };

    const int lr0 = tid >> 2;
    const int lch = tid & 3;

    auto load_chunk = [&](int kc, int s) {
        uint32_t st = sbase + (uint32_t)s * STG_B;
#pragma unroll
        for (int mmat = 0; mmat < 3; ++mmat) {
            const __half* src = srcs[mmat] + (size_t)kc * 32;
            uint32_t mb = st + (uint32_t)mmat * MAT_B;
#pragma unroll
            for (int i = 0; i < 2; ++i) {
                int r = lr0 + i * 64;
                cp16(mb + (uint32_t)(r * PADK + lch * 8) * 2,
                     src + (size_t)r * DIMC + lch * 8);
            }
        }
    };

    float acc[4][4][4];
#pragma unroll
    for (int i = 0; i < 4; ++i)
#pragma unroll
        for (int j = 0; j < 4; ++j)
#pragma unroll
            for (int k = 0; k < 4; ++k) acc[i][j][k] = 0.0f;

    const int aRow = lane & 15;
    const int aColHalf = (lane >> 4) * 8;
    const int bRow = lane & 7;
    const int bColHalf = ((lane >> 3) & 1) * 8;

    load_chunk(0, 0); cp_commit();
    load_chunk(1, 1); cp_commit();

    const int NC = DIMC / 32;   // 32
    int sc = 0;
    for (int kc = 0; kc < NC; ++kc) {
        if (kc + 1 < NC) cp_wait1(); else cp_wait0();
        __syncthreads();
        if (kc + 2 < NC) {
            int s2 = sc + 2; if (s2 >= NSTG) s2 -= NSTG;
            load_chunk(kc + 2, s2);
            cp_commit();
        }

        uint32_t st = sbase + (uint32_t)sc * STG_B;
        uint32_t aA = st, bH = st + MAT_B, bL = st + 2 * MAT_B;

#pragma unroll
        for (int ks = 0; ks < 2; ++ks) {
            uint32_t ah[4][4], bh[4][2], bl[4][2];
            int kcol = ks * 16;
#pragma unroll
            for (int mf = 0; mf < 4; ++mf) {
                uint32_t off = (uint32_t)((wm0 + mf * 16 + aRow) * PADK + kcol + aColHalf) * 2;
                ldsm4(ah[mf][0], ah[mf][1], ah[mf][2], ah[mf][3], aA + off);
            }
#pragma unroll
            for (int nf = 0; nf < 4; ++nf) {
                uint32_t off = (uint32_t)((wn0 + nf * 8 + bRow) * PADK + kcol + bColHalf) * 2;
                ldsm2(bh[nf][0], bh[nf][1], bH + off);
                ldsm2(bl[nf][0], bl[nf][1], bL + off);
            }
#pragma unroll
            for (int mf = 0; mf < 4; ++mf)
#pragma unroll
                for (int nf = 0; nf < 4; ++nf) {
                    mma_fp(acc[mf][nf], ah[mf], bh[nf][0], bh[nf][1]);
                    mma_fp(acc[mf][nf], ah[mf], bl[nf][0], bl[nf][1]);
                }
        }

        ++sc; if (sc == NSTG) sc = 0;
    }

    const int erow = lane >> 2;
    const int ecol = (lane & 3) * 2;
#pragma unroll
    for (int mf = 0; mf < 4; ++mf) {
#pragma unroll
        for (int half = 0; half < 2; ++half) {
            int m = row0 + wm0 + mf * 16 + erow + half * 8;
            int b_ = m >> 11, t = m & (TT - 1);
#pragma unroll
            for (int nf = 0; nf < 4; ++nf) {
                int n = col0 + wn0 + nf * 8 + ecol;
                float vx = acc[mf][nf][half * 2 + 0] + bias[n + 0];
                float vy = acc[mf][nf][half * 2 + 1] + bias[n + 1];
                if (MODE == 0) {
                    float2 v = {vx, vy};
                    *(float2*)(Cout + (size_t)m * DIMC + n) = v;
                } else {
                    int sec = n >> 10;
                    int cc = n & (DIMC - 1);
                    int h = cc >> 6, d = cc & 63;
                    size_t idx = (((size_t)(b_ * NH + h)) * TT + t) * HD + d;
                    if (sec == 0) {
                        float qx = (vx + pos[cc + 0]) * QSCALE;
                        float qy = (vy + pos[cc + 1]) * QSCALE;
                        *(uint32_t*)(g_qh + idx) =
                            packh2(__float2half_rn(qx), __float2half_rn(qy));
                    } else if (sec == 1) {
                        *(uint32_t*)(g_kh + idx) =
                            packh2(__float2half_rn(vx), __float2half_rn(vy));
                    } else {
                        *(uint32_t*)(g_vh + idx) =
                            packh2(__float2half_rn(vx), __float2half_rn(vy));
                    }
                }
            }
        }
    }
}

// ============================================================================
// HMMA flash attention: 128 q-rows/CTA, Bc=64.
// SINGLE-product QK^T (Q fp16) and PV (P fp16). K,V fp16. fp16 output.
// Smem: one Q buffer + 2-stage KV -> 55.3 KB -> 4 CTAs/SM.
// ============================================================================
#define AT_PADH 72                      // fp16 elems per smem row (144 B)
#define Q_BYTES (128 * AT_PADH * 2)     // 18432
#define KV_MAT  (64 * AT_PADH * 2)      // 9216
#define KV_STAGE (2 * KV_MAT)           // 18432 (Kh, Vh)
#define ATT_SMEM (Q_BYTES + 2 * KV_STAGE)   // 55296

__global__ __launch_bounds__(256) void attn2()
{
    extern __shared__ char smraw[];
    const uint32_t sb = smem_u32(smraw);
    const uint32_t sQh = sb;
    const uint32_t sKV = sb + Q_BYTES;

    const int tid = threadIdx.x;
    const int lane = tid & 31;
    const int qi = gridDim.x - 1 - blockIdx.x;   // heavy tiles first
    const int bh = blockIdx.y;
    const int q0 = qi * 128;
    const int qr0 = (tid >> 5) * 16;

    const __half* qhp = g_qh + (size_t)bh * TT * HD;
    const __half* kvsrc[2] = {
        g_kh + (size_t)bh * TT * HD, g_vh + (size_t)bh * TT * HD };

    auto prefetchKV = [&](int j, uint32_t dst) {
        int kb = j * 64;
#pragma unroll
        for (int i = 0; i < 4; ++i) {
            int c = tid + i * 256;          // 0..1023
            int mat = c >> 9, rem = c & 511;
            int r = rem >> 3, ch = rem & 7;
            cp16(dst + (uint32_t)mat * KV_MAT + (uint32_t)(r * 144 + ch * 16),
                 kvsrc[mat] + (size_t)(kb + r) * HD + ch * 8);
        }
    };

    // Q tile (1024 cp16 / 256 thr = 4 each) + first K/V tile
#pragma unroll
    for (int i = 0; i < 4; ++i) {
        int c = tid + i * 256;
        int r = c >> 3, ch = c & 7;
        cp16(sQh + (uint32_t)(r * 144 + ch * 16), qhp + (size_t)(q0 + r) * HD + ch * 8);
    }
    prefetchKV(0, sKV);
    cp_commit();
    cp_wait0();
    __syncthreads();

    // persistent Q fragments
    uint32_t fqh[4][4];
    {
        int rr = qr0 + (lane & 15);
#pragma unroll
        for (int kf = 0; kf < 4; ++kf) {
            int cc = kf * 16 + ((lane & 16) ? 8 : 0);
            uint32_t off = (uint32_t)(rr * 144 + cc * 2);
            ldsm4(fqh[kf][0], fqh[kf][1], fqh[kf][2], fqh[kf][3], sQh + off);
        }
    }

    float o[8][4];
#pragma unroll
    for (int i = 0; i < 8; ++i)
#pragma unroll
        for (int k = 0; k < 4; ++k) o[i][k] = 0.0f;
    float m0 = -1e30f, m1 = -1e30f, l0 = 0.0f, l1 = 0.0f;

    const int ntiles = 2 * qi + 2;
    for (int j = 0; j < ntiles; ++j) {
        uint32_t stage = sKV + (uint32_t)(j & 1) * KV_STAGE;
        if (j + 1 < ntiles) {
            prefetchKV(j + 1, sKV + (uint32_t)((j + 1) & 1) * KV_STAGE);
            cp_commit();
        }

        // ---- S = Q K^T (single product) ----
        float c[8][4];
#pragma unroll
        for (int i = 0; i < 8; ++i)
#pragma unroll
            for (int k = 0; k < 4; ++k) c[i][k] = 0.0f;

        uint32_t Kh = stage;
        {
            int rb = ((lane & 16) ? 8 : 0) + (lane & 7);
            int cb = ((lane & 8) ? 8 : 0);
#pragma unroll
            for (int kf = 0; kf < 4; ++kf) {
#pragma unroll
                for (int jp = 0; jp < 4; ++jp) {
                    uint32_t off = (uint32_t)((jp * 16 + rb) * 144 + (kf * 16 + cb) * 2);
                    uint32_t h0, h1, h2, h3;
                    ldsm4(h0, h1, h2, h3, Kh + off);
                    mma_fp(c[2 * jp],     fqh[kf], h0, h1);
                    mma_fp(c[2 * jp + 1], fqh[kf], h2, h3);
                }
            }
        }

        // ---- causal mask (only last two tiles) ----
        if (j >= 2 * qi) {
            int row0 = q0 + qr0 + (lane >> 2);
            int kb = j * 64 + (lane & 3) * 2;
#pragma unroll
            for (int nf = 0; nf < 8; ++nf) {
                int key = kb + nf * 8;
                if (key     > row0)     c[nf][0] = -1e30f;
                if (key + 1 > row0)     c[nf][1] = -1e30f;
                if (key     > row0 + 8) c[nf][2] = -1e30f;
                if (key + 1 > row0 + 8) c[nf][3] = -1e30f;
            }
        }

        // ---- online softmax ----
        float v0 = -1e30f, v1 = -1e30f;
#pragma unroll
        for (int nf = 0; nf < 8; ++nf) {
            v0 = fmaxf(v0, fmaxf(c[nf][0], c[nf][1]));
            v1 = fmaxf(v1, fmaxf(c[nf][2], c[nf][3]));
        }
        v0 = fmaxf(v0, __shfl_xor_sync(0xFFFFFFFFu, v0, 1));
        v0 = fmaxf(v0, __shfl_xor_sync(0xFFFFFFFFu, v0, 2));
        v1 = fmaxf(v1, __shfl_xor_sync(0xFFFFFFFFu, v1, 1));
        v1 = fmaxf(v1, __shfl_xor_sync(0xFFFFFFFFu, v1, 2));
        float mn0 = fmaxf(m0, v0), mn1 = fmaxf(m1, v1);
        float a0 = exp2p(m0 - mn0), a1 = exp2p(m1 - mn1);
        m0 = mn0; m1 = mn1;
        l0 *= a0; l1 *= a1;
#pragma unroll
        for (int nf = 0; nf < 8; ++nf) {
            o[nf][0] *= a0; o[nf][1] *= a0;
            o[nf][2] *= a1; o[nf][3] *= a1;
        }

        // ---- P (exp2 poly, fp16) + P V (single product) ----
        uint32_t Vh = stage + KV_MAT;
        int vrb = ((lane & 8) ? 8 : 0) + (lane & 7);
        int vcb = ((lane & 16) ? 8 : 0);
#pragma unroll
        for (int t = 0; t < 4; ++t) {
            float p00 = exp2p(c[2 * t][0] - m0), p01 = exp2p(c[2 * t][1] - m0);
            float p02 = exp2p(c[2 * t][2] - m1), p03 = exp2p(c[2 * t][3] - m1);
            float p10 = exp2p(c[2 * t + 1][0] - m0), p11 = exp2p(c[2 * t + 1][1] - m0);
            float p12 = exp2p(c[2 * t + 1][2] - m1), p13 = exp2p(c[2 * t + 1][3] - m1);
            l0 += p00 + p01 + p10 + p11;
            l1 += p02 + p03 + p12 + p13;

            uint32_t ph[4];
            ph[0] = packh2(__float2half_rn(p00), __float2half_rn(p01));
            ph[1] = packh2(__float2half_rn(p02), __float2half_rn(p03));
            ph[2] = packh2(__float2half_rn(p10), __float2half_rn(p11));
            ph[3] = packh2(__float2half_rn(p12), __float2half_rn(p13));

#pragma unroll
            for (int dp = 0; dp < 4; ++dp) {
                uint32_t off = (uint32_t)((t * 16 + vrb) * 144 + (dp * 16 + vcb) * 2);
                uint32_t h0, h1, h2, h3;
                ldsm4t(h0, h1, h2, h3, Vh + off);
                mma_fp(o[2 * dp],     ph, h0, h1);
                mma_fp(o[2 * dp + 1], ph, h2, h3);
            }
        }

        if (j + 1 < ntiles) cp_wait0();
        __syncthreads();
    }

    // ---- epilogue: normalize, write fp16 [B,T,C] ----
    l0 += __shfl_xor_sync(0xFFFFFFFFu, l0, 1);
    l0 += __shfl_xor_sync(0xFFFFFFFFu, l0, 2);
    l1 += __shfl_xor_sync(0xFFFFFFFFu, l1, 1);
    l1 += __shfl_xor_sync(0xFFFFFFFFu, l1, 2);
    float inv0 = 1.0f / l0, inv1 = 1.0f / l1;

    int b_ = bh >> 4, h = bh & 15;
    int t0 = q0 + qr0 + (lane >> 2);
    size_t r0 = ((size_t)b_ * TT + t0) * DIMC;
    size_t r1 = r0 + (size_t)8 * DIMC;
    int coff = h * 64 + (lane & 3) * 2;
#pragma unroll
    for (int nf = 0; nf < 8; ++nf) {
        int col = coff + nf * 8;
        *(uint32_t*)(g_ah + r0 + col) =
            packh2(__float2half_rn(o[nf][0] * inv0), __float2half_rn(o[nf][1] * inv0));
        *(uint32_t*)(g_ah + r1 + col) =
            packh2(__float2half_rn(o[nf][2] * inv1), __float2half_rn(o[nf][3] * inv1));
    }
}

// ============================================================================
// Launch
// ============================================================================
extern "C" void kernel_launch(void* const* d_in, const int* in_sizes, int n_in,
                              void* d_out, int out_size)
{
    (void)in_sizes; (void)n_in; (void)out_size;
    const float* x     = (const float*)d_in[0];
    const float* w_qkv = (const float*)d_in[1];
    const float* b_qkv = (const float*)d_in[2];
    const float* w_out = (const float*)d_in[3];
    const float* b_out = (const float*)d_in[4];
    const float* pos   = (const float*)d_in[5];
    float* out = (float*)d_out;

    cudaFuncSetAttribute(hmma_gemm<1>, cudaFuncAttributeMaxDynamicSharedMemorySize, GEMM_SMEM);
    cudaFuncSetAttribute(hmma_gemm<0>, cudaFuncAttributeMaxDynamicSharedMemorySize, GEMM_SMEM);
    cudaFuncSetAttribute(attn2, cudaFuncAttributeMaxDynamicSharedMemorySize, ATT_SMEM);

    // 0) convert input to fp16 + transpose/split weights (fp16 hi/lo)
    conv_kernel<<<MTOT * DIMC / 1024, 256>>>(x);
    transpose_split<0><<<dim3(N_QKV / 32, DIMC / 32), dim3(32, 8)>>>(w_qkv);
    transpose_split<1><<<dim3(DIMC / 32, DIMC / 32), dim3(32, 8)>>>(w_out);

    // 1) QKV projection + bias (+pos, q-scale) -> fp16 Q, K, V
    hmma_gemm<1><<<dim3(N_QKV / 128, MTOT / 128), 256, GEMM_SMEM>>>(b_qkv, pos, nullptr);

    // 2) HMMA flash attention -> fp16 attn out
    attn2<<<dim3(TT / 128, BB * NH), 256, ATT_SMEM>>>();

    // 3) output projection + bias
    hmma_gemm<0><<<dim3(DIMC / 128, MTOT / 128), 256, GEMM_SMEM>>>(b_out, nullptr, out);
}

// round 12
// speedup vs baseline: 2.2382x; 1.4262x over previous
#include <cuda_runtime.h>
#include <cuda_bf16.h>
#include <cuda_fp16.h>
#include <cstdint>

// Problem constants
#define BB   2
#define TT   2048
#define DIMC 1024
#define NH   16
#define HD   64
#define MTOT (BB * TT)          // 4096
#define N_QKV (3 * DIMC)        // 3072

// q pre-scale: 1/sqrt(64) * log2(e)
#define QSCALE 0.18033688011112042f

// -------- scratch (device globals; no allocation allowed) --------
__device__ __half g_qh[BB * NH * TT * HD];
__device__ __half g_kh[BB * NH * TT * HD];
__device__ __half g_vh[BB * NH * TT * HD];
__device__ __half g_xh[MTOT * DIMC];          // x (fp16)
__device__ __half g_ah[MTOT * DIMC];          // attn out [B,T,C] (fp16)
__device__ __half g_wqh[N_QKV * DIMC];        // W_qkv^T (fp16)
__device__ __half g_woh[DIMC * DIMC];         // W_out^T (fp16)

// ============================================================================
// Helpers (plain-target PTX: cp.async / ldmatrix / mma.sync)
// ============================================================================
__device__ __forceinline__ uint32_t smem_u32(const void* p) {
    uint32_t a;
    asm("{ .reg .u64 t; cvta.to.shared.u64 t, %1; cvt.u32.u64 %0, t; }" : "=r"(a) : "l"(p));
    return a;
}
__device__ __forceinline__ void cp16(uint32_t dst, const void* src) {
    asm volatile("cp.async.cg.shared.global [%0], [%1], 16;" :: "r"(dst), "l"(src));
}
__device__ __forceinline__ void cp_commit() { asm volatile("cp.async.commit_group;" ::: "memory"); }
__device__ __forceinline__ void cp_wait0()  { asm volatile("cp.async.wait_group 0;" ::: "memory"); }
__device__ __forceinline__ void cp_wait1()  { asm volatile("cp.async.wait_group 1;" ::: "memory"); }

__device__ __forceinline__ void ldsm4(uint32_t& r0, uint32_t& r1, uint32_t& r2, uint32_t& r3,
                                      uint32_t addr) {
    asm volatile("ldmatrix.sync.aligned.m8n8.x4.shared.b16 {%0,%1,%2,%3}, [%4];"
                 : "=r"(r0), "=r"(r1), "=r"(r2), "=r"(r3) : "r"(addr));
}
__device__ __forceinline__ void ldsm4t(uint32_t& r0, uint32_t& r1, uint32_t& r2, uint32_t& r3,
                                       uint32_t addr) {
    asm volatile("ldmatrix.sync.aligned.m8n8.x4.trans.shared.b16 {%0,%1,%2,%3}, [%4];"
                 : "=r"(r0), "=r"(r1), "=r"(r2), "=r"(r3) : "r"(addr));
}
__device__ __forceinline__ void ldsm2(uint32_t& r0, uint32_t& r1, uint32_t addr) {
    asm volatile("ldmatrix.sync.aligned.m8n8.x2.shared.b16 {%0,%1}, [%2];"
                 : "=r"(r0), "=r"(r1) : "r"(addr));
}
__device__ __forceinline__ void mma_fp(float* c, const uint32_t* a, uint32_t b0, uint32_t b1) {
    asm volatile(
        "mma.sync.aligned.m16n8k16.row.col.f32.f16.f16.f32 "
        "{%0,%1,%2,%3}, {%4,%5,%6,%7}, {%8,%9}, {%0,%1,%2,%3};"
        : "+f"(c[0]), "+f"(c[1]), "+f"(c[2]), "+f"(c[3])
        : "r"(a[0]), "r"(a[1]), "r"(a[2]), "r"(a[3]), "r"(b0), "r"(b1));
}

// exp2 on FFMA pipe: magic-number round + degree-5 Taylor, t <= 0
__device__ __forceinline__ float exp2p(float t) {
    t = fmaxf(t, -80.0f);
    float k = t + 12582912.0f;
    int ik = __float_as_int(k) << 23;
    float f = t - (k - 12582912.0f);
    float r = 1.3333558146e-3f;
    r = fmaf(r, f, 9.6181291076e-3f);
    r = fmaf(r, f, 5.5504108664e-2f);
    r = fmaf(r, f, 2.4022650696e-1f);
    r = fmaf(r, f, 6.9314718056e-1f);
    r = fmaf(r, f, 1.0f);
    return __int_as_float(__float_as_int(r) + ik);
}

__device__ __forceinline__ uint32_t packh2(__half a, __half b) {
    __half2 h = __halves2half2(a, b);
    return *(uint32_t*)&h;
}

// ============================================================================
// fp32 -> fp16 conversion (x), vectorized float4
// ============================================================================
__global__ void conv_kernel(const float* __restrict__ src) {
    int i = (blockIdx.x * blockDim.x + threadIdx.x) * 4;
    float4 v = *(const float4*)(src + i);
    *(uint32_t*)(g_xh + i)     = packh2(__float2half_rn(v.x), __float2half_rn(v.y));
    *(uint32_t*)(g_xh + i + 2) = packh2(__float2half_rn(v.z), __float2half_rn(v.w));
}

// ============================================================================
// W[K=1024, N] -> W^T [N, 1024] fp16
// ============================================================================
template <int W>
__global__ void transpose_conv(const float* __restrict__ Win) {
    const int N = (W == 0) ? N_QKV : DIMC;
    __half* Th = (W == 0) ? g_wqh : g_woh;
    __shared__ float t[32][33];
    int tx = threadIdx.x, ty = threadIdx.y;
    int n0 = blockIdx.x * 32, k0 = blockIdx.y * 32;
#pragma unroll
    for (int j = 0; j < 32; j += 8)
        t[ty + j][tx] = Win[(size_t)(k0 + ty + j) * N + n0 + tx];
    __syncthreads();
#pragma unroll
    for (int j = 0; j < 32; j += 8) {
        float v = t[tx][ty + j];
        Th[(size_t)(n0 + ty + j) * DIMC + k0 + tx] = __float2half_rn(v);
    }
}

// ============================================================================
// HMMA fp16 GEMM: C = A·B, both single fp16. 3-stage cp.async ring, one
// barrier/iter. 128x128 CTA, BK=32, 8 warps (2x4), 64x32 warp tiles.
// MODE 1 -> fp16 Q (+pos, scaled), K, V. MODE 0 -> fp32 Cout + bias.
// ============================================================================
#define PADK   40                  // 32 + 8 fp16 padding (80B rows)
#define MAT_B  (128 * PADK * 2)    // 10240 B
#define STG_B  (2 * MAT_B)         // 20480 B (A, B)
#define NSTG   3
#define GEMM_SMEM (NSTG * STG_B)   // 61440 B

template <int MODE>
__global__ __launch_bounds__(256) void hmma_gemm(
    const float* __restrict__ bias, const float* __restrict__ pos,
    float* __restrict__ Cout)
{
    const __half* Aa = (MODE == 1) ? g_xh : g_ah;
    const __half* Bb = (MODE == 1) ? g_wqh : g_woh;

    extern __shared__ char smraw[];
    const uint32_t sbase = smem_u32(smraw);

    const int tid = threadIdx.x;
    const int wid = tid >> 5, lane = tid & 31;
    const int wm0 = (wid >> 2) * 64;
    const int wn0 = (wid & 3) * 32;

    const int row0 = blockIdx.y * 128;
    const int col0 = blockIdx.x * 128;

    const __half* srcs[2] = {
        Aa + (size_t)row0 * DIMC,
        Bb + (size_t)col0 * DIMC };

    const int lr0 = tid >> 2;           // 0..63, 2 passes -> 128 rows
    const int lch = tid & 3;            // 16B chunk in 64B row

    auto load_chunk = [&](int kc, int s) {
        uint32_t st = sbase + (uint32_t)s * STG_B;
#pragma unroll
        for (int mmat = 0; mmat < 2; ++mmat) {
            const __half* src = srcs[mmat] + (size_t)kc * 32;
            uint32_t mb = st + (uint32_t)mmat * MAT_B;
#pragma unroll
            for (int i = 0; i < 2; ++i) {
                int r = lr0 + i * 64;
                cp16(mb + (uint32_t)(r * PADK + lch * 8) * 2,
                     src + (size_t)r * DIMC + lch * 8);
            }
        }
    };

    float acc[4][4][4];
#pragma unroll
    for (int i = 0; i < 4; ++i)
#pragma unroll
        for (int j = 0; j < 4; ++j)
#pragma unroll
            for (int k = 0; k < 4; ++k) acc[i][j][k] = 0.0f;

    const int aRow = lane & 15;
    const int aColHalf = (lane >> 4) * 8;
    const int bRow = lane & 7;
    const int bColHalf = ((lane >> 3) & 1) * 8;

    load_chunk(0, 0); cp_commit();
    load_chunk(1, 1); cp_commit();

    const int NC = DIMC / 32;   // 32
    int sc = 0;
    for (int kc = 0; kc < NC; ++kc) {
        if (kc + 1 < NC) cp_wait1(); else cp_wait0();
        __syncthreads();
        if (kc + 2 < NC) {
            int s2 = sc + 2; if (s2 >= NSTG) s2 -= NSTG;
            load_chunk(kc + 2, s2);
            cp_commit();
        }

        uint32_t st = sbase + (uint32_t)sc * STG_B;
        uint32_t aA = st, bB = st + MAT_B;

#pragma unroll
        for (int ks = 0; ks < 2; ++ks) {
            uint32_t ah[4][4], bh[4][2];
            int kcol = ks * 16;
#pragma unroll
            for (int mf = 0; mf < 4; ++mf) {
                uint32_t off = (uint32_t)((wm0 + mf * 16 + aRow) * PADK + kcol + aColHalf) * 2;
                ldsm4(ah[mf][0], ah[mf][1], ah[mf][2], ah[mf][3], aA + off);
            }
#pragma unroll
            for (int nf = 0; nf < 4; ++nf) {
                uint32_t off = (uint32_t)((wn0 + nf * 8 + bRow) * PADK + kcol + bColHalf) * 2;
                ldsm2(bh[nf][0], bh[nf][1], bB + off);
            }
#pragma unroll
            for (int mf = 0; mf < 4; ++mf)
#pragma unroll
                for (int nf = 0; nf < 4; ++nf)
                    mma_fp(acc[mf][nf], ah[mf], bh[nf][0], bh[nf][1]);
        }

        ++sc; if (sc == NSTG) sc = 0;
    }

    const int erow = lane >> 2;
    const int ecol = (lane & 3) * 2;
#pragma unroll
    for (int mf = 0; mf < 4; ++mf) {
#pragma unroll
        for (int half = 0; half < 2; ++half) {
            int m = row0 + wm0 + mf * 16 + erow + half * 8;
            int b_ = m >> 11, t = m & (TT - 1);
#pragma unroll
            for (int nf = 0; nf < 4; ++nf) {
                int n = col0 + wn0 + nf * 8 + ecol;
                float vx = acc[mf][nf][half * 2 + 0] + bias[n + 0];
                float vy = acc[mf][nf][half * 2 + 1] + bias[n + 1];
                if (MODE == 0) {
                    float2 v = {vx, vy};
                    *(float2*)(Cout + (size_t)m * DIMC + n) = v;
                } else {
                    int sec = n >> 10;
                    int cc = n & (DIMC - 1);
                    int h = cc >> 6, d = cc & 63;
                    size_t idx = (((size_t)(b_ * NH + h)) * TT + t) * HD + d;
                    if (sec == 0) {
                        float qx = (vx + pos[cc + 0]) * QSCALE;
                        float qy = (vy + pos[cc + 1]) * QSCALE;
                        *(uint32_t*)(g_qh + idx) =
                            packh2(__float2half_rn(qx), __float2half_rn(qy));
                    } else if (sec == 1) {
                        *(uint32_t*)(g_kh + idx) =
                            packh2(__float2half_rn(vx), __float2half_rn(vy));
                    } else {
                        *(uint32_t*)(g_vh + idx) =
                            packh2(__float2half_rn(vx), __float2half_rn(vy));
                    }
                }
            }
        }
    }
}

// ============================================================================
// HMMA flash attention (round-11 winner, unchanged): 128 q-rows/CTA, Bc=64.
// Single-product QK^T and PV, all fp16 operands. fp16 output.
// ============================================================================
#define AT_PADH 72                      // fp16 elems per smem row (144 B)
#define Q_BYTES (128 * AT_PADH * 2)     // 18432
#define KV_MAT  (64 * AT_PADH * 2)      // 9216
#define KV_STAGE (2 * KV_MAT)           // 18432 (Kh, Vh)
#define ATT_SMEM (Q_BYTES + 2 * KV_STAGE)   // 55296

__global__ __launch_bounds__(256) void attn2()
{
    extern __shared__ char smraw[];
    const uint32_t sb = smem_u32(smraw);
    const uint32_t sQh = sb;
    const uint32_t sKV = sb + Q_BYTES;

    const int tid = threadIdx.x;
    const int lane = tid & 31;
    const int qi = gridDim.x - 1 - blockIdx.x;   // heavy tiles first
    const int bh = blockIdx.y;
    const int q0 = qi * 128;
    const int qr0 = (tid >> 5) * 16;

    const __half* qhp = g_qh + (size_t)bh * TT * HD;
    const __half* kvsrc[2] = {
        g_kh + (size_t)bh * TT * HD, g_vh + (size_t)bh * TT * HD };

    auto prefetchKV = [&](int j, uint32_t dst) {
        int kb = j * 64;
#pragma unroll
        for (int i = 0; i < 4; ++i) {
            int c = tid + i * 256;          // 0..1023
            int mat = c >> 9, rem = c & 511;
            int r = rem >> 3, ch = rem & 7;
            cp16(dst + (uint32_t)mat * KV_MAT + (uint32_t)(r * 144 + ch * 16),
                 kvsrc[mat] + (size_t)(kb + r) * HD + ch * 8);
        }
    };

#pragma unroll
    for (int i = 0; i < 4; ++i) {
        int c = tid + i * 256;
        int r = c >> 3, ch = c & 7;
        cp16(sQh + (uint32_t)(r * 144 + ch * 16), qhp + (size_t)(q0 + r) * HD + ch * 8);
    }
    prefetchKV(0, sKV);
    cp_commit();
    cp_wait0();
    __syncthreads();

    uint32_t fqh[4][4];
    {
        int rr = qr0 + (lane & 15);
#pragma unroll
        for (int kf = 0; kf < 4; ++kf) {
            int cc = kf * 16 + ((lane & 16) ? 8 : 0);
            uint32_t off = (uint32_t)(rr * 144 + cc * 2);
            ldsm4(fqh[kf][0], fqh[kf][1], fqh[kf][2], fqh[kf][3], sQh + off);
        }
    }

    float o[8][4];
#pragma unroll
    for (int i = 0; i < 8; ++i)
#pragma unroll
        for (int k = 0; k < 4; ++k) o[i][k] = 0.0f;
    float m0 = -1e30f, m1 = -1e30f, l0 = 0.0f, l1 = 0.0f;

    const int ntiles = 2 * qi + 2;
    for (int j = 0; j < ntiles; ++j) {
        uint32_t stage = sKV + (uint32_t)(j & 1) * KV_STAGE;
        if (j + 1 < ntiles) {
            prefetchKV(j + 1, sKV + (uint32_t)((j + 1) & 1) * KV_STAGE);
            cp_commit();
        }

        float c[8][4];
#pragma unroll
        for (int i = 0; i < 8; ++i)
#pragma unroll
            for (int k = 0; k < 4; ++k) c[i][k] = 0.0f;

        uint32_t Kh = stage;
        {
            int rb = ((lane & 16) ? 8 : 0) + (lane & 7);
            int cb = ((lane & 8) ? 8 : 0);
#pragma unroll
            for (int kf = 0; kf < 4; ++kf) {
#pragma unroll
                for (int jp = 0; jp < 4; ++jp) {
                    uint32_t off = (uint32_t)((jp * 16 + rb) * 144 + (kf * 16 + cb) * 2);
                    uint32_t h0, h1, h2, h3;
                    ldsm4(h0, h1, h2, h3, Kh + off);
                    mma_fp(c[2 * jp],     fqh[kf], h0, h1);
                    mma_fp(c[2 * jp + 1], fqh[kf], h2, h3);
                }
            }
        }

        if (j >= 2 * qi) {
            int row0 = q0 + qr0 + (lane >> 2);
            int kb = j * 64 + (lane & 3) * 2;
#pragma unroll
            for (int nf = 0; nf < 8; ++nf) {
                int key = kb + nf * 8;
                if (key     > row0)     c[nf][0] = -1e30f;
                if (key + 1 > row0)     c[nf][1] = -1e30f;
                if (key     > row0 + 8) c[nf][2] = -1e30f;
                if (key + 1 > row0 + 8) c[nf][3] = -1e30f;
            }
        }

        float v0 = -1e30f, v1 = -1e30f;
#pragma unroll
        for (int nf = 0; nf < 8; ++nf) {
            v0 = fmaxf(v0, fmaxf(c[nf][0], c[nf][1]));
            v1 = fmaxf(v1, fmaxf(c[nf][2], c[nf][3]));
        }
        v0 = fmaxf(v0, __shfl_xor_sync(0xFFFFFFFFu, v0, 1));
        v0 = fmaxf(v0, __shfl_xor_sync(0xFFFFFFFFu, v0, 2));
        v1 = fmaxf(v1, __shfl_xor_sync(0xFFFFFFFFu, v1, 1));
        v1 = fmaxf(v1, __shfl_xor_sync(0xFFFFFFFFu, v1, 2));
        float mn0 = fmaxf(m0, v0), mn1 = fmaxf(m1, v1);
        float a0 = exp2p(m0 - mn0), a1 = exp2p(m1 - mn1);
        m0 = mn0; m1 = mn1;
        l0 *= a0; l1 *= a1;
#pragma unroll
        for (int nf = 0; nf < 8; ++nf) {
            o[nf][0] *= a0; o[nf][1] *= a0;
            o[nf][2] *= a1; o[nf][3] *= a1;
        }

        uint32_t Vh = stage + KV_MAT;
        int vrb = ((lane & 8) ? 8 : 0) + (lane & 7);
        int vcb = ((lane & 16) ? 8 : 0);
#pragma unroll
        for (int t = 0; t < 4; ++t) {
            float p00 = exp2p(c[2 * t][0] - m0), p01 = exp2p(c[2 * t][1] - m0);
            float p02 = exp2p(c[2 * t][2] - m1), p03 = exp2p(c[2 * t][3] - m1);
            float p10 = exp2p(c[2 * t + 1][0] - m0), p11 = exp2p(c[2 * t + 1][1] - m0);
            float p12 = exp2p(c[2 * t + 1][2] - m1), p13 = exp2p(c[2 * t + 1][3] - m1);
            l0 += p00 + p01 + p10 + p11;
            l1 += p02 + p03 + p12 + p13;

            uint32_t ph[4];
            ph[0] = packh2(__float2half_rn(p00), __float2half_rn(p01));
            ph[1] = packh2(__float2half_rn(p02), __float2half_rn(p03));
            ph[2] = packh2(__float2half_rn(p10), __float2half_rn(p11));
            ph[3] = packh2(__float2half_rn(p12), __float2half_rn(p13));

#pragma unroll
            for (int dp = 0; dp < 4; ++dp) {
                uint32_t off = (uint32_t)((t * 16 + vrb) * 144 + (dp * 16 + vcb) * 2);
                uint32_t h0, h1, h2, h3;
                ldsm4t(h0, h1, h2, h3, Vh + off);
                mma_fp(o[2 * dp],     ph, h0, h1);
                mma_fp(o[2 * dp + 1], ph, h2, h3);
            }
        }

        if (j + 1 < ntiles) cp_wait0();
        __syncthreads();
    }

    l0 += __shfl_xor_sync(0xFFFFFFFFu, l0, 1);
    l0 += __shfl_xor_sync(0xFFFFFFFFu, l0, 2);
    l1 += __shfl_xor_sync(0xFFFFFFFFu, l1, 1);
    l1 += __shfl_xor_sync(0xFFFFFFFFu, l1, 2);
    float inv0 = 1.0f / l0, inv1 = 1.0f / l1;

    int b_ = bh >> 4, h = bh & 15;
    int t0 = q0 + qr0 + (lane >> 2);
    size_t r0 = ((size_t)b_ * TT + t0) * DIMC;
    size_t r1 = r0 + (size_t)8 * DIMC;
    int coff = h * 64 + (lane & 3) * 2;
#pragma unroll
    for (int nf = 0; nf < 8; ++nf) {
        int col = coff + nf * 8;
        *(uint32_t*)(g_ah + r0 + col) =
            packh2(__float2half_rn(o[nf][0] * inv0), __float2half_rn(o[nf][1] * inv0));
        *(uint32_t*)(g_ah + r1 + col) =
            packh2(__float2half_rn(o[nf][2] * inv1), __float2half_rn(o[nf][3] * inv1));
    }
}

// ============================================================================
// Launch
// ============================================================================
extern "C" void kernel_launch(void* const* d_in, const int* in_sizes, int n_in,
                              void* d_out, int out_size)
{
    (void)in_sizes; (void)n_in; (void)out_size;
    const float* x     = (const float*)d_in[0];
    const float* w_qkv = (const float*)d_in[1];
    const float* b_qkv = (const float*)d_in[2];
    const float* w_out = (const float*)d_in[3];
    const float* b_out = (const float*)d_in[4];
    const float* pos   = (const float*)d_in[5];
    float* out = (float*)d_out;

    cudaFuncSetAttribute(hmma_gemm<1>, cudaFuncAttributeMaxDynamicSharedMemorySize, GEMM_SMEM);
    cudaFuncSetAttribute(hmma_gemm<0>, cudaFuncAttributeMaxDynamicSharedMemorySize, GEMM_SMEM);
    cudaFuncSetAttribute(attn2, cudaFuncAttributeMaxDynamicSharedMemorySize, ATT_SMEM);

    // 0) convert input + transpose/convert weights to fp16
    conv_kernel<<<MTOT * DIMC / 1024, 256>>>(x);
    transpose_conv<0><<<dim3(N_QKV / 32, DIMC / 32), dim3(32, 8)>>>(w_qkv);
    transpose_conv<1><<<dim3(DIMC / 32, DIMC / 32), dim3(32, 8)>>>(w_out);

    // 1) QKV projection + bias (+pos, q-scale) -> fp16 Q, K, V
    hmma_gemm<1><<<dim3(N_QKV / 128, MTOT / 128), 256, GEMM_SMEM>>>(b_qkv, pos, nullptr);

    // 2) HMMA flash attention -> fp16 attn out
    attn2<<<dim3(TT / 128, BB * NH), 256, ATT_SMEM>>>();

    // 3) output projection + bias
    hmma_gemm<0><<<dim3(DIMC / 128, MTOT / 128), 256, GEMM_SMEM>>>(b_out, nullptr, out);
}

// round 13
// speedup vs baseline: 2.3852x; 1.0657x over previous
#include <cuda_runtime.h>
#include <cuda_bf16.h>
#include <cuda_fp16.h>
#include <cstdint>

// Problem constants
#define BB   2
#define TT   2048
#define DIMC 1024
#define NH   16
#define HD   64
#define MTOT (BB * TT)          // 4096
#define N_QKV (3 * DIMC)        // 3072

// q pre-scale: 1/sqrt(64) * log2(e)
#define QSCALE 0.18033688011112042f

// -------- scratch (device globals; no allocation allowed) --------
__device__ __half g_qh[BB * NH * TT * HD];
__device__ __half g_kh[BB * NH * TT * HD];
__device__ __half g_vh[BB * NH * TT * HD];
__device__ __half g_xh[MTOT * DIMC];          // x (fp16)
__device__ __half g_ah[MTOT * DIMC];          // attn out [B,T,C] (fp16)
__device__ __half g_wqh[N_QKV * DIMC];        // W_qkv^T (fp16)
__device__ __half g_woh[DIMC * DIMC];         // W_out^T (fp16)

// ============================================================================
// Helpers (plain-target PTX: cp.async / ldmatrix / mma.sync)
// ============================================================================
__device__ __forceinline__ uint32_t smem_u32(const void* p) {
    uint32_t a;
    asm("{ .reg .u64 t; cvta.to.shared.u64 t, %1; cvt.u32.u64 %0, t; }" : "=r"(a) : "l"(p));
    return a;
}
__device__ __forceinline__ void cp16(uint32_t dst, const void* src) {
    asm volatile("cp.async.cg.shared.global [%0], [%1], 16;" :: "r"(dst), "l"(src));
}
__device__ __forceinline__ void cp_commit() { asm volatile("cp.async.commit_group;" ::: "memory"); }
__device__ __forceinline__ void cp_wait0()  { asm volatile("cp.async.wait_group 0;" ::: "memory"); }
__device__ __forceinline__ void cp_wait1()  { asm volatile("cp.async.wait_group 1;" ::: "memory"); }

__device__ __forceinline__ void ldsm4(uint32_t& r0, uint32_t& r1, uint32_t& r2, uint32_t& r3,
                                      uint32_t addr) {
    asm volatile("ldmatrix.sync.aligned.m8n8.x4.shared.b16 {%0,%1,%2,%3}, [%4];"
                 : "=r"(r0), "=r"(r1), "=r"(r2), "=r"(r3) : "r"(addr));
}
__device__ __forceinline__ void ldsm4t(uint32_t& r0, uint32_t& r1, uint32_t& r2, uint32_t& r3,
                                       uint32_t addr) {
    asm volatile("ldmatrix.sync.aligned.m8n8.x4.trans.shared.b16 {%0,%1,%2,%3}, [%4];"
                 : "=r"(r0), "=r"(r1), "=r"(r2), "=r"(r3) : "r"(addr));
}
__device__ __forceinline__ void ldsm2(uint32_t& r0, uint32_t& r1, uint32_t addr) {
    asm volatile("ldmatrix.sync.aligned.m8n8.x2.shared.b16 {%0,%1}, [%2];"
                 : "=r"(r0), "=r"(r1) : "r"(addr));
}
__device__ __forceinline__ void mma_fp(float* c, const uint32_t* a, uint32_t b0, uint32_t b1) {
    asm volatile(
        "mma.sync.aligned.m16n8k16.row.col.f32.f16.f16.f32 "
        "{%0,%1,%2,%3}, {%4,%5,%6,%7}, {%8,%9}, {%0,%1,%2,%3};"
        : "+f"(c[0]), "+f"(c[1]), "+f"(c[2]), "+f"(c[3])
        : "r"(a[0]), "r"(a[1]), "r"(a[2]), "r"(a[3]), "r"(b0), "r"(b1));
}

// exp2 on FFMA pipe: magic-number round + degree-5 Taylor, t <= 0
__device__ __forceinline__ float exp2p(float t) {
    t = fmaxf(t, -80.0f);
    float k = t + 12582912.0f;
    int ik = __float_as_int(k) << 23;
    float f = t - (k - 12582912.0f);
    float r = 1.3333558146e-3f;
    r = fmaf(r, f, 9.6181291076e-3f);
    r = fmaf(r, f, 5.5504108664e-2f);
    r = fmaf(r, f, 2.4022650696e-1f);
    r = fmaf(r, f, 6.9314718056e-1f);
    r = fmaf(r, f, 1.0f);
    return __int_as_float(__float_as_int(r) + ik);
}

__device__ __forceinline__ uint32_t packh2(__half a, __half b) {
    __half2 h = __halves2half2(a, b);
    return *(uint32_t*)&h;
}

// ============================================================================
// fp32 -> fp16 conversion (x), vectorized float4
// ============================================================================
__global__ void conv_kernel(const float* __restrict__ src) {
    int i = (blockIdx.x * blockDim.x + threadIdx.x) * 4;
    float4 v = *(const float4*)(src + i);
    *(uint32_t*)(g_xh + i)     = packh2(__float2half_rn(v.x), __float2half_rn(v.y));
    *(uint32_t*)(g_xh + i + 2) = packh2(__float2half_rn(v.z), __float2half_rn(v.w));
}

// ============================================================================
// W[K=1024, N] -> W^T [N, 1024] fp16
// ============================================================================
template <int W>
__global__ void transpose_conv(const float* __restrict__ Win) {
    const int N = (W == 0) ? N_QKV : DIMC;
    __half* Th = (W == 0) ? g_wqh : g_woh;
    __shared__ float t[32][33];
    int tx = threadIdx.x, ty = threadIdx.y;
    int n0 = blockIdx.x * 32, k0 = blockIdx.y * 32;
#pragma unroll
    for (int j = 0; j < 32; j += 8)
        t[ty + j][tx] = Win[(size_t)(k0 + ty + j) * N + n0 + tx];
    __syncthreads();
#pragma unroll
    for (int j = 0; j < 32; j += 8) {
        float v = t[tx][ty + j];
        Th[(size_t)(n0 + ty + j) * DIMC + k0 + tx] = __float2half_rn(v);
    }
}

// ============================================================================
// HMMA fp16 GEMM (round-12 winner, unchanged): C = A·B single fp16.
// 3-stage cp.async ring, one barrier/iter. 128x128 CTA, BK=32, 8 warps.
// MODE 1 -> fp16 Q (+pos, scaled), K, V. MODE 0 -> fp32 Cout + bias.
// ============================================================================
#define PADK   40                  // 32 + 8 fp16 padding (80B rows)
#define MAT_B  (128 * PADK * 2)    // 10240 B
#define STG_B  (2 * MAT_B)         // 20480 B (A, B)
#define NSTG   3
#define GEMM_SMEM (NSTG * STG_B)   // 61440 B

template <int MODE>
__global__ __launch_bounds__(256) void hmma_gemm(
    const float* __restrict__ bias, const float* __restrict__ pos,
    float* __restrict__ Cout)
{
    const __half* Aa = (MODE == 1) ? g_xh : g_ah;
    const __half* Bb = (MODE == 1) ? g_wqh : g_woh;

    extern __shared__ char smraw[];
    const uint32_t sbase = smem_u32(smraw);

    const int tid = threadIdx.x;
    const int wid = tid >> 5, lane = tid & 31;
    const int wm0 = (wid >> 2) * 64;
    const int wn0 = (wid & 3) * 32;

    const int row0 = blockIdx.y * 128;
    const int col0 = blockIdx.x * 128;

    const __half* srcs[2] = {
        Aa + (size_t)row0 * DIMC,
        Bb + (size_t)col0 * DIMC };

    const int lr0 = tid >> 2;
    const int lch = tid & 3;

    auto load_chunk = [&](int kc, int s) {
        uint32_t st = sbase + (uint32_t)s * STG_B;
#pragma unroll
        for (int mmat = 0; mmat < 2; ++mmat) {
            const __half* src = srcs[mmat] + (size_t)kc * 32;
            uint32_t mb = st + (uint32_t)mmat * MAT_B;
#pragma unroll
            for (int i = 0; i < 2; ++i) {
                int r = lr0 + i * 64;
                cp16(mb + (uint32_t)(r * PADK + lch * 8) * 2,
                     src + (size_t)r * DIMC + lch * 8);
            }
        }
    };

    float acc[4][4][4];
#pragma unroll
    for (int i = 0; i < 4; ++i)
#pragma unroll
        for (int j = 0; j < 4; ++j)
#pragma unroll
            for (int k = 0; k < 4; ++k) acc[i][j][k] = 0.0f;

    const int aRow = lane & 15;
    const int aColHalf = (lane >> 4) * 8;
    const int bRow = lane & 7;
    const int bColHalf = ((lane >> 3) & 1) * 8;

    load_chunk(0, 0); cp_commit();
    load_chunk(1, 1); cp_commit();

    const int NC = DIMC / 32;   // 32
    int sc = 0;
    for (int kc = 0; kc < NC; ++kc) {
        if (kc + 1 < NC) cp_wait1(); else cp_wait0();
        __syncthreads();
        if (kc + 2 < NC) {
            int s2 = sc + 2; if (s2 >= NSTG) s2 -= NSTG;
            load_chunk(kc + 2, s2);
            cp_commit();
        }

        uint32_t st = sbase + (uint32_t)sc * STG_B;
        uint32_t aA = st, bB = st + MAT_B;

#pragma unroll
        for (int ks = 0; ks < 2; ++ks) {
            uint32_t ah[4][4], bh[4][2];
            int kcol = ks * 16;
#pragma unroll
            for (int mf = 0; mf < 4; ++mf) {
                uint32_t off = (uint32_t)((wm0 + mf * 16 + aRow) * PADK + kcol + aColHalf) * 2;
                ldsm4(ah[mf][0], ah[mf][1], ah[mf][2], ah[mf][3], aA + off);
            }
#pragma unroll
            for (int nf = 0; nf < 4; ++nf) {
                uint32_t off = (uint32_t)((wn0 + nf * 8 + bRow) * PADK + kcol + bColHalf) * 2;
                ldsm2(bh[nf][0], bh[nf][1], bB + off);
            }
#pragma unroll
            for (int mf = 0; mf < 4; ++mf)
#pragma unroll
                for (int nf = 0; nf < 4; ++nf)
                    mma_fp(acc[mf][nf], ah[mf], bh[nf][0], bh[nf][1]);
        }

        ++sc; if (sc == NSTG) sc = 0;
    }

    const int erow = lane >> 2;
    const int ecol = (lane & 3) * 2;
#pragma unroll
    for (int mf = 0; mf < 4; ++mf) {
#pragma unroll
        for (int half = 0; half < 2; ++half) {
            int m = row0 + wm0 + mf * 16 + erow + half * 8;
            int b_ = m >> 11, t = m & (TT - 1);
#pragma unroll
            for (int nf = 0; nf < 4; ++nf) {
                int n = col0 + wn0 + nf * 8 + ecol;
                float vx = acc[mf][nf][half * 2 + 0] + bias[n + 0];
                float vy = acc[mf][nf][half * 2 + 1] + bias[n + 1];
                if (MODE == 0) {
                    float2 v = {vx, vy};
                    *(float2*)(Cout + (size_t)m * DIMC + n) = v;
                } else {
                    int sec = n >> 10;
                    int cc = n & (DIMC - 1);
                    int h = cc >> 6, d = cc & 63;
                    size_t idx = (((size_t)(b_ * NH + h)) * TT + t) * HD + d;
                    if (sec == 0) {
                        float qx = (vx + pos[cc + 0]) * QSCALE;
                        float qy = (vy + pos[cc + 1]) * QSCALE;
                        *(uint32_t*)(g_qh + idx) =
                            packh2(__float2half_rn(qx), __float2half_rn(qy));
                    } else if (sec == 1) {
                        *(uint32_t*)(g_kh + idx) =
                            packh2(__float2half_rn(vx), __float2half_rn(vy));
                    } else {
                        *(uint32_t*)(g_vh + idx) =
                            packh2(__float2half_rn(vx), __float2half_rn(vy));
                    }
                }
            }
        }
    }
}

// ============================================================================
// HMMA flash attention — balanced pairing. Tq=64 rows, 4 warps (128 thr),
// Bc=64. Each CTA processes q-tile qa AND its complement (31-qa):
// total work = (qa+1)+(32-qa) = 33 KV tiles per CTA, exactly constant.
// Single-product QK^T and PV, fp16 operands (numerics identical to r11).
// ============================================================================
#define AT_PADH 72                      // fp16 elems per smem row (144 B)
#define Q_BYTES (64 * AT_PADH * 2)      // 9216
#define KV_MAT  (64 * AT_PADH * 2)      // 9216
#define KV_STAGE (2 * KV_MAT)           // 18432 (Kh, Vh)
#define ATT_SMEM (Q_BYTES + 2 * KV_STAGE)   // 46080
#define NQT (TT / 64)                   // 32 q-tiles

__global__ __launch_bounds__(128) void attn2()
{
    extern __shared__ char smraw[];
    const uint32_t sb = smem_u32(smraw);
    const uint32_t sQh = sb;
    const uint32_t sKV = sb + Q_BYTES;

    const int tid = threadIdx.x;
    const int lane = tid & 31;
    const int bh = blockIdx.y;
    const int qr0 = (tid >> 5) * 16;     // warp's q-row base (4 warps x 16)

    const __half* qhp = g_qh + (size_t)bh * TT * HD;
    const __half* kvsrc[2] = {
        g_kh + (size_t)bh * TT * HD, g_vh + (size_t)bh * TT * HD };

    auto prefetchKV = [&](int j, uint32_t dst) {
        int kb = j * 64;
#pragma unroll
        for (int i = 0; i < 8; ++i) {
            int c = tid + i * 128;          // 0..1023
            int mat = c >> 9, rem = c & 511;
            int r = rem >> 3, ch = rem & 7;
            cp16(dst + (uint32_t)mat * KV_MAT + (uint32_t)(r * 144 + ch * 16),
                 kvsrc[mat] + (size_t)(kb + r) * HD + ch * 8);
        }
    };

    int b_ = bh >> 4, h = bh & 15;
    int coff = h * 64 + (lane & 3) * 2;

    // two segments: q-tile qa, then q-tile (NQT-1 - qa)
#pragma unroll 1
    for (int seg = 0; seg < 2; ++seg) {
        const int qi = (seg == 0) ? (int)blockIdx.x : (NQT - 1 - (int)blockIdx.x);
        const int q0 = qi * 64;
        const int ntiles = qi + 1;

        // load Q tile (512 cp16 / 128 thr = 4 each) + first KV tile
#pragma unroll
        for (int i = 0; i < 4; ++i) {
            int c = tid + i * 128;
            int r = c >> 3, ch = c & 7;
            cp16(sQh + (uint32_t)(r * 144 + ch * 16),
                 qhp + (size_t)(q0 + r) * HD + ch * 8);
        }
        prefetchKV(0, sKV);
        cp_commit();
        cp_wait0();
        __syncthreads();

        // persistent Q fragments
        uint32_t fqh[4][4];
        {
            int rr = qr0 + (lane & 15);
#pragma unroll
            for (int kf = 0; kf < 4; ++kf) {
                int cc = kf * 16 + ((lane & 16) ? 8 : 0);
                uint32_t off = (uint32_t)(rr * 144 + cc * 2);
                ldsm4(fqh[kf][0], fqh[kf][1], fqh[kf][2], fqh[kf][3], sQh + off);
            }
        }

        float o[8][4];
#pragma unroll
        for (int i = 0; i < 8; ++i)
#pragma unroll
            for (int k = 0; k < 4; ++k) o[i][k] = 0.0f;
        float m0 = -1e30f, m1 = -1e30f, l0 = 0.0f, l1 = 0.0f;

        for (int j = 0; j < ntiles; ++j) {
            uint32_t stage = sKV + (uint32_t)(j & 1) * KV_STAGE;
            if (j + 1 < ntiles) {
                prefetchKV(j + 1, sKV + (uint32_t)((j + 1) & 1) * KV_STAGE);
                cp_commit();
            }

            // ---- S = Q K^T ----
            float c[8][4];
#pragma unroll
            for (int i = 0; i < 8; ++i)
#pragma unroll
                for (int k = 0; k < 4; ++k) c[i][k] = 0.0f;

            uint32_t Kh = stage;
            {
                int rb = ((lane & 16) ? 8 : 0) + (lane & 7);
                int cb = ((lane & 8) ? 8 : 0);
#pragma unroll
                for (int kf = 0; kf < 4; ++kf) {
#pragma unroll
                    for (int jp = 0; jp < 4; ++jp) {
                        uint32_t off = (uint32_t)((jp * 16 + rb) * 144 + (kf * 16 + cb) * 2);
                        uint32_t h0, h1, h2, h3;
                        ldsm4(h0, h1, h2, h3, Kh + off);
                        mma_fp(c[2 * jp],     fqh[kf], h0, h1);
                        mma_fp(c[2 * jp + 1], fqh[kf], h2, h3);
                    }
                }
            }

            // ---- causal mask (diagonal tile only: j == qi) ----
            if (j == ntiles - 1) {
                int row0 = q0 + qr0 + (lane >> 2);
                int kb = j * 64 + (lane & 3) * 2;
#pragma unroll
                for (int nf = 0; nf < 8; ++nf) {
                    int key = kb + nf * 8;
                    if (key     > row0)     c[nf][0] = -1e30f;
                    if (key + 1 > row0)     c[nf][1] = -1e30f;
                    if (key     > row0 + 8) c[nf][2] = -1e30f;
                    if (key + 1 > row0 + 8) c[nf][3] = -1e30f;
                }
            }

            // ---- online softmax ----
            float v0 = -1e30f, v1 = -1e30f;
#pragma unroll
            for (int nf = 0; nf < 8; ++nf) {
                v0 = fmaxf(v0, fmaxf(c[nf][0], c[nf][1]));
                v1 = fmaxf(v1, fmaxf(c[nf][2], c[nf][3]));
            }
            v0 = fmaxf(v0, __shfl_xor_sync(0xFFFFFFFFu, v0, 1));
            v0 = fmaxf(v0, __shfl_xor_sync(0xFFFFFFFFu, v0, 2));
            v1 = fmaxf(v1, __shfl_xor_sync(0xFFFFFFFFu, v1, 1));
            v1 = fmaxf(v1, __shfl_xor_sync(0xFFFFFFFFu, v1, 2));
            float mn0 = fmaxf(m0, v0), mn1 = fmaxf(m1, v1);
            float a0 = exp2p(m0 - mn0), a1 = exp2p(m1 - mn1);
            m0 = mn0; m1 = mn1;
            l0 *= a0; l1 *= a1;
#pragma unroll
            for (int nf = 0; nf < 8; ++nf) {
                o[nf][0] *= a0; o[nf][1] *= a0;
                o[nf][2] *= a1; o[nf][3] *= a1;
            }

            // ---- P (exp2 poly, fp16) + P V ----
            uint32_t Vh = stage + KV_MAT;
            int vrb = ((lane & 8) ? 8 : 0) + (lane & 7);
            int vcb = ((lane & 16) ? 8 : 0);
#pragma unroll
            for (int t = 0; t < 4; ++t) {
                float p00 = exp2p(c[2 * t][0] - m0), p01 = exp2p(c[2 * t][1] - m0);
                float p02 = exp2p(c[2 * t][2] - m1), p03 = exp2p(c[2 * t][3] - m1);
                float p10 = exp2p(c[2 * t + 1][0] - m0), p11 = exp2p(c[2 * t + 1][1] - m0);
                float p12 = exp2p(c[2 * t + 1][2] - m1), p13 = exp2p(c[2 * t + 1][3] - m1);
                l0 += p00 + p01 + p10 + p11;
                l1 += p02 + p03 + p12 + p13;

                uint32_t ph[4];
                ph[0] = packh2(__float2half_rn(p00), __float2half_rn(p01));
                ph[1] = packh2(__float2half_rn(p02), __float2half_rn(p03));
                ph[2] = packh2(__float2half_rn(p10), __float2half_rn(p11));
                ph[3] = packh2(__float2half_rn(p12), __float2half_rn(p13));

#pragma unroll
                for (int dp = 0; dp < 4; ++dp) {
                    uint32_t off = (uint32_t)((t * 16 + vrb) * 144 + (dp * 16 + vcb) * 2);
                    uint32_t h0, h1, h2, h3;
                    ldsm4t(h0, h1, h2, h3, Vh + off);
                    mma_fp(o[2 * dp],     ph, h0, h1);
                    mma_fp(o[2 * dp + 1], ph, h2, h3);
                }
            }

            if (j + 1 < ntiles) cp_wait0();
            __syncthreads();
        }

        // ---- epilogue: normalize, write fp16 [B,T,C] ----
        l0 += __shfl_xor_sync(0xFFFFFFFFu, l0, 1);
        l0 += __shfl_xor_sync(0xFFFFFFFFu, l0, 2);
        l1 += __shfl_xor_sync(0xFFFFFFFFu, l1, 1);
        l1 += __shfl_xor_sync(0xFFFFFFFFu, l1, 2);
        float inv0 = 1.0f / l0, inv1 = 1.0f / l1;

        int t0 = q0 + qr0 + (lane >> 2);
        size_t r0 = ((size_t)b_ * TT + t0) * DIMC;
        size_t r1 = r0 + (size_t)8 * DIMC;
#pragma unroll
        for (int nf = 0; nf < 8; ++nf) {
            int col = coff + nf * 8;
            *(uint32_t*)(g_ah + r0 + col) =
                packh2(__float2half_rn(o[nf][0] * inv0), __float2half_rn(o[nf][1] * inv0));
            *(uint32_t*)(g_ah + r1 + col) =
                packh2(__float2half_rn(o[nf][2] * inv1), __float2half_rn(o[nf][3] * inv1));
        }
        __syncthreads();   // Q smem reuse in next segment
    }
}

// ============================================================================
// Launch
// ============================================================================
extern "C" void kernel_launch(void* const* d_in, const int* in_sizes, int n_in,
                              void* d_out, int out_size)
{
    (void)in_sizes; (void)n_in; (void)out_size;
    const float* x     = (const float*)d_in[0];
    const float* w_qkv = (const float*)d_in[1];
    const float* b_qkv = (const float*)d_in[2];
    const float* w_out = (const float*)d_in[3];
    const float* b_out = (const float*)d_in[4];
    const float* pos   = (const float*)d_in[5];
    float* out = (float*)d_out;

    cudaFuncSetAttribute(hmma_gemm<1>, cudaFuncAttributeMaxDynamicSharedMemorySize, GEMM_SMEM);
    cudaFuncSetAttribute(hmma_gemm<0>, cudaFuncAttributeMaxDynamicSharedMemorySize, GEMM_SMEM);
    cudaFuncSetAttribute(attn2, cudaFuncAttributeMaxDynamicSharedMemorySize, ATT_SMEM);

    // 0) convert input + transpose/convert weights to fp16
    conv_kernel<<<MTOT * DIMC / 1024, 256>>>(x);
    transpose_conv<0><<<dim3(N_QKV / 32, DIMC / 32), dim3(32, 8)>>>(w_qkv);
    transpose_conv<1><<<dim3(DIMC / 32, DIMC / 32), dim3(32, 8)>>>(w_out);

    // 1) QKV projection + bias (+pos, q-scale) -> fp16 Q, K, V
    hmma_gemm<1><<<dim3(N_QKV / 128, MTOT / 128), 256, GEMM_SMEM>>>(b_qkv, pos, nullptr);

    // 2) HMMA flash attention (balanced q-tile pairing) -> fp16 attn out
    attn2<<<dim3(NQT / 2, BB * NH), 128, ATT_SMEM>>>();

    // 3) output projection + bias
    hmma_gemm<0><<<dim3(DIMC / 128, MTOT / 128), 256, GEMM_SMEM>>>(b_out, nullptr, out);
}

// round 14
// speedup vs baseline: 2.4058x; 1.0086x over previous
#include <cuda_runtime.h>
#include <cuda_bf16.h>
#include <cuda_fp16.h>
#include <cstdint>

// Problem constants
#define BB   2
#define TT   2048
#define DIMC 1024
#define NH   16
#define HD   64
#define MTOT (BB * TT)          // 4096
#define N_QKV (3 * DIMC)        // 3072

// q pre-scale: 1/sqrt(64) * log2(e)
#define QSCALE 0.18033688011112042f

// -------- scratch (device globals; no allocation allowed) --------
__device__ __half g_qh[BB * NH * TT * HD];
__device__ __half g_kh[BB * NH * TT * HD];
__device__ __half g_vh[BB * NH * TT * HD];
__device__ __half g_xh[MTOT * DIMC];          // x (fp16)
__device__ __half g_ah[MTOT * DIMC];          // attn out [B,T,C] (fp16)
__device__ __half g_wqh[N_QKV * DIMC];        // W_qkv^T (fp16)
__device__ __half g_woh[DIMC * DIMC];         // W_out^T (fp16)

// ============================================================================
// Helpers (plain-target PTX: cp.async / ldmatrix / mma.sync)
// ============================================================================
__device__ __forceinline__ uint32_t smem_u32(const void* p) {
    uint32_t a;
    asm("{ .reg .u64 t; cvta.to.shared.u64 t, %1; cvt.u32.u64 %0, t; }" : "=r"(a) : "l"(p));
    return a;
}
__device__ __forceinline__ void cp16(uint32_t dst, const void* src) {
    asm volatile("cp.async.cg.shared.global [%0], [%1], 16;" :: "r"(dst), "l"(src));
}
__device__ __forceinline__ void cp_commit() { asm volatile("cp.async.commit_group;" ::: "memory"); }
__device__ __forceinline__ void cp_wait0()  { asm volatile("cp.async.wait_group 0;" ::: "memory"); }
__device__ __forceinline__ void cp_wait1()  { asm volatile("cp.async.wait_group 1;" ::: "memory"); }

__device__ __forceinline__ void ldsm4(uint32_t& r0, uint32_t& r1, uint32_t& r2, uint32_t& r3,
                                      uint32_t addr) {
    asm volatile("ldmatrix.sync.aligned.m8n8.x4.shared.b16 {%0,%1,%2,%3}, [%4];"
                 : "=r"(r0), "=r"(r1), "=r"(r2), "=r"(r3) : "r"(addr));
}
__device__ __forceinline__ void ldsm4t(uint32_t& r0, uint32_t& r1, uint32_t& r2, uint32_t& r3,
                                       uint32_t addr) {
    asm volatile("ldmatrix.sync.aligned.m8n8.x4.trans.shared.b16 {%0,%1,%2,%3}, [%4];"
                 : "=r"(r0), "=r"(r1), "=r"(r2), "=r"(r3) : "r"(addr));
}
__device__ __forceinline__ void ldsm2(uint32_t& r0, uint32_t& r1, uint32_t addr) {
    asm volatile("ldmatrix.sync.aligned.m8n8.x2.shared.b16 {%0,%1}, [%2];"
                 : "=r"(r0), "=r"(r1) : "r"(addr));
}
__device__ __forceinline__ void mma_fp(float* c, const uint32_t* a, uint32_t b0, uint32_t b1) {
    asm volatile(
        "mma.sync.aligned.m16n8k16.row.col.f32.f16.f16.f32 "
        "{%0,%1,%2,%3}, {%4,%5,%6,%7}, {%8,%9}, {%0,%1,%2,%3};"
        : "+f"(c[0]), "+f"(c[1]), "+f"(c[2]), "+f"(c[3])
        : "r"(a[0]), "r"(a[1]), "r"(a[2]), "r"(a[3]), "r"(b0), "r"(b1));
}

// exp2 on FFMA pipe: magic-number round + degree-5 Taylor, t <= 0
// exp2p(0) == 1.0f exactly (poly terminates at 1.0f, ik == 0).
__device__ __forceinline__ float exp2p(float t) {
    t = fmaxf(t, -80.0f);
    float k = t + 12582912.0f;
    int ik = __float_as_int(k) << 23;
    float f = t - (k - 12582912.0f);
    float r = 1.3333558146e-3f;
    r = fmaf(r, f, 9.6181291076e-3f);
    r = fmaf(r, f, 5.5504108664e-2f);
    r = fmaf(r, f, 2.4022650696e-1f);
    r = fmaf(r, f, 6.9314718056e-1f);
    r = fmaf(r, f, 1.0f);
    return __int_as_float(__float_as_int(r) + ik);
}

__device__ __forceinline__ uint32_t packh2(__half a, __half b) {
    __half2 h = __halves2half2(a, b);
    return *(uint32_t*)&h;
}

// ============================================================================
// fp32 -> fp16 conversion (x), vectorized float4
// ============================================================================
__global__ void conv_kernel(const float* __restrict__ src) {
    int i = (blockIdx.x * blockDim.x + threadIdx.x) * 4;
    float4 v = *(const float4*)(src + i);
    *(uint32_t*)(g_xh + i)     = packh2(__float2half_rn(v.x), __float2half_rn(v.y));
    *(uint32_t*)(g_xh + i + 2) = packh2(__float2half_rn(v.z), __float2half_rn(v.w));
}

// ============================================================================
// Fused weight transpose: W[K=1024, N] -> W^T [N, 1024] fp16 for BOTH weights.
// blockIdx.x < N_QKV/32 -> w_qkv ; else -> w_out (offset grid).
// ============================================================================
__global__ void transpose_conv_fused(const float* __restrict__ Wq,
                                     const float* __restrict__ Wo) {
    const int bq = N_QKV / 32;           // 96 blocks for w_qkv
    bool isQ = (blockIdx.x < (unsigned)bq);
    const float* Win = isQ ? Wq : Wo;
    __half* Th = isQ ? g_wqh : g_woh;
    const int N = isQ ? N_QKV : DIMC;
    int bx = isQ ? blockIdx.x : (blockIdx.x - bq);

    __shared__ float t[32][33];
    int tx = threadIdx.x, ty = threadIdx.y;
    int n0 = bx * 32, k0 = blockIdx.y * 32;
#pragma unroll
    for (int j = 0; j < 32; j += 8)
        t[ty + j][tx] = Win[(size_t)(k0 + ty + j) * N + n0 + tx];
    __syncthreads();
#pragma unroll
    for (int j = 0; j < 32; j += 8) {
        float v = t[tx][ty + j];
        Th[(size_t)(n0 + ty + j) * DIMC + k0 + tx] = __float2half_rn(v);
    }
}

// ============================================================================
// HMMA fp16 GEMM (round-12 winner, unchanged): C = A·B single fp16.
// 3-stage cp.async ring, one barrier/iter. 128x128 CTA, BK=32, 8 warps.
// MODE 1 -> fp16 Q (+pos, scaled), K, V. MODE 0 -> fp32 Cout + bias.
// ============================================================================
#define PADK   40                  // 32 + 8 fp16 padding (80B rows)
#define MAT_B  (128 * PADK * 2)    // 10240 B
#define STG_B  (2 * MAT_B)         // 20480 B (A, B)
#define NSTG   3
#define GEMM_SMEM (NSTG * STG_B)   // 61440 B

template <int MODE>
__global__ __launch_bounds__(256) void hmma_gemm(
    const float* __restrict__ bias, const float* __restrict__ pos,
    float* __restrict__ Cout)
{
    const __half* Aa = (MODE == 1) ? g_xh : g_ah;
    const __half* Bb = (MODE == 1) ? g_wqh : g_woh;

    extern __shared__ char smraw[];
    const uint32_t sbase = smem_u32(smraw);

    const int tid = threadIdx.x;
    const int wid = tid >> 5, lane = tid & 31;
    const int wm0 = (wid >> 2) * 64;
    const int wn0 = (wid & 3) * 32;

    const int row0 = blockIdx.y * 128;
    const int col0 = blockIdx.x * 128;

    const __half* srcs[2] = {
        Aa + (size_t)row0 * DIMC,
        Bb + (size_t)col0 * DIMC };

    const int lr0 = tid >> 2;
    const int lch = tid & 3;

    auto load_chunk = [&](int kc, int s) {
        uint32_t st = sbase + (uint32_t)s * STG_B;
#pragma unroll
        for (int mmat = 0; mmat < 2; ++mmat) {
            const __half* src = srcs[mmat] + (size_t)kc * 32;
            uint32_t mb = st + (uint32_t)mmat * MAT_B;
#pragma unroll
            for (int i = 0; i < 2; ++i) {
                int r = lr0 + i * 64;
                cp16(mb + (uint32_t)(r * PADK + lch * 8) * 2,
                     src + (size_t)r * DIMC + lch * 8);
            }
        }
    };

    float acc[4][4][4];
#pragma unroll
    for (int i = 0; i < 4; ++i)
#pragma unroll
        for (int j = 0; j < 4; ++j)
#pragma unroll
            for (int k = 0; k < 4; ++k) acc[i][j][k] = 0.0f;

    const int aRow = lane & 15;
    const int aColHalf = (lane >> 4) * 8;
    const int bRow = lane & 7;
    const int bColHalf = ((lane >> 3) & 1) * 8;

    load_chunk(0, 0); cp_commit();
    load_chunk(1, 1); cp_commit();

    const int NC = DIMC / 32;   // 32
    int sc = 0;
    for (int kc = 0; kc < NC; ++kc) {
        if (kc + 1 < NC) cp_wait1(); else cp_wait0();
        __syncthreads();
        if (kc + 2 < NC) {
            int s2 = sc + 2; if (s2 >= NSTG) s2 -= NSTG;
            load_chunk(kc + 2, s2);
            cp_commit();
        }

        uint32_t st = sbase + (uint32_t)sc * STG_B;
        uint32_t aA = st, bB = st + MAT_B;

#pragma unroll
        for (int ks = 0; ks < 2; ++ks) {
            uint32_t ah[4][4], bh[4][2];
            int kcol = ks * 16;
#pragma unroll
            for (int mf = 0; mf < 4; ++mf) {
                uint32_t off = (uint32_t)((wm0 + mf * 16 + aRow) * PADK + kcol + aColHalf) * 2;
                ldsm4(ah[mf][0], ah[mf][1], ah[mf][2], ah[mf][3], aA + off);
            }
#pragma unroll
            for (int nf = 0; nf < 4; ++nf) {
                uint32_t off = (uint32_t)((wn0 + nf * 8 + bRow) * PADK + kcol + bColHalf) * 2;
                ldsm2(bh[nf][0], bh[nf][1], bB + off);
            }
#pragma unroll
            for (int mf = 0; mf < 4; ++mf)
#pragma unroll
                for (int nf = 0; nf < 4; ++nf)
                    mma_fp(acc[mf][nf], ah[mf], bh[nf][0], bh[nf][1]);
        }

        ++sc; if (sc == NSTG) sc = 0;
    }

    const int erow = lane >> 2;
    const int ecol = (lane & 3) * 2;
#pragma unroll
    for (int mf = 0; mf < 4; ++mf) {
#pragma unroll
        for (int half = 0; half < 2; ++half) {
            int m = row0 + wm0 + mf * 16 + erow + half * 8;
            int b_ = m >> 11, t = m & (TT - 1);
#pragma unroll
            for (int nf = 0; nf < 4; ++nf) {
                int n = col0 + wn0 + nf * 8 + ecol;
                float vx = acc[mf][nf][half * 2 + 0] + bias[n + 0];
                float vy = acc[mf][nf][half * 2 + 1] + bias[n + 1];
                if (MODE == 0) {
                    float2 v = {vx, vy};
                    *(float2*)(Cout + (size_t)m * DIMC + n) = v;
                } else {
                    int sec = n >> 10;
                    int cc = n & (DIMC - 1);
                    int h = cc >> 6, d = cc & 63;
                    size_t idx = (((size_t)(b_ * NH + h)) * TT + t) * HD + d;
                    if (sec == 0) {
                        float qx = (vx + pos[cc + 0]) * QSCALE;
                        float qy = (vy + pos[cc + 1]) * QSCALE;
                        *(uint32_t*)(g_qh + idx) =
                            packh2(__float2half_rn(qx), __float2half_rn(qy));
                    } else if (sec == 1) {
                        *(uint32_t*)(g_kh + idx) =
                            packh2(__float2half_rn(vx), __float2half_rn(vy));
                    } else {
                        *(uint32_t*)(g_vh + idx) =
                            packh2(__float2half_rn(vx), __float2half_rn(vy));
                    }
                }
            }
        }
    }
}

// ============================================================================
// HMMA flash attention — balanced pairing (round-13) + conditional rescale.
// Tq=64, 4 warps, Bc=64; CTA does q-tile qa and complement (31-qa).
// Rescale of o/l is skipped (bit-exact: a==1.0) when no lane's max changed.
// ============================================================================
#define AT_PADH 72                      // fp16 elems per smem row (144 B)
#define Q_BYTES (64 * AT_PADH * 2)      // 9216
#define KV_MAT  (64 * AT_PADH * 2)      // 9216
#define KV_STAGE (2 * KV_MAT)           // 18432 (Kh, Vh)
#define ATT_SMEM (Q_BYTES + 2 * KV_STAGE)   // 46080
#define NQT (TT / 64)                   // 32 q-tiles

__global__ __launch_bounds__(128) void attn2()
{
    extern __shared__ char smraw[];
    const uint32_t sb = smem_u32(smraw);
    const uint32_t sQh = sb;
    const uint32_t sKV = sb + Q_BYTES;

    const int tid = threadIdx.x;
    const int lane = tid & 31;
    const int bh = blockIdx.y;
    const int qr0 = (tid >> 5) * 16;     // warp's q-row base (4 warps x 16)

    const __half* qhp = g_qh + (size_t)bh * TT * HD;
    const __half* kvsrc[2] = {
        g_kh + (size_t)bh * TT * HD, g_vh + (size_t)bh * TT * HD };

    auto prefetchKV = [&](int j, uint32_t dst) {
        int kb = j * 64;
#pragma unroll
        for (int i = 0; i < 8; ++i) {
            int c = tid + i * 128;          // 0..1023
            int mat = c >> 9, rem = c & 511;
            int r = rem >> 3, ch = rem & 7;
            cp16(dst + (uint32_t)mat * KV_MAT + (uint32_t)(r * 144 + ch * 16),
                 kvsrc[mat] + (size_t)(kb + r) * HD + ch * 8);
        }
    };

    int b_ = bh >> 4, h = bh & 15;
    int coff = h * 64 + (lane & 3) * 2;

#pragma unroll 1
    for (int seg = 0; seg < 2; ++seg) {
        const int qi = (seg == 0) ? (int)blockIdx.x : (NQT - 1 - (int)blockIdx.x);
        const int q0 = qi * 64;
        const int ntiles = qi + 1;

#pragma unroll
        for (int i = 0; i < 4; ++i) {
            int c = tid + i * 128;
            int r = c >> 3, ch = c & 7;
            cp16(sQh + (uint32_t)(r * 144 + ch * 16),
                 qhp + (size_t)(q0 + r) * HD + ch * 8);
        }
        prefetchKV(0, sKV);
        cp_commit();
        cp_wait0();
        __syncthreads();

        uint32_t fqh[4][4];
        {
            int rr = qr0 + (lane & 15);
#pragma unroll
            for (int kf = 0; kf < 4; ++kf) {
                int cc = kf * 16 + ((lane & 16) ? 8 : 0);
                uint32_t off = (uint32_t)(rr * 144 + cc * 2);
                ldsm4(fqh[kf][0], fqh[kf][1], fqh[kf][2], fqh[kf][3], sQh + off);
            }
        }

        float o[8][4];
#pragma unroll
        for (int i = 0; i < 8; ++i)
#pragma unroll
            for (int k = 0; k < 4; ++k) o[i][k] = 0.0f;
        float m0 = -1e30f, m1 = -1e30f, l0 = 0.0f, l1 = 0.0f;

        for (int j = 0; j < ntiles; ++j) {
            uint32_t stage = sKV + (uint32_t)(j & 1) * KV_STAGE;
            if (j + 1 < ntiles) {
                prefetchKV(j + 1, sKV + (uint32_t)((j + 1) & 1) * KV_STAGE);
                cp_commit();
            }

            // ---- S = Q K^T ----
            float c[8][4];
#pragma unroll
            for (int i = 0; i < 8; ++i)
#pragma unroll
                for (int k = 0; k < 4; ++k) c[i][k] = 0.0f;

            uint32_t Kh = stage;
            {
                int rb = ((lane & 16) ? 8 : 0) + (lane & 7);
                int cb = ((lane & 8) ? 8 : 0);
#pragma unroll
                for (int kf = 0; kf < 4; ++kf) {
#pragma unroll
                    for (int jp = 0; jp < 4; ++jp) {
                        uint32_t off = (uint32_t)((jp * 16 + rb) * 144 + (kf * 16 + cb) * 2);
                        uint32_t h0, h1, h2, h3;
                        ldsm4(h0, h1, h2, h3, Kh + off);
                        mma_fp(c[2 * jp],     fqh[kf], h0, h1);
                        mma_fp(c[2 * jp + 1], fqh[kf], h2, h3);
                    }
                }
            }

            // ---- causal mask (diagonal tile only) ----
            if (j == ntiles - 1) {
                int row0 = q0 + qr0 + (lane >> 2);
                int kb = j * 64 + (lane & 3) * 2;
#pragma unroll
                for (int nf = 0; nf < 8; ++nf) {
                    int key = kb + nf * 8;
                    if (key     > row0)     c[nf][0] = -1e30f;
                    if (key + 1 > row0)     c[nf][1] = -1e30f;
                    if (key     > row0 + 8) c[nf][2] = -1e30f;
                    if (key + 1 > row0 + 8) c[nf][3] = -1e30f;
                }
            }

            // ---- online softmax (conditional rescale) ----
            float v0 = -1e30f, v1 = -1e30f;
#pragma unroll
            for (int nf = 0; nf < 8; ++nf) {
                v0 = fmaxf(v0, fmaxf(c[nf][0], c[nf][1]));
                v1 = fmaxf(v1, fmaxf(c[nf][2], c[nf][3]));
            }
            v0 = fmaxf(v0, __shfl_xor_sync(0xFFFFFFFFu, v0, 1));
            v0 = fmaxf(v0, __shfl_xor_sync(0xFFFFFFFFu, v0, 2));
            v1 = fmaxf(v1, __shfl_xor_sync(0xFFFFFFFFu, v1, 1));
            v1 = fmaxf(v1, __shfl_xor_sync(0xFFFFFFFFu, v1, 2));
            float mn0 = fmaxf(m0, v0), mn1 = fmaxf(m1, v1);
            bool nochg = (mn0 == m0) && (mn1 == m1);
            if (!__all_sync(0xFFFFFFFFu, nochg)) {
                float a0 = exp2p(m0 - mn0), a1 = exp2p(m1 - mn1);
                l0 *= a0; l1 *= a1;
#pragma unroll
                for (int nf = 0; nf < 8; ++nf) {
                    o[nf][0] *= a0; o[nf][1] *= a0;
                    o[nf][2] *= a1; o[nf][3] *= a1;
                }
            }
            m0 = mn0; m1 = mn1;

            // ---- P (exp2 poly, fp16) + P V ----
            uint32_t Vh = stage + KV_MAT;
            int vrb = ((lane & 8) ? 8 : 0) + (lane & 7);
            int vcb = ((lane & 16) ? 8 : 0);
#pragma unroll
            for (int t = 0; t < 4; ++t) {
                float p00 = exp2p(c[2 * t][0] - m0), p01 = exp2p(c[2 * t][1] - m0);
                float p02 = exp2p(c[2 * t][2] - m1), p03 = exp2p(c[2 * t][3] - m1);
                float p10 = exp2p(c[2 * t + 1][0] - m0), p11 = exp2p(c[2 * t + 1][1] - m0);
                float p12 = exp2p(c[2 * t + 1][2] - m1), p13 = exp2p(c[2 * t + 1][3] - m1);
                l0 += p00 + p01 + p10 + p11;
                l1 += p02 + p03 + p12 + p13;

                uint32_t ph[4];
                ph[0] = packh2(__float2half_rn(p00), __float2half_rn(p01));
                ph[1] = packh2(__float2half_rn(p02), __float2half_rn(p03));
                ph[2] = packh2(__float2half_rn(p10), __float2half_rn(p11));
                ph[3] = packh2(__float2half_rn(p12), __float2half_rn(p13));

#pragma unroll
                for (int dp = 0; dp < 4; ++dp) {
                    uint32_t off = (uint32_t)((t * 16 + vrb) * 144 + (dp * 16 + vcb) * 2);
                    uint32_t h0, h1, h2, h3;
                    ldsm4t(h0, h1, h2, h3, Vh + off);
                    mma_fp(o[2 * dp],     ph, h0, h1);
                    mma_fp(o[2 * dp + 1], ph, h2, h3);
                }
            }

            if (j + 1 < ntiles) cp_wait0();
            __syncthreads();
        }

        // ---- epilogue: normalize, write fp16 [B,T,C] ----
        l0 += __shfl_xor_sync(0xFFFFFFFFu, l0, 1);
        l0 += __shfl_xor_sync(0xFFFFFFFFu, l0, 2);
        l1 += __shfl_xor_sync(0xFFFFFFFFu, l1, 1);
        l1 += __shfl_xor_sync(0xFFFFFFFFu, l1, 2);
        float inv0 = 1.0f / l0, inv1 = 1.0f / l1;

        int t0 = q0 + qr0 + (lane >> 2);
        size_t r0 = ((size_t)b_ * TT + t0) * DIMC;
        size_t r1 = r0 + (size_t)8 * DIMC;
#pragma unroll
        for (int nf = 0; nf < 8; ++nf) {
            int col = coff + nf * 8;
            *(uint32_t*)(g_ah + r0 + col) =
                packh2(__float2half_rn(o[nf][0] * inv0), __float2half_rn(o[nf][1] * inv0));
            *(uint32_t*)(g_ah + r1 + col) =
                packh2(__float2half_rn(o[nf][2] * inv1), __float2half_rn(o[nf][3] * inv1));
        }
        __syncthreads();   // Q smem reuse in next segment
    }
}

// ============================================================================
// Launch
// ============================================================================
extern "C" void kernel_launch(void* const* d_in, const int* in_sizes, int n_in,
                              void* d_out, int out_size)
{
    (void)in_sizes; (void)n_in; (void)out_size;
    const float* x     = (const float*)d_in[0];
    const float* w_qkv = (const float*)d_in[1];
    const float* b_qkv = (const float*)d_in[2];
    const float* w_out = (const float*)d_in[3];
    const float* b_out = (const float*)d_in[4];
    const float* pos   = (const float*)d_in[5];
    float* out = (float*)d_out;

    cudaFuncSetAttribute(hmma_gemm<1>, cudaFuncAttributeMaxDynamicSharedMemorySize, GEMM_SMEM);
    cudaFuncSetAttribute(hmma_gemm<0>, cudaFuncAttributeMaxDynamicSharedMemorySize, GEMM_SMEM);
    cudaFuncSetAttribute(attn2, cudaFuncAttributeMaxDynamicSharedMemorySize, ATT_SMEM);

    // 0) convert input + fused transpose/convert of both weights to fp16
    conv_kernel<<<MTOT * DIMC / 1024, 256>>>(x);
    transpose_conv_fused<<<dim3(N_QKV / 32 + DIMC / 32, DIMC / 32), dim3(32, 8)>>>(w_qkv, w_out);

    // 1) QKV projection + bias (+pos, q-scale) -> fp16 Q, K, V
    hmma_gemm<1><<<dim3(N_QKV / 128, MTOT / 128), 256, GEMM_SMEM>>>(b_qkv, pos, nullptr);

    // 2) HMMA flash attention (balanced pairing, lazy rescale) -> fp16 attn out
    attn2<<<dim3(NQT / 2, BB * NH), 128, ATT_SMEM>>>();

    // 3) output projection + bias
    hmma_gemm<0><<<dim3(DIMC / 128, MTOT / 128), 256, GEMM_SMEM>>>(b_out, nullptr, out);
}

// round 15
// speedup vs baseline: 2.5578x; 1.0632x over previous
#include <cuda_runtime.h>
#include <cuda_bf16.h>
#include <cuda_fp16.h>
#include <cstdint>

// Problem constants
#define BB   2
#define TT   2048
#define DIMC 1024
#define NH   16
#define HD   64
#define MTOT (BB * TT)          // 4096
#define N_QKV (3 * DIMC)        // 3072

// q pre-scale: 1/sqrt(64) * log2(e)
#define QSCALE 0.18033688011112042f

// -------- scratch (device globals; no allocation allowed) --------
__device__ __half g_qh[BB * NH * TT * HD];
__device__ __half g_kh[BB * NH * TT * HD];
__device__ __half g_vh[BB * NH * TT * HD];
__device__ __half g_xh[MTOT * DIMC];          // x (fp16)
__device__ __half g_ah[MTOT * DIMC];          // attn out [B,T,C] (fp16)
__device__ __half g_wqh[N_QKV * DIMC];        // W_qkv^T (fp16)
__device__ __half g_woh[DIMC * DIMC];         // W_out^T (fp16)

// ============================================================================
// Helpers (plain-target PTX: cp.async / ldmatrix / mma.sync)
// ============================================================================
__device__ __forceinline__ uint32_t smem_u32(const void* p) {
    uint32_t a;
    asm("{ .reg .u64 t; cvta.to.shared.u64 t, %1; cvt.u32.u64 %0, t; }" : "=r"(a) : "l"(p));
    return a;
}
__device__ __forceinline__ void cp16(uint32_t dst, const void* src) {
    asm volatile("cp.async.cg.shared.global [%0], [%1], 16;" :: "r"(dst), "l"(src));
}
__device__ __forceinline__ void cp_commit() { asm volatile("cp.async.commit_group;" ::: "memory"); }
__device__ __forceinline__ void cp_wait0()  { asm volatile("cp.async.wait_group 0;" ::: "memory"); }
__device__ __forceinline__ void cp_wait1()  { asm volatile("cp.async.wait_group 1;" ::: "memory"); }

__device__ __forceinline__ void ldsm4(uint32_t& r0, uint32_t& r1, uint32_t& r2, uint32_t& r3,
                                      uint32_t addr) {
    asm volatile("ldmatrix.sync.aligned.m8n8.x4.shared.b16 {%0,%1,%2,%3}, [%4];"
                 : "=r"(r0), "=r"(r1), "=r"(r2), "=r"(r3) : "r"(addr));
}
__device__ __forceinline__ void ldsm4t(uint32_t& r0, uint32_t& r1, uint32_t& r2, uint32_t& r3,
                                       uint32_t addr) {
    asm volatile("ldmatrix.sync.aligned.m8n8.x4.trans.shared.b16 {%0,%1,%2,%3}, [%4];"
                 : "=r"(r0), "=r"(r1), "=r"(r2), "=r"(r3) : "r"(addr));
}
__device__ __forceinline__ void ldsm2(uint32_t& r0, uint32_t& r1, uint32_t addr) {
    asm volatile("ldmatrix.sync.aligned.m8n8.x2.shared.b16 {%0,%1}, [%2];"
                 : "=r"(r0), "=r"(r1) : "r"(addr));
}
__device__ __forceinline__ void mma_fp(float* c, const uint32_t* a, uint32_t b0, uint32_t b1) {
    asm volatile(
        "mma.sync.aligned.m16n8k16.row.col.f32.f16.f16.f32 "
        "{%0,%1,%2,%3}, {%4,%5,%6,%7}, {%8,%9}, {%0,%1,%2,%3};"
        : "+f"(c[0]), "+f"(c[1]), "+f"(c[2]), "+f"(c[3])
        : "r"(a[0]), "r"(a[1]), "r"(a[2]), "r"(a[3]), "r"(b0), "r"(b1));
}

// exp2 on FFMA pipe: magic-number round + degree-5 Taylor, t <= 0
// exp2p(0) == 1.0f exactly.
__device__ __forceinline__ float exp2p(float t) {
    t = fmaxf(t, -80.0f);
    float k = t + 12582912.0f;
    int ik = __float_as_int(k) << 23;
    float f = t - (k - 12582912.0f);
    float r = 1.3333558146e-3f;
    r = fmaf(r, f, 9.6181291076e-3f);
    r = fmaf(r, f, 5.5504108664e-2f);
    r = fmaf(r, f, 2.4022650696e-1f);
    r = fmaf(r, f, 6.9314718056e-1f);
    r = fmaf(r, f, 1.0f);
    return __int_as_float(__float_as_int(r) + ik);
}

__device__ __forceinline__ uint32_t packh2(__half a, __half b) {
    __half2 h = __halves2half2(a, b);
    return *(uint32_t*)&h;
}

// ============================================================================
// fp32 -> fp16 conversion (x), vectorized float4
// ============================================================================
__global__ void conv_kernel(const float* __restrict__ src) {
    int i = (blockIdx.x * blockDim.x + threadIdx.x) * 4;
    float4 v = *(const float4*)(src + i);
    *(uint32_t*)(g_xh + i)     = packh2(__float2half_rn(v.x), __float2half_rn(v.y));
    *(uint32_t*)(g_xh + i + 2) = packh2(__float2half_rn(v.z), __float2half_rn(v.w));
}

// ============================================================================
// Fused weight transpose: W[K=1024, N] -> W^T [N, 1024] fp16 for BOTH weights.
// ============================================================================
__global__ void transpose_conv_fused(const float* __restrict__ Wq,
                                     const float* __restrict__ Wo) {
    const int bq = N_QKV / 32;           // 96 blocks for w_qkv
    bool isQ = (blockIdx.x < (unsigned)bq);
    const float* Win = isQ ? Wq : Wo;
    __half* Th = isQ ? g_wqh : g_woh;
    const int N = isQ ? N_QKV : DIMC;
    int bx = isQ ? blockIdx.x : (blockIdx.x - bq);

    __shared__ float t[32][33];
    int tx = threadIdx.x, ty = threadIdx.y;
    int n0 = bx * 32, k0 = blockIdx.y * 32;
#pragma unroll
    for (int j = 0; j < 32; j += 8)
        t[ty + j][tx] = Win[(size_t)(k0 + ty + j) * N + n0 + tx];
    __syncthreads();
#pragma unroll
    for (int j = 0; j < 32; j += 8) {
        float v = t[tx][ty + j];
        Th[(size_t)(n0 + ty + j) * DIMC + k0 + tx] = __float2half_rn(v);
    }
}

// ============================================================================
// HMMA fp16 GEMM: C = A·B single fp16. BK=64 (144B rows, conflict-free),
// 3-stage cp.async ring, one barrier/iter, 16 iterations total.
// 128x128 CTA, 8 warps (2x4), 64x32 warp tiles.
// MODE 1 -> fp16 Q (+pos, scaled), K, V. MODE 0 -> fp32 Cout + bias.
// ============================================================================
#define PADK   72                  // 64 + 8 fp16 padding (144B rows)
#define MAT_B  (128 * PADK * 2)    // 18432 B
#define STG_B  (2 * MAT_B)         // 36864 B (A, B)
#define NSTG   3
#define GEMM_SMEM (NSTG * STG_B)   // 110592 B

template <int MODE>
__global__ __launch_bounds__(256) void hmma_gemm(
    const float* __restrict__ bias, const float* __restrict__ pos,
    float* __restrict__ Cout)
{
    const __half* Aa = (MODE == 1) ? g_xh : g_ah;
    const __half* Bb = (MODE == 1) ? g_wqh : g_woh;

    extern __shared__ char smraw[];
    const uint32_t sbase = smem_u32(smraw);

    const int tid = threadIdx.x;
    const int wid = tid >> 5, lane = tid & 31;
    const int wm0 = (wid >> 2) * 64;
    const int wn0 = (wid & 3) * 32;

    const int row0 = blockIdx.y * 128;
    const int col0 = blockIdx.x * 128;

    const __half* srcs[2] = {
        Aa + (size_t)row0 * DIMC,
        Bb + (size_t)col0 * DIMC };

    // per chunk per matrix: 128 rows x 8 x16B chunks = 1024 cp16 / 256 thr = 4
    auto load_chunk = [&](int kc, int s) {
        uint32_t st = sbase + (uint32_t)s * STG_B;
#pragma unroll
        for (int i = 0; i < 4; ++i) {
            int idx = tid + i * 256;
            int r = idx >> 3, ch = idx & 7;
            uint32_t so = (uint32_t)(r * PADK * 2 + ch * 16);
            const size_t go = (size_t)kc * 64 + (size_t)r * DIMC + ch * 8;
            cp16(st + so,         srcs[0] + go);
            cp16(st + MAT_B + so, srcs[1] + go);
        }
    };

    float acc[4][4][4];
#pragma unroll
    for (int i = 0; i < 4; ++i)
#pragma unroll
        for (int j = 0; j < 4; ++j)
#pragma unroll
            for (int k = 0; k < 4; ++k) acc[i][j][k] = 0.0f;

    const int aRow = lane & 15;
    const int aColHalf = (lane >> 4) * 8;
    const int bRow = lane & 7;
    const int bColHalf = ((lane >> 3) & 1) * 8;

    load_chunk(0, 0); cp_commit();
    load_chunk(1, 1); cp_commit();

    const int NC = DIMC / 64;   // 16
    int sc = 0;
    for (int kc = 0; kc < NC; ++kc) {
        if (kc + 1 < NC) cp_wait1(); else cp_wait0();
        __syncthreads();
        if (kc + 2 < NC) {
            int s2 = sc + 2; if (s2 >= NSTG) s2 -= NSTG;
            load_chunk(kc + 2, s2);
            cp_commit();
        }

        uint32_t st = sbase + (uint32_t)sc * STG_B;
        uint32_t aA = st, bB = st + MAT_B;

#pragma unroll
        for (int ks = 0; ks < 4; ++ks) {
            uint32_t ah[4][4], bh[4][2];
            int kcol = ks * 16;
#pragma unroll
            for (int mf = 0; mf < 4; ++mf) {
                uint32_t off = (uint32_t)((wm0 + mf * 16 + aRow) * PADK + kcol + aColHalf) * 2;
                ldsm4(ah[mf][0], ah[mf][1], ah[mf][2], ah[mf][3], aA + off);
            }
#pragma unroll
            for (int nf = 0; nf < 4; ++nf) {
                uint32_t off = (uint32_t)((wn0 + nf * 8 + bRow) * PADK + kcol + bColHalf) * 2;
                ldsm2(bh[nf][0], bh[nf][1], bB + off);
            }
#pragma unroll
            for (int mf = 0; mf < 4; ++mf)
#pragma unroll
                for (int nf = 0; nf < 4; ++nf)
                    mma_fp(acc[mf][nf], ah[mf], bh[nf][0], bh[nf][1]);
        }

        ++sc; if (sc == NSTG) sc = 0;
    }

    const int erow = lane >> 2;
    const int ecol = (lane & 3) * 2;
#pragma unroll
    for (int mf = 0; mf < 4; ++mf) {
#pragma unroll
        for (int half = 0; half < 2; ++half) {
            int m = row0 + wm0 + mf * 16 + erow + half * 8;
            int b_ = m >> 11, t = m & (TT - 1);
#pragma unroll
            for (int nf = 0; nf < 4; ++nf) {
                int n = col0 + wn0 + nf * 8 + ecol;
                float vx = acc[mf][nf][half * 2 + 0] + bias[n + 0];
                float vy = acc[mf][nf][half * 2 + 1] + bias[n + 1];
                if (MODE == 0) {
                    float2 v = {vx, vy};
                    *(float2*)(Cout + (size_t)m * DIMC + n) = v;
                } else {
                    int sec = n >> 10;
                    int cc = n & (DIMC - 1);
                    int h = cc >> 6, d = cc & 63;
                    size_t idx = (((size_t)(b_ * NH + h)) * TT + t) * HD + d;
                    if (sec == 0) {
                        float qx = (vx + pos[cc + 0]) * QSCALE;
                        float qy = (vy + pos[cc + 1]) * QSCALE;
                        *(uint32_t*)(g_qh + idx) =
                            packh2(__float2half_rn(qx), __float2half_rn(qy));
                    } else if (sec == 1) {
                        *(uint32_t*)(g_kh + idx) =
                            packh2(__float2half_rn(vx), __float2half_rn(vy));
                    } else {
                        *(uint32_t*)(g_vh + idx) =
                            packh2(__float2half_rn(vx), __float2half_rn(vy));
                    }
                }
            }
        }
    }
}

// ============================================================================
// HMMA flash attention (round-14, unchanged): balanced pairing + lazy rescale.
// Tq=64, 4 warps, Bc=64; CTA does q-tile qa and complement (31-qa).
// ============================================================================
#define AT_PADH 72                      // fp16 elems per smem row (144 B)
#define Q_BYTES (64 * AT_PADH * 2)      // 9216
#define KV_MAT  (64 * AT_PADH * 2)      // 9216
#define KV_STAGE (2 * KV_MAT)           // 18432 (Kh, Vh)
#define ATT_SMEM (Q_BYTES + 2 * KV_STAGE)   // 46080
#define NQT (TT / 64)                   // 32 q-tiles

__global__ __launch_bounds__(128) void attn2()
{
    extern __shared__ char smraw[];
    const uint32_t sb = smem_u32(smraw);
    const uint32_t sQh = sb;
    const uint32_t sKV = sb + Q_BYTES;

    const int tid = threadIdx.x;
    const int lane = tid & 31;
    const int bh = blockIdx.y;
    const int qr0 = (tid >> 5) * 16;

    const __half* qhp = g_qh + (size_t)bh * TT * HD;
    const __half* kvsrc[2] = {
        g_kh + (size_t)bh * TT * HD, g_vh + (size_t)bh * TT * HD };

    auto prefetchKV = [&](int j, uint32_t dst) {
        int kb = j * 64;
#pragma unroll
        for (int i = 0; i < 8; ++i) {
            int c = tid + i * 128;
            int mat = c >> 9, rem = c & 511;
            int r = rem >> 3, ch = rem & 7;
            cp16(dst + (uint32_t)mat * KV_MAT + (uint32_t)(r * 144 + ch * 16),
                 kvsrc[mat] + (size_t)(kb + r) * HD + ch * 8);
        }
    };

    int b_ = bh >> 4, h = bh & 15;
    int coff = h * 64 + (lane & 3) * 2;

#pragma unroll 1
    for (int seg = 0; seg < 2; ++seg) {
        const int qi = (seg == 0) ? (int)blockIdx.x : (NQT - 1 - (int)blockIdx.x);
        const int q0 = qi * 64;
        const int ntiles = qi + 1;

#pragma unroll
        for (int i = 0; i < 4; ++i) {
            int c = tid + i * 128;
            int r = c >> 3, ch = c & 7;
            cp16(sQh + (uint32_t)(r * 144 + ch * 16),
                 qhp + (size_t)(q0 + r) * HD + ch * 8);
        }
        prefetchKV(0, sKV);
        cp_commit();
        cp_wait0();
        __syncthreads();

        uint32_t fqh[4][4];
        {
            int rr = qr0 + (lane & 15);
#pragma unroll
            for (int kf = 0; kf < 4; ++kf) {
                int cc = kf * 16 + ((lane & 16) ? 8 : 0);
                uint32_t off = (uint32_t)(rr * 144 + cc * 2);
                ldsm4(fqh[kf][0], fqh[kf][1], fqh[kf][2], fqh[kf][3], sQh + off);
            }
        }

        float o[8][4];
#pragma unroll
        for (int i = 0; i < 8; ++i)
#pragma unroll
            for (int k = 0; k < 4; ++k) o[i][k] = 0.0f;
        float m0 = -1e30f, m1 = -1e30f, l0 = 0.0f, l1 = 0.0f;

        for (int j = 0; j < ntiles; ++j) {
            uint32_t stage = sKV + (uint32_t)(j & 1) * KV_STAGE;
            if (j + 1 < ntiles) {
                prefetchKV(j + 1, sKV + (uint32_t)((j + 1) & 1) * KV_STAGE);
                cp_commit();
            }

            float c[8][4];
#pragma unroll
            for (int i = 0; i < 8; ++i)
#pragma unroll
                for (int k = 0; k < 4; ++k) c[i][k] = 0.0f;

            uint32_t Kh = stage;
            {
                int rb = ((lane & 16) ? 8 : 0) + (lane & 7);
                int cb = ((lane & 8) ? 8 : 0);
#pragma unroll
                for (int kf = 0; kf < 4; ++kf) {
#pragma unroll
                    for (int jp = 0; jp < 4; ++jp) {
                        uint32_t off = (uint32_t)((jp * 16 + rb) * 144 + (kf * 16 + cb) * 2);
                        uint32_t h0, h1, h2, h3;
                        ldsm4(h0, h1, h2, h3, Kh + off);
                        mma_fp(c[2 * jp],     fqh[kf], h0, h1);
                        mma_fp(c[2 * jp + 1], fqh[kf], h2, h3);
                    }
                }
            }

            if (j == ntiles - 1) {
                int row0 = q0 + qr0 + (lane >> 2);
                int kb = j * 64 + (lane & 3) * 2;
#pragma unroll
                for (int nf = 0; nf < 8; ++nf) {
                    int key = kb + nf * 8;
                    if (key     > row0)     c[nf][0] = -1e30f;
                    if (key + 1 > row0)     c[nf][1] = -1e30f;
                    if (key     > row0 + 8) c[nf][2] = -1e30f;
                    if (key + 1 > row0 + 8) c[nf][3] = -1e30f;
                }
            }

            float v0 = -1e30f, v1 = -1e30f;
#pragma unroll
            for (int nf = 0; nf < 8; ++nf) {
                v0 = fmaxf(v0, fmaxf(c[nf][0], c[nf][1]));
                v1 = fmaxf(v1, fmaxf(c[nf][2], c[nf][3]));
            }
            v0 = fmaxf(v0, __shfl_xor_sync(0xFFFFFFFFu, v0, 1));
            v0 = fmaxf(v0, __shfl_xor_sync(0xFFFFFFFFu, v0, 2));
            v1 = fmaxf(v1, __shfl_xor_sync(0xFFFFFFFFu, v1, 1));
            v1 = fmaxf(v1, __shfl_xor_sync(0xFFFFFFFFu, v1, 2));
            float mn0 = fmaxf(m0, v0), mn1 = fmaxf(m1, v1);
            bool nochg = (mn0 == m0) && (mn1 == m1);
            if (!__all_sync(0xFFFFFFFFu, nochg)) {
                float a0 = exp2p(m0 - mn0), a1 = exp2p(m1 - mn1);
                l0 *= a0; l1 *= a1;
#pragma unroll
                for (int nf = 0; nf < 8; ++nf) {
                    o[nf][0] *= a0; o[nf][1] *= a0;
                    o[nf][2] *= a1; o[nf][3] *= a1;
                }
            }
            m0 = mn0; m1 = mn1;

            uint32_t Vh = stage + KV_MAT;
            int vrb = ((lane & 8) ? 8 : 0) + (lane & 7);
            int vcb = ((lane & 16) ? 8 : 0);
#pragma unroll
            for (int t = 0; t < 4; ++t) {
                float p00 = exp2p(c[2 * t][0] - m0), p01 = exp2p(c[2 * t][1] - m0);
                float p02 = exp2p(c[2 * t][2] - m1), p03 = exp2p(c[2 * t][3] - m1);
                float p10 = exp2p(c[2 * t + 1][0] - m0), p11 = exp2p(c[2 * t + 1][1] - m0);
                float p12 = exp2p(c[2 * t + 1][2] - m1), p13 = exp2p(c[2 * t + 1][3] - m1);
                l0 += p00 + p01 + p10 + p11;
                l1 += p02 + p03 + p12 + p13;

                uint32_t ph[4];
                ph[0] = packh2(__float2half_rn(p00), __float2half_rn(p01));
                ph[1] = packh2(__float2half_rn(p02), __float2half_rn(p03));
                ph[2] = packh2(__float2half_rn(p10), __float2half_rn(p11));
                ph[3] = packh2(__float2half_rn(p12), __float2half_rn(p13));

#pragma unroll
                for (int dp = 0; dp < 4; ++dp) {
                    uint32_t off = (uint32_t)((t * 16 + vrb) * 144 + (dp * 16 + vcb) * 2);
                    uint32_t h0, h1, h2, h3;
                    ldsm4t(h0, h1, h2, h3, Vh + off);
                    mma_fp(o[2 * dp],     ph, h0, h1);
                    mma_fp(o[2 * dp + 1], ph, h2, h3);
                }
            }

            if (j + 1 < ntiles) cp_wait0();
            __syncthreads();
        }

        l0 += __shfl_xor_sync(0xFFFFFFFFu, l0, 1);
        l0 += __shfl_xor_sync(0xFFFFFFFFu, l0, 2);
        l1 += __shfl_xor_sync(0xFFFFFFFFu, l1, 1);
        l1 += __shfl_xor_sync(0xFFFFFFFFu, l1, 2);
        float inv0 = 1.0f / l0, inv1 = 1.0f / l1;

        int t0 = q0 + qr0 + (lane >> 2);
        size_t r0 = ((size_t)b_ * TT + t0) * DIMC;
        size_t r1 = r0 + (size_t)8 * DIMC;
#pragma unroll
        for (int nf = 0; nf < 8; ++nf) {
            int col = coff + nf * 8;
            *(uint32_t*)(g_ah + r0 + col) =
                packh2(__float2half_rn(o[nf][0] * inv0), __float2half_rn(o[nf][1] * inv0));
            *(uint32_t*)(g_ah + r1 + col) =
                packh2(__float2half_rn(o[nf][2] * inv1), __float2half_rn(o[nf][3] * inv1));
        }
        __syncthreads();
    }
}

// ============================================================================
// Launch
// ============================================================================
extern "C" void kernel_launch(void* const* d_in, const int* in_sizes, int n_in,
                              void* d_out, int out_size)
{
    (void)in_sizes; (void)n_in; (void)out_size;
    const float* x     = (const float*)d_in[0];
    const float* w_qkv = (const float*)d_in[1];
    const float* b_qkv = (const float*)d_in[2];
    const float* w_out = (const float*)d_in[3];
    const float* b_out = (const float*)d_in[4];
    const float* pos   = (const float*)d_in[5];
    float* out = (float*)d_out;

    cudaFuncSetAttribute(hmma_gemm<1>, cudaFuncAttributeMaxDynamicSharedMemorySize, GEMM_SMEM);
    cudaFuncSetAttribute(hmma_gemm<0>, cudaFuncAttributeMaxDynamicSharedMemorySize, GEMM_SMEM);
    cudaFuncSetAttribute(attn2, cudaFuncAttributeMaxDynamicSharedMemorySize, ATT_SMEM);

    // 0) convert input + fused transpose/convert of both weights to fp16
    conv_kernel<<<MTOT * DIMC / 1024, 256>>>(x);
    transpose_conv_fused<<<dim3(N_QKV / 32 + DIMC / 32, DIMC / 32), dim3(32, 8)>>>(w_qkv, w_out);

    // 1) QKV projection + bias (+pos, q-scale) -> fp16 Q, K, V
    hmma_gemm<1><<<dim3(N_QKV / 128, MTOT / 128), 256, GEMM_SMEM>>>(b_qkv, pos, nullptr);

    // 2) HMMA flash attention (balanced pairing, lazy rescale) -> fp16 attn out
    attn2<<<dim3(NQT / 2, BB * NH), 128, ATT_SMEM>>>();

    // 3) output projection + bias
    hmma_gemm<0><<<dim3(DIMC / 128, MTOT / 128), 256, GEMM_SMEM>>>(b_out, nullptr, out);
}

// round 16
// speedup vs baseline: 2.5998x; 1.0164x over previous
#include <cuda_runtime.h>
#include <cuda_bf16.h>
#include <cuda_fp16.h>
#include <cstdint>

// Problem constants
#define BB   2
#define TT   2048
#define DIMC 1024
#define NH   16
#define HD   64
#define MTOT (BB * TT)          // 4096
#define N_QKV (3 * DIMC)        // 3072

// q pre-scale: 1/sqrt(64) * log2(e)
#define QSCALE 0.18033688011112042f

// -------- scratch (device globals; no allocation allowed) --------
__device__ __half g_qh[BB * NH * TT * HD];
__device__ __half g_kh[BB * NH * TT * HD];
__device__ __half g_vh[BB * NH * TT * HD];
__device__ __half g_xh[MTOT * DIMC];          // x (fp16)
__device__ __half g_ah[MTOT * DIMC];          // attn out [B,T,C] (fp16)
__device__ __half g_wqh[N_QKV * DIMC];        // W_qkv^T (fp16)
__device__ __half g_woh[DIMC * DIMC];         // W_out^T (fp16)

// ============================================================================
// Helpers (plain-target PTX: cp.async / ldmatrix / mma.sync)
// ============================================================================
__device__ __forceinline__ uint32_t smem_u32(const void* p) {
    uint32_t a;
    asm("{ .reg .u64 t; cvta.to.shared.u64 t, %1; cvt.u32.u64 %0, t; }" : "=r"(a) : "l"(p));
    return a;
}
__device__ __forceinline__ void cp16(uint32_t dst, const void* src) {
    asm volatile("cp.async.cg.shared.global [%0], [%1], 16;" :: "r"(dst), "l"(src));
}
__device__ __forceinline__ void cp_commit() { asm volatile("cp.async.commit_group;" ::: "memory"); }
__device__ __forceinline__ void cp_wait0()  { asm volatile("cp.async.wait_group 0;" ::: "memory"); }
__device__ __forceinline__ void cp_wait1()  { asm volatile("cp.async.wait_group 1;" ::: "memory"); }

__device__ __forceinline__ void ldsm4(uint32_t& r0, uint32_t& r1, uint32_t& r2, uint32_t& r3,
                                      uint32_t addr) {
    asm volatile("ldmatrix.sync.aligned.m8n8.x4.shared.b16 {%0,%1,%2,%3}, [%4];"
                 : "=r"(r0), "=r"(r1), "=r"(r2), "=r"(r3) : "r"(addr));
}
__device__ __forceinline__ void ldsm4t(uint32_t& r0, uint32_t& r1, uint32_t& r2, uint32_t& r3,
                                       uint32_t addr) {
    asm volatile("ldmatrix.sync.aligned.m8n8.x4.trans.shared.b16 {%0,%1,%2,%3}, [%4];"
                 : "=r"(r0), "=r"(r1), "=r"(r2), "=r"(r3) : "r"(addr));
}
__device__ __forceinline__ void ldsm2(uint32_t& r0, uint32_t& r1, uint32_t addr) {
    asm volatile("ldmatrix.sync.aligned.m8n8.x2.shared.b16 {%0,%1}, [%2];"
                 : "=r"(r0), "=r"(r1) : "r"(addr));
}
__device__ __forceinline__ void mma_fp(float* c, const uint32_t* a, uint32_t b0, uint32_t b1) {
    asm volatile(
        "mma.sync.aligned.m16n8k16.row.col.f32.f16.f16.f32 "
        "{%0,%1,%2,%3}, {%4,%5,%6,%7}, {%8,%9}, {%0,%1,%2,%3};"
        : "+f"(c[0]), "+f"(c[1]), "+f"(c[2]), "+f"(c[3])
        : "r"(a[0]), "r"(a[1]), "r"(a[2]), "r"(a[3]), "r"(b0), "r"(b1));
}

// exp2 on FFMA pipe: magic-number round + degree-5 Taylor, t <= 0
// exp2p(0) == 1.0f exactly.
__device__ __forceinline__ float exp2p(float t) {
    t = fmaxf(t, -80.0f);
    float k = t + 12582912.0f;
    int ik = __float_as_int(k) << 23;
    float f = t - (k - 12582912.0f);
    float r = 1.3333558146e-3f;
    r = fmaf(r, f, 9.6181291076e-3f);
    r = fmaf(r, f, 5.5504108664e-2f);
    r = fmaf(r, f, 2.4022650696e-1f);
    r = fmaf(r, f, 6.9314718056e-1f);
    r = fmaf(r, f, 1.0f);
    return __int_as_float(__float_as_int(r) + ik);
}

__device__ __forceinline__ uint32_t packh2(__half a, __half b) {
    __half2 h = __halves2half2(a, b);
    return *(uint32_t*)&h;
}

// ============================================================================
// fp32 -> fp16 conversion (x), vectorized float4
// ============================================================================
__global__ void conv_kernel(const float* __restrict__ src) {
    int i = (blockIdx.x * blockDim.x + threadIdx.x) * 4;
    float4 v = *(const float4*)(src + i);
    *(uint32_t*)(g_xh + i)     = packh2(__float2half_rn(v.x), __float2half_rn(v.y));
    *(uint32_t*)(g_xh + i + 2) = packh2(__float2half_rn(v.z), __float2half_rn(v.w));
}

// ============================================================================
// Fused weight transpose: W[K=1024, N] -> W^T [N, 1024] fp16 for BOTH weights.
// ============================================================================
__global__ void transpose_conv_fused(const float* __restrict__ Wq,
                                     const float* __restrict__ Wo) {
    const int bq = N_QKV / 32;           // 96 blocks for w_qkv
    bool isQ = (blockIdx.x < (unsigned)bq);
    const float* Win = isQ ? Wq : Wo;
    __half* Th = isQ ? g_wqh : g_woh;
    const int N = isQ ? N_QKV : DIMC;
    int bx = isQ ? blockIdx.x : (blockIdx.x - bq);

    __shared__ float t[32][33];
    int tx = threadIdx.x, ty = threadIdx.y;
    int n0 = bx * 32, k0 = blockIdx.y * 32;
#pragma unroll
    for (int j = 0; j < 32; j += 8)
        t[ty + j][tx] = Win[(size_t)(k0 + ty + j) * N + n0 + tx];
    __syncthreads();
#pragma unroll
    for (int j = 0; j < 32; j += 8) {
        float v = t[tx][ty + j];
        Th[(size_t)(n0 + ty + j) * DIMC + k0 + tx] = __float2half_rn(v);
    }
}

// ============================================================================
// HMMA fp16 GEMM (round-15 winner, unchanged): C = A·B single fp16. BK=64
// (144B rows, conflict-free), 3-stage cp.async ring, one barrier/iter.
// 128x128 CTA, 8 warps (2x4), 64x32 warp tiles.
// MODE 1 -> fp16 Q (+pos, scaled), K, V. MODE 0 -> fp32 Cout + bias.
// ============================================================================
#define PADK   72                  // 64 + 8 fp16 padding (144B rows)
#define MAT_B  (128 * PADK * 2)    // 18432 B
#define STG_B  (2 * MAT_B)         // 36864 B (A, B)
#define NSTG   3
#define GEMM_SMEM (NSTG * STG_B)   // 110592 B

template <int MODE>
__global__ __launch_bounds__(256) void hmma_gemm(
    const float* __restrict__ bias, const float* __restrict__ pos,
    float* __restrict__ Cout)
{
    const __half* Aa = (MODE == 1) ? g_xh : g_ah;
    const __half* Bb = (MODE == 1) ? g_wqh : g_woh;

    extern __shared__ char smraw[];
    const uint32_t sbase = smem_u32(smraw);

    const int tid = threadIdx.x;
    const int wid = tid >> 5, lane = tid & 31;
    const int wm0 = (wid >> 2) * 64;
    const int wn0 = (wid & 3) * 32;

    const int row0 = blockIdx.y * 128;
    const int col0 = blockIdx.x * 128;

    const __half* srcs[2] = {
        Aa + (size_t)row0 * DIMC,
        Bb + (size_t)col0 * DIMC };

    auto load_chunk = [&](int kc, int s) {
        uint32_t st = sbase + (uint32_t)s * STG_B;
#pragma unroll
        for (int i = 0; i < 4; ++i) {
            int idx = tid + i * 256;
            int r = idx >> 3, ch = idx & 7;
            uint32_t so = (uint32_t)(r * PADK * 2 + ch * 16);
            const size_t go = (size_t)kc * 64 + (size_t)r * DIMC + ch * 8;
            cp16(st + so,         srcs[0] + go);
            cp16(st + MAT_B + so, srcs[1] + go);
        }
    };

    float acc[4][4][4];
#pragma unroll
    for (int i = 0; i < 4; ++i)
#pragma unroll
        for (int j = 0; j < 4; ++j)
#pragma unroll
            for (int k = 0; k < 4; ++k) acc[i][j][k] = 0.0f;

    const int aRow = lane & 15;
    const int aColHalf = (lane >> 4) * 8;
    const int bRow = lane & 7;
    const int bColHalf = ((lane >> 3) & 1) * 8;

    load_chunk(0, 0); cp_commit();
    load_chunk(1, 1); cp_commit();

    const int NC = DIMC / 64;   // 16
    int sc = 0;
    for (int kc = 0; kc < NC; ++kc) {
        if (kc + 1 < NC) cp_wait1(); else cp_wait0();
        __syncthreads();
        if (kc + 2 < NC) {
            int s2 = sc + 2; if (s2 >= NSTG) s2 -= NSTG;
            load_chunk(kc + 2, s2);
            cp_commit();
        }

        uint32_t st = sbase + (uint32_t)sc * STG_B;
        uint32_t aA = st, bB = st + MAT_B;

#pragma unroll
        for (int ks = 0; ks < 4; ++ks) {
            uint32_t ah[4][4], bh[4][2];
            int kcol = ks * 16;
#pragma unroll
            for (int mf = 0; mf < 4; ++mf) {
                uint32_t off = (uint32_t)((wm0 + mf * 16 + aRow) * PADK + kcol + aColHalf) * 2;
                ldsm4(ah[mf][0], ah[mf][1], ah[mf][2], ah[mf][3], aA + off);
            }
#pragma unroll
            for (int nf = 0; nf < 4; ++nf) {
                uint32_t off = (uint32_t)((wn0 + nf * 8 + bRow) * PADK + kcol + bColHalf) * 2;
                ldsm2(bh[nf][0], bh[nf][1], bB + off);
            }
#pragma unroll
            for (int mf = 0; mf < 4; ++mf)
#pragma unroll
                for (int nf = 0; nf < 4; ++nf)
                    mma_fp(acc[mf][nf], ah[mf], bh[nf][0], bh[nf][1]);
        }

        ++sc; if (sc == NSTG) sc = 0;
    }

    const int erow = lane >> 2;
    const int ecol = (lane & 3) * 2;
#pragma unroll
    for (int mf = 0; mf < 4; ++mf) {
#pragma unroll
        for (int half = 0; half < 2; ++half) {
            int m = row0 + wm0 + mf * 16 + erow + half * 8;
            int b_ = m >> 11, t = m & (TT - 1);
#pragma unroll
            for (int nf = 0; nf < 4; ++nf) {
                int n = col0 + wn0 + nf * 8 + ecol;
                float vx = acc[mf][nf][half * 2 + 0] + bias[n + 0];
                float vy = acc[mf][nf][half * 2 + 1] + bias[n + 1];
                if (MODE == 0) {
                    float2 v = {vx, vy};
                    *(float2*)(Cout + (size_t)m * DIMC + n) = v;
                } else {
                    int sec = n >> 10;
                    int cc = n & (DIMC - 1);
                    int h = cc >> 6, d = cc & 63;
                    size_t idx = (((size_t)(b_ * NH + h)) * TT + t) * HD + d;
                    if (sec == 0) {
                        float qx = (vx + pos[cc + 0]) * QSCALE;
                        float qy = (vy + pos[cc + 1]) * QSCALE;
                        *(uint32_t*)(g_qh + idx) =
                            packh2(__float2half_rn(qx), __float2half_rn(qy));
                    } else if (sec == 1) {
                        *(uint32_t*)(g_kh + idx) =
                            packh2(__float2half_rn(vx), __float2half_rn(vy));
                    } else {
                        *(uint32_t*)(g_vh + idx) =
                            packh2(__float2half_rn(vx), __float2half_rn(vy));
                    }
                }
            }
        }
    }
}

// ============================================================================
// HMMA flash attention — balanced pairing + lazy rescale (round-14 body),
// now with __launch_bounds__(128, 4): reg cap 128 -> 4 CTAs/SM.
// Tq=64, 4 warps, Bc=64; CTA does q-tile qa and complement (31-qa).
// ============================================================================
#define AT_PADH 72                      // fp16 elems per smem row (144 B)
#define Q_BYTES (64 * AT_PADH * 2)      // 9216
#define KV_MAT  (64 * AT_PADH * 2)      // 9216
#define KV_STAGE (2 * KV_MAT)           // 18432 (Kh, Vh)
#define ATT_SMEM (Q_BYTES + 2 * KV_STAGE)   // 46080
#define NQT (TT / 64)                   // 32 q-tiles

__global__ __launch_bounds__(128, 4) void attn2()
{
    extern __shared__ char smraw[];
    const uint32_t sb = smem_u32(smraw);
    const uint32_t sQh = sb;
    const uint32_t sKV = sb + Q_BYTES;

    const int tid = threadIdx.x;
    const int lane = tid & 31;
    const int bh = blockIdx.y;
    const int qr0 = (tid >> 5) * 16;

    const __half* qhp = g_qh + (size_t)bh * TT * HD;
    const __half* kvsrc[2] = {
        g_kh + (size_t)bh * TT * HD, g_vh + (size_t)bh * TT * HD };

    auto prefetchKV = [&](int j, uint32_t dst) {
        int kb = j * 64;
#pragma unroll
        for (int i = 0; i < 8; ++i) {
            int c = tid + i * 128;
            int mat = c >> 9, rem = c & 511;
            int r = rem >> 3, ch = rem & 7;
            cp16(dst + (uint32_t)mat * KV_MAT + (uint32_t)(r * 144 + ch * 16),
                 kvsrc[mat] + (size_t)(kb + r) * HD + ch * 8);
        }
    };

    int b_ = bh >> 4, h = bh & 15;
    int coff = h * 64 + (lane & 3) * 2;

#pragma unroll 1
    for (int seg = 0; seg < 2; ++seg) {
        const int qi = (seg == 0) ? (int)blockIdx.x : (NQT - 1 - (int)blockIdx.x);
        const int q0 = qi * 64;
        const int ntiles = qi + 1;

#pragma unroll
        for (int i = 0; i < 4; ++i) {
            int c = tid + i * 128;
            int r = c >> 3, ch = c & 7;
            cp16(sQh + (uint32_t)(r * 144 + ch * 16),
                 qhp + (size_t)(q0 + r) * HD + ch * 8);
        }
        prefetchKV(0, sKV);
        cp_commit();
        cp_wait0();
        __syncthreads();

        uint32_t fqh[4][4];
        {
            int rr = qr0 + (lane & 15);
#pragma unroll
            for (int kf = 0; kf < 4; ++kf) {
                int cc = kf * 16 + ((lane & 16) ? 8 : 0);
                uint32_t off = (uint32_t)(rr * 144 + cc * 2);
                ldsm4(fqh[kf][0], fqh[kf][1], fqh[kf][2], fqh[kf][3], sQh + off);
            }
        }

        float o[8][4];
#pragma unroll
        for (int i = 0; i < 8; ++i)
#pragma unroll
            for (int k = 0; k < 4; ++k) o[i][k] = 0.0f;
        float m0 = -1e30f, m1 = -1e30f, l0 = 0.0f, l1 = 0.0f;

        for (int j = 0; j < ntiles; ++j) {
            uint32_t stage = sKV + (uint32_t)(j & 1) * KV_STAGE;
            if (j + 1 < ntiles) {
                prefetchKV(j + 1, sKV + (uint32_t)((j + 1) & 1) * KV_STAGE);
                cp_commit();
            }

            float c[8][4];
#pragma unroll
            for (int i = 0; i < 8; ++i)
#pragma unroll
                for (int k = 0; k < 4; ++k) c[i][k] = 0.0f;

            uint32_t Kh = stage;
            {
                int rb = ((lane & 16) ? 8 : 0) + (lane & 7);
                int cb = ((lane & 8) ? 8 : 0);
#pragma unroll
                for (int kf = 0; kf < 4; ++kf) {
#pragma unroll
                    for (int jp = 0; jp < 4; ++jp) {
                        uint32_t off = (uint32_t)((jp * 16 + rb) * 144 + (kf * 16 + cb) * 2);
                        uint32_t h0, h1, h2, h3;
                        ldsm4(h0, h1, h2, h3, Kh + off);
                        mma_fp(c[2 * jp],     fqh[kf], h0, h1);
                        mma_fp(c[2 * jp + 1], fqh[kf], h2, h3);
                    }
                }
            }

            if (j == ntiles - 1) {
                int row0 = q0 + qr0 + (lane >> 2);
                int kb = j * 64 + (lane & 3) * 2;
#pragma unroll
                for (int nf = 0; nf < 8; ++nf) {
                    int key = kb + nf * 8;
                    if (key     > row0)     c[nf][0] = -1e30f;
                    if (key + 1 > row0)     c[nf][1] = -1e30f;
                    if (key     > row0 + 8) c[nf][2] = -1e30f;
                    if (key + 1 > row0 + 8) c[nf][3] = -1e30f;
                }
            }

            float v0 = -1e30f, v1 = -1e30f;
#pragma unroll
            for (int nf = 0; nf < 8; ++nf) {
                v0 = fmaxf(v0, fmaxf(c[nf][0], c[nf][1]));
                v1 = fmaxf(v1, fmaxf(c[nf][2], c[nf][3]));
            }
            v0 = fmaxf(v0, __shfl_xor_sync(0xFFFFFFFFu, v0, 1));
            v0 = fmaxf(v0, __shfl_xor_sync(0xFFFFFFFFu, v0, 2));
            v1 = fmaxf(v1, __shfl_xor_sync(0xFFFFFFFFu, v1, 1));
            v1 = fmaxf(v1, __shfl_xor_sync(0xFFFFFFFFu, v1, 2));
            float mn0 = fmaxf(m0, v0), mn1 = fmaxf(m1, v1);
            bool nochg = (mn0 == m0) && (mn1 == m1);
            if (!__all_sync(0xFFFFFFFFu, nochg)) {
                float a0 = exp2p(m0 - mn0), a1 = exp2p(m1 - mn1);
                l0 *= a0; l1 *= a1;
#pragma unroll
                for (int nf = 0; nf < 8; ++nf) {
                    o[nf][0] *= a0; o[nf][1] *= a0;
                    o[nf][2] *= a1; o[nf][3] *= a1;
                }
            }
            m0 = mn0; m1 = mn1;

            uint32_t Vh = stage + KV_MAT;
            int vrb = ((lane & 8) ? 8 : 0) + (lane & 7);
            int vcb = ((lane & 16) ? 8 : 0);
#pragma unroll
            for (int t = 0; t < 4; ++t) {
                float p00 = exp2p(c[2 * t][0] - m0), p01 = exp2p(c[2 * t][1] - m0);
                float p02 = exp2p(c[2 * t][2] - m1), p03 = exp2p(c[2 * t][3] - m1);
                float p10 = exp2p(c[2 * t + 1][0] - m0), p11 = exp2p(c[2 * t + 1][1] - m0);
                float p12 = exp2p(c[2 * t + 1][2] - m1), p13 = exp2p(c[2 * t + 1][3] - m1);
                l0 += p00 + p01 + p10 + p11;
                l1 += p02 + p03 + p12 + p13;

                uint32_t ph[4];
                ph[0] = packh2(__float2half_rn(p00), __float2half_rn(p01));
                ph[1] = packh2(__float2half_rn(p02), __float2half_rn(p03));
                ph[2] = packh2(__float2half_rn(p10), __float2half_rn(p11));
                ph[3] = packh2(__float2half_rn(p12), __float2half_rn(p13));

#pragma unroll
                for (int dp = 0; dp < 4; ++dp) {
                    uint32_t off = (uint32_t)((t * 16 + vrb) * 144 + (dp * 16 + vcb) * 2);
                    uint32_t h0, h1, h2, h3;
                    ldsm4t(h0, h1, h2, h3, Vh + off);
                    mma_fp(o[2 * dp],     ph, h0, h1);
                    mma_fp(o[2 * dp + 1], ph, h2, h3);
                }
            }

            if (j + 1 < ntiles) cp_wait0();
            __syncthreads();
        }

        l0 += __shfl_xor_sync(0xFFFFFFFFu, l0, 1);
        l0 += __shfl_xor_sync(0xFFFFFFFFu, l0, 2);
        l1 += __shfl_xor_sync(0xFFFFFFFFu, l1, 1);
        l1 += __shfl_xor_sync(0xFFFFFFFFu, l1, 2);
        float inv0 = 1.0f / l0, inv1 = 1.0f / l1;

        int t0 = q0 + qr0 + (lane >> 2);
        size_t r0 = ((size_t)b_ * TT + t0) * DIMC;
        size_t r1 = r0 + (size_t)8 * DIMC;
#pragma unroll
        for (int nf = 0; nf < 8; ++nf) {
            int col = coff + nf * 8;
            *(uint32_t*)(g_ah + r0 + col) =
                packh2(__float2half_rn(o[nf][0] * inv0), __float2half_rn(o[nf][1] * inv0));
            *(uint32_t*)(g_ah + r1 + col) =
                packh2(__float2half_rn(o[nf][2] * inv1), __float2half_rn(o[nf][3] * inv1));
        }
        __syncthreads();
    }
}

// ============================================================================
// Launch
// ============================================================================
extern "C" void kernel_launch(void* const* d_in, const int* in_sizes, int n_in,
                              void* d_out, int out_size)
{
    (void)in_sizes; (void)n_in; (void)out_size;
    const float* x     = (const float*)d_in[0];
    const float* w_qkv = (const float*)d_in[1];
    const float* b_qkv = (const float*)d_in[2];
    const float* w_out = (const float*)d_in[3];
    const float* b_out = (const float*)d_in[4];
    const float* pos   = (const float*)d_in[5];
    float* out = (float*)d_out;

    cudaFuncSetAttribute(hmma_gemm<1>, cudaFuncAttributeMaxDynamicSharedMemorySize, GEMM_SMEM);
    cudaFuncSetAttribute(hmma_gemm<0>, cudaFuncAttributeMaxDynamicSharedMemorySize, GEMM_SMEM);
    cudaFuncSetAttribute(attn2, cudaFuncAttributeMaxDynamicSharedMemorySize, ATT_SMEM);

    // 0) convert input + fused transpose/convert of both weights to fp16
    conv_kernel<<<MTOT * DIMC / 1024, 256>>>(x);
    transpose_conv_fused<<<dim3(N_QKV / 32 + DIMC / 32, DIMC / 32), dim3(32, 8)>>>(w_qkv, w_out);

    // 1) QKV projection + bias (+pos, q-scale) -> fp16 Q, K, V
    hmma_gemm<1><<<dim3(N_QKV / 128, MTOT / 128), 256, GEMM_SMEM>>>(b_qkv, pos, nullptr);

    // 2) HMMA flash attention (balanced pairing, lazy rescale, 4 CTA/SM)
    attn2<<<dim3(NQT / 2, BB * NH), 128, ATT_SMEM>>>();

    // 3) output projection + bias
    hmma_gemm<0><<<dim3(DIMC / 128, MTOT / 128), 256, GEMM_SMEM>>>(b_out, nullptr, out);
}

// round 17
// speedup vs baseline: 2.6562x; 1.0217x over previous
#include <cuda_runtime.h>
#include <cuda_bf16.h>
#include <cuda_fp16.h>
#include <cstdint>

// Problem constants
#define BB   2
#define TT   2048
#define DIMC 1024
#define NH   16
#define HD   64
#define MTOT (BB * TT)          // 4096
#define N_QKV (3 * DIMC)        // 3072

// q pre-scale: 1/sqrt(64) * log2(e)
#define QSCALE 0.18033688011112042f

// -------- scratch (device globals; no allocation allowed) --------
__device__ __half g_qh[BB * NH * TT * HD];
__device__ __half g_kh[BB * NH * TT * HD];
__device__ __half g_vh[BB * NH * TT * HD];
__device__ __half g_xh[MTOT * DIMC];          // x (fp16)
__device__ __half g_ah[MTOT * DIMC];          // attn out [B,T,C] (fp16)
__device__ __half g_wqh[N_QKV * DIMC];        // W_qkv^T (fp16)
__device__ __half g_woh[DIMC * DIMC];         // W_out^T (fp16)

// ============================================================================
// Helpers (plain-target PTX: cp.async / ldmatrix / mma.sync)
// ============================================================================
__device__ __forceinline__ uint32_t smem_u32(const void* p) {
    uint32_t a;
    asm("{ .reg .u64 t; cvta.to.shared.u64 t, %1; cvt.u32.u64 %0, t; }" : "=r"(a) : "l"(p));
    return a;
}
__device__ __forceinline__ void cp16(uint32_t dst, const void* src) {
    asm volatile("cp.async.cg.shared.global [%0], [%1], 16;" :: "r"(dst), "l"(src));
}
__device__ __forceinline__ void cp_commit() { asm volatile("cp.async.commit_group;" ::: "memory"); }
__device__ __forceinline__ void cp_wait0()  { asm volatile("cp.async.wait_group 0;" ::: "memory"); }
__device__ __forceinline__ void cp_wait1()  { asm volatile("cp.async.wait_group 1;" ::: "memory"); }

__device__ __forceinline__ void ldsm4(uint32_t& r0, uint32_t& r1, uint32_t& r2, uint32_t& r3,
                                      uint32_t addr) {
    asm volatile("ldmatrix.sync.aligned.m8n8.x4.shared.b16 {%0,%1,%2,%3}, [%4];"
                 : "=r"(r0), "=r"(r1), "=r"(r2), "=r"(r3) : "r"(addr));
}
__device__ __forceinline__ void ldsm4t(uint32_t& r0, uint32_t& r1, uint32_t& r2, uint32_t& r3,
                                       uint32_t addr) {
    asm volatile("ldmatrix.sync.aligned.m8n8.x4.trans.shared.b16 {%0,%1,%2,%3}, [%4];"
                 : "=r"(r0), "=r"(r1), "=r"(r2), "=r"(r3) : "r"(addr));
}
__device__ __forceinline__ void ldsm2(uint32_t& r0, uint32_t& r1, uint32_t addr) {
    asm volatile("ldmatrix.sync.aligned.m8n8.x2.shared.b16 {%0,%1}, [%2];"
                 : "=r"(r0), "=r"(r1) : "r"(addr));
}
__device__ __forceinline__ void mma_fp(float* c, const uint32_t* a, uint32_t b0, uint32_t b1) {
    asm volatile(
        "mma.sync.aligned.m16n8k16.row.col.f32.f16.f16.f32 "
        "{%0,%1,%2,%3}, {%4,%5,%6,%7}, {%8,%9}, {%0,%1,%2,%3};"
        : "+f"(c[0]), "+f"(c[1]), "+f"(c[2]), "+f"(c[3])
        : "r"(a[0]), "r"(a[1]), "r"(a[2]), "r"(a[3]), "r"(b0), "r"(b1));
}

// exp2 on FFMA pipe: magic-number round + degree-5 Taylor, t <= 0
// exp2p(0) == 1.0f exactly.
__device__ __forceinline__ float exp2p(float t) {
    t = fmaxf(t, -80.0f);
    float k = t + 12582912.0f;
    int ik = __float_as_int(k) << 23;
    float f = t - (k - 12582912.0f);
    float r = 1.3333558146e-3f;
    r = fmaf(r, f, 9.6181291076e-3f);
    r = fmaf(r, f, 5.5504108664e-2f);
    r = fmaf(r, f, 2.4022650696e-1f);
    r = fmaf(r, f, 6.9314718056e-1f);
    r = fmaf(r, f, 1.0f);
    return __int_as_float(__float_as_int(r) + ik);
}

__device__ __forceinline__ uint32_t packh2(__half a, __half b) {
    __half2 h = __halves2half2(a, b);
    return *(uint32_t*)&h;
}

// ============================================================================
// Fused prep: blocks [0, 128) transpose/convert both weights;
// blocks [128, 128+4096) convert x to fp16 (1024 elems per block-slot).
// Grid: dim3(128 + 4096/32, 32), block dim3(32, 8).
// ============================================================================
__global__ void prep_fused(const float* __restrict__ x,
                           const float* __restrict__ Wq,
                           const float* __restrict__ Wo) {
    const int bq = N_QKV / 32;               // 96
    const int bt = bq + DIMC / 32;           // 128 transpose blocks
    int tidl = threadIdx.y * 32 + threadIdx.x;   // 0..255

    if (blockIdx.x >= (unsigned)bt) {
        // x conversion: slot id 0..4095, 1024 elems each
        int cid = (blockIdx.x - bt) * 32 + blockIdx.y;
        int i = (cid * 256 + tidl) * 4;
        float4 v = *(const float4*)(x + i);
        *(uint32_t*)(g_xh + i)     = packh2(__float2half_rn(v.x), __float2half_rn(v.y));
        *(uint32_t*)(g_xh + i + 2) = packh2(__float2half_rn(v.z), __float2half_rn(v.w));
        return;
    }

    bool isQ = (blockIdx.x < (unsigned)bq);
    const float* Win = isQ ? Wq : Wo;
    __half* Th = isQ ? g_wqh : g_woh;
    const int N = isQ ? N_QKV : DIMC;
    int bx = isQ ? blockIdx.x : (blockIdx.x - bq);

    __shared__ float t[32][33];
    int tx = threadIdx.x, ty = threadIdx.y;
    int n0 = bx * 32, k0 = blockIdx.y * 32;
#pragma unroll
    for (int j = 0; j < 32; j += 8)
        t[ty + j][tx] = Win[(size_t)(k0 + ty + j) * N + n0 + tx];
    __syncthreads();
#pragma unroll
    for (int j = 0; j < 32; j += 8) {
        float v = t[tx][ty + j];
        Th[(size_t)(n0 + ty + j) * DIMC + k0 + tx] = __float2half_rn(v);
    }
}

// ============================================================================
// HMMA fp16 GEMM (round-15 winner, unchanged): C = A·B single fp16. BK=64
// (144B rows, conflict-free), 3-stage cp.async ring, one barrier/iter.
// 128x128 CTA, 8 warps (2x4), 64x32 warp tiles.
// MODE 1 -> fp16 Q (+pos, scaled), K, V. MODE 0 -> fp32 Cout + bias.
// ============================================================================
#define PADK   72                  // 64 + 8 fp16 padding (144B rows)
#define MAT_B  (128 * PADK * 2)    // 18432 B
#define STG_B  (2 * MAT_B)         // 36864 B (A, B)
#define NSTG   3
#define GEMM_SMEM (NSTG * STG_B)   // 110592 B

template <int MODE>
__global__ __launch_bounds__(256) void hmma_gemm(
    const float* __restrict__ bias, const float* __restrict__ pos,
    float* __restrict__ Cout)
{
    const __half* Aa = (MODE == 1) ? g_xh : g_ah;
    const __half* Bb = (MODE == 1) ? g_wqh : g_woh;

    extern __shared__ char smraw[];
    const uint32_t sbase = smem_u32(smraw);

    const int tid = threadIdx.x;
    const int wid = tid >> 5, lane = tid & 31;
    const int wm0 = (wid >> 2) * 64;
    const int wn0 = (wid & 3) * 32;

    const int row0 = blockIdx.y * 128;
    const int col0 = blockIdx.x * 128;

    const __half* srcs[2] = {
        Aa + (size_t)row0 * DIMC,
        Bb + (size_t)col0 * DIMC };

    auto load_chunk = [&](int kc, int s) {
        uint32_t st = sbase + (uint32_t)s * STG_B;
#pragma unroll
        for (int i = 0; i < 4; ++i) {
            int idx = tid + i * 256;
            int r = idx >> 3, ch = idx & 7;
            uint32_t so = (uint32_t)(r * PADK * 2 + ch * 16);
            const size_t go = (size_t)kc * 64 + (size_t)r * DIMC + ch * 8;
            cp16(st + so,         srcs[0] + go);
            cp16(st + MAT_B + so, srcs[1] + go);
        }
    };

    float acc[4][4][4];
#pragma unroll
    for (int i = 0; i < 4; ++i)
#pragma unroll
        for (int j = 0; j < 4; ++j)
#pragma unroll
            for (int k = 0; k < 4; ++k) acc[i][j][k] = 0.0f;

    const int aRow = lane & 15;
    const int aColHalf = (lane >> 4) * 8;
    const int bRow = lane & 7;
    const int bColHalf = ((lane >> 3) & 1) * 8;

    load_chunk(0, 0); cp_commit();
    load_chunk(1, 1); cp_commit();

    const int NC = DIMC / 64;   // 16
    int sc = 0;
    for (int kc = 0; kc < NC; ++kc) {
        if (kc + 1 < NC) cp_wait1(); else cp_wait0();
        __syncthreads();
        if (kc + 2 < NC) {
            int s2 = sc + 2; if (s2 >= NSTG) s2 -= NSTG;
            load_chunk(kc + 2, s2);
            cp_commit();
        }

        uint32_t st = sbase + (uint32_t)sc * STG_B;
        uint32_t aA = st, bB = st + MAT_B;

#pragma unroll
        for (int ks = 0; ks < 4; ++ks) {
            uint32_t ah[4][4], bh[4][2];
            int kcol = ks * 16;
#pragma unroll
            for (int mf = 0; mf < 4; ++mf) {
                uint32_t off = (uint32_t)((wm0 + mf * 16 + aRow) * PADK + kcol + aColHalf) * 2;
                ldsm4(ah[mf][0], ah[mf][1], ah[mf][2], ah[mf][3], aA + off);
            }
#pragma unroll
            for (int nf = 0; nf < 4; ++nf) {
                uint32_t off = (uint32_t)((wn0 + nf * 8 + bRow) * PADK + kcol + bColHalf) * 2;
                ldsm2(bh[nf][0], bh[nf][1], bB + off);
            }
#pragma unroll
            for (int mf = 0; mf < 4; ++mf)
#pragma unroll
                for (int nf = 0; nf < 4; ++nf)
                    mma_fp(acc[mf][nf], ah[mf], bh[nf][0], bh[nf][1]);
        }

        ++sc; if (sc == NSTG) sc = 0;
    }

    const int erow = lane >> 2;
    const int ecol = (lane & 3) * 2;
#pragma unroll
    for (int mf = 0; mf < 4; ++mf) {
#pragma unroll
        for (int half = 0; half < 2; ++half) {
            int m = row0 + wm0 + mf * 16 + erow + half * 8;
            int b_ = m >> 11, t = m & (TT - 1);
#pragma unroll
            for (int nf = 0; nf < 4; ++nf) {
                int n = col0 + wn0 + nf * 8 + ecol;
                float vx = acc[mf][nf][half * 2 + 0] + bias[n + 0];
                float vy = acc[mf][nf][half * 2 + 1] + bias[n + 1];
                if (MODE == 0) {
                    float2 v = {vx, vy};
                    *(float2*)(Cout + (size_t)m * DIMC + n) = v;
                } else {
                    int sec = n >> 10;
                    int cc = n & (DIMC - 1);
                    int h = cc >> 6, d = cc & 63;
                    size_t idx = (((size_t)(b_ * NH + h)) * TT + t) * HD + d;
                    if (sec == 0) {
                        float qx = (vx + pos[cc + 0]) * QSCALE;
                        float qy = (vy + pos[cc + 1]) * QSCALE;
                        *(uint32_t*)(g_qh + idx) =
                            packh2(__float2half_rn(qx), __float2half_rn(qy));
                    } else if (sec == 1) {
                        *(uint32_t*)(g_kh + idx) =
                            packh2(__float2half_rn(vx), __float2half_rn(vy));
                    } else {
                        *(uint32_t*)(g_vh + idx) =
                            packh2(__float2half_rn(vx), __float2half_rn(vy));
                    }
                }
            }
        }
    }
}

// ============================================================================
// HMMA flash attention — balanced pairing + lazy rescale + diagonal-tile
// work skip. Tq=64, 4 warps, Bc=64, 4 CTAs/SM.
// On the diagonal tile, warp w only computes key blocks jp <= w (others are
// fully masked; skipping drops only ~2^-80 terms from l — negligible).
// ============================================================================
#define AT_PADH 72                      // fp16 elems per smem row (144 B)
#define Q_BYTES (64 * AT_PADH * 2)      // 9216
#define KV_MAT  (64 * AT_PADH * 2)      // 9216
#define KV_STAGE (2 * KV_MAT)           // 18432 (Kh, Vh)
#define ATT_SMEM (Q_BYTES + 2 * KV_STAGE)   // 46080
#define NQT (TT / 64)                   // 32 q-tiles

__global__ __launch_bounds__(128, 4) void attn2()
{
    extern __shared__ char smraw[];
    const uint32_t sb = smem_u32(smraw);
    const uint32_t sQh = sb;
    const uint32_t sKV = sb + Q_BYTES;

    const int tid = threadIdx.x;
    const int lane = tid & 31;
    const int bh = blockIdx.y;
    const int warp = tid >> 5;
    const int qr0 = warp * 16;

    const __half* qhp = g_qh + (size_t)bh * TT * HD;
    const __half* kvsrc[2] = {
        g_kh + (size_t)bh * TT * HD, g_vh + (size_t)bh * TT * HD };

    auto prefetchKV = [&](int j, uint32_t dst) {
        int kb = j * 64;
#pragma unroll
        for (int i = 0; i < 8; ++i) {
            int c = tid + i * 128;
            int mat = c >> 9, rem = c & 511;
            int r = rem >> 3, ch = rem & 7;
            cp16(dst + (uint32_t)mat * KV_MAT + (uint32_t)(r * 144 + ch * 16),
                 kvsrc[mat] + (size_t)(kb + r) * HD + ch * 8);
        }
    };

    int b_ = bh >> 4, h = bh & 15;
    int coff = h * 64 + (lane & 3) * 2;

    // hoisted ldsm address components
    const int rb = ((lane & 16) ? 8 : 0) + (lane & 7);
    const int cb = ((lane & 8) ? 8 : 0);
    const int vrb = ((lane & 8) ? 8 : 0) + (lane & 7);
    const int vcb = ((lane & 16) ? 8 : 0);

#pragma unroll 1
    for (int seg = 0; seg < 2; ++seg) {
        const int qi = (seg == 0) ? (int)blockIdx.x : (NQT - 1 - (int)blockIdx.x);
        const int q0 = qi * 64;
        const int ntiles = qi + 1;

#pragma unroll
        for (int i = 0; i < 4; ++i) {
            int c = tid + i * 128;
            int r = c >> 3, ch = c & 7;
            cp16(sQh + (uint32_t)(r * 144 + ch * 16),
                 qhp + (size_t)(q0 + r) * HD + ch * 8);
        }
        prefetchKV(0, sKV);
        cp_commit();
        cp_wait0();
        __syncthreads();

        uint32_t fqh[4][4];
        {
            int rr = qr0 + (lane & 15);
#pragma unroll
            for (int kf = 0; kf < 4; ++kf) {
                int cc = kf * 16 + ((lane & 16) ? 8 : 0);
                uint32_t off = (uint32_t)(rr * 144 + cc * 2);
                ldsm4(fqh[kf][0], fqh[kf][1], fqh[kf][2], fqh[kf][3], sQh + off);
            }
        }

        float o[8][4];
#pragma unroll
        for (int i = 0; i < 8; ++i)
#pragma unroll
            for (int k = 0; k < 4; ++k) o[i][k] = 0.0f;
        float m0 = -1e30f, m1 = -1e30f, l0 = 0.0f, l1 = 0.0f;

        for (int j = 0; j < ntiles; ++j) {
            uint32_t stage = sKV + (uint32_t)(j & 1) * KV_STAGE;
            if (j + 1 < ntiles) {
                prefetchKV(j + 1, sKV + (uint32_t)((j + 1) & 1) * KV_STAGE);
                cp_commit();
            }

            const bool diag = (j == ntiles - 1);

            // ---- S = Q K^T ----
            float c[8][4];
#pragma unroll
            for (int i = 0; i < 8; ++i)
#pragma unroll
                for (int k = 0; k < 4; ++k) c[i][k] = 0.0f;

            uint32_t Kh = stage;
            if (!diag) {
#pragma unroll
                for (int kf = 0; kf < 4; ++kf) {
#pragma unroll
                    for (int jp = 0; jp < 4; ++jp) {
                        uint32_t off = (uint32_t)((jp * 16 + rb) * 144 + (kf * 16 + cb) * 2);
                        uint32_t h0, h1, h2, h3;
                        ldsm4(h0, h1, h2, h3, Kh + off);
                        mma_fp(c[2 * jp],     fqh[kf], h0, h1);
                        mma_fp(c[2 * jp + 1], fqh[kf], h2, h3);
                    }
                }
            } else {
                // warp `warp` only needs key blocks jp <= warp
                for (int jp = 0; jp <= warp; ++jp) {
#pragma unroll
                    for (int kf = 0; kf < 4; ++kf) {
                        uint32_t off = (uint32_t)((jp * 16 + rb) * 144 + (kf * 16 + cb) * 2);
                        uint32_t h0, h1, h2, h3;
                        ldsm4(h0, h1, h2, h3, Kh + off);
                        mma_fp(c[2 * jp],     fqh[kf], h0, h1);
                        mma_fp(c[2 * jp + 1], fqh[kf], h2, h3);
                    }
                }
                // causal mask (covers computed and skipped blocks)
                int row0 = q0 + qr0 + (lane >> 2);
                int kb = j * 64 + (lane & 3) * 2;
#pragma unroll
                for (int nf = 0; nf < 8; ++nf) {
                    int key = kb + nf * 8;
                    if (key     > row0)     c[nf][0] = -1e30f;
                    if (key + 1 > row0)     c[nf][1] = -1e30f;
                    if (key     > row0 + 8) c[nf][2] = -1e30f;
                    if (key + 1 > row0 + 8) c[nf][3] = -1e30f;
                }
            }

            // ---- online softmax (lazy rescale) ----
            float v0 = -1e30f, v1 = -1e30f;
#pragma unroll
            for (int nf = 0; nf < 8; ++nf) {
                v0 = fmaxf(v0, fmaxf(c[nf][0], c[nf][1]));
                v1 = fmaxf(v1, fmaxf(c[nf][2], c[nf][3]));
            }
            v0 = fmaxf(v0, __shfl_xor_sync(0xFFFFFFFFu, v0, 1));
            v0 = fmaxf(v0, __shfl_xor_sync(0xFFFFFFFFu, v0, 2));
            v1 = fmaxf(v1, __shfl_xor_sync(0xFFFFFFFFu, v1, 1));
            v1 = fmaxf(v1, __shfl_xor_sync(0xFFFFFFFFu, v1, 2));
            float mn0 = fmaxf(m0, v0), mn1 = fmaxf(m1, v1);
            bool nochg = (mn0 == m0) && (mn1 == m1);
            if (!__all_sync(0xFFFFFFFFu, nochg)) {
                float a0 = exp2p(m0 - mn0), a1 = exp2p(m1 - mn1);
                l0 *= a0; l1 *= a1;
#pragma unroll
                for (int nf = 0; nf < 8; ++nf) {
                    o[nf][0] *= a0; o[nf][1] *= a0;
                    o[nf][2] *= a1; o[nf][3] *= a1;
                }
            }
            m0 = mn0; m1 = mn1;

            // ---- P (exp2 poly, fp16) + P V ----
            uint32_t Vh = stage + KV_MAT;
            const int tlim = diag ? warp : 3;
            for (int t = 0; t <= tlim; ++t) {
                float p00 = exp2p(c[2 * t][0] - m0), p01 = exp2p(c[2 * t][1] - m0);
                float p02 = exp2p(c[2 * t][2] - m1), p03 = exp2p(c[2 * t][3] - m1);
                float p10 = exp2p(c[2 * t + 1][0] - m0), p11 = exp2p(c[2 * t + 1][1] - m0);
                float p12 = exp2p(c[2 * t + 1][2] - m1), p13 = exp2p(c[2 * t + 1][3] - m1);
                l0 += p00 + p01 + p10 + p11;
                l1 += p02 + p03 + p12 + p13;

                uint32_t ph[4];
                ph[0] = packh2(__float2half_rn(p00), __float2half_rn(p01));
                ph[1] = packh2(__float2half_rn(p02), __float2half_rn(p03));
                ph[2] = packh2(__float2half_rn(p10), __float2half_rn(p11));
                ph[3] = packh2(__float2half_rn(p12), __float2half_rn(p13));

#pragma unroll
                for (int dp = 0; dp < 4; ++dp) {
                    uint32_t off = (uint32_t)((t * 16 + vrb) * 144 + (dp * 16 + vcb) * 2);
                    uint32_t h0, h1, h2, h3;
                    ldsm4t(h0, h1, h2, h3, Vh + off);
                    mma_fp(o[2 * dp],     ph, h0, h1);
                    mma_fp(o[2 * dp + 1], ph, h2, h3);
                }
            }

            if (j + 1 < ntiles) cp_wait0();
            __syncthreads();
        }

        l0 += __shfl_xor_sync(0xFFFFFFFFu, l0, 1);
        l0 += __shfl_xor_sync(0xFFFFFFFFu, l0, 2);
        l1 += __shfl_xor_sync(0xFFFFFFFFu, l1, 1);
        l1 += __shfl_xor_sync(0xFFFFFFFFu, l1, 2);
        float inv0 = 1.0f / l0, inv1 = 1.0f / l1;

        int t0 = q0 + qr0 + (lane >> 2);
        size_t r0 = ((size_t)b_ * TT + t0) * DIMC;
        size_t r1 = r0 + (size_t)8 * DIMC;
#pragma unroll
        for (int nf = 0; nf < 8; ++nf) {
            int col = coff + nf * 8;
            *(uint32_t*)(g_ah + r0 + col) =
                packh2(__float2half_rn(o[nf][0] * inv0), __float2half_rn(o[nf][1] * inv0));
            *(uint32_t*)(g_ah + r1 + col) =
                packh2(__float2half_rn(o[nf][2] * inv1), __float2half_rn(o[nf][3] * inv1));
        }
        __syncthreads();
    }
}

// ============================================================================
// Launch
// ============================================================================
extern "C" void kernel_launch(void* const* d_in, const int* in_sizes, int n_in,
                              void* d_out, int out_size)
{
    (void)in_sizes; (void)n_in; (void)out_size;
    const float* x     = (const float*)d_in[0];
    const float* w_qkv = (const float*)d_in[1];
    const float* b_qkv = (const float*)d_in[2];
    const float* w_out = (const float*)d_in[3];
    const float* b_out = (const float*)d_in[4];
    const float* pos   = (const float*)d_in[5];
    float* out = (float*)d_out;

    cudaFuncSetAttribute(hmma_gemm<1>, cudaFuncAttributeMaxDynamicSharedMemorySize, GEMM_SMEM);
    cudaFuncSetAttribute(hmma_gemm<0>, cudaFuncAttributeMaxDynamicSharedMemorySize, GEMM_SMEM);
    cudaFuncSetAttribute(attn2, cudaFuncAttributeMaxDynamicSharedMemorySize, ATT_SMEM);

    // 0) fused prep: x -> fp16 + both weights transposed/converted
    //    grid.x = 128 transpose blocks + 4096/32 conversion slots
    prep_fused<<<dim3(N_QKV / 32 + DIMC / 32 + MTOT * DIMC / 1024 / 32, DIMC / 32),
                 dim3(32, 8)>>>(x, w_qkv, w_out);

    // 1) QKV projection + bias (+pos, q-scale) -> fp16 Q, K, V
    hmma_gemm<1><<<dim3(N_QKV / 128, MTOT / 128), 256, GEMM_SMEM>>>(b_qkv, pos, nullptr);

    // 2) HMMA flash attention (balanced pairing, lazy rescale, diag skip)
    attn2<<<dim3(NQT / 2, BB * NH), 128, ATT_SMEM>>>();

    // 3) output projection + bias
    hmma_gemm<0><<<dim3(DIMC / 128, MTOT / 128), 256, GEMM_SMEM>>>(b_out, nullptr, out);
}